// round 11
// baseline (speedup 1.0000x reference)
#include <cstdint>
#include <stdint.h>
#include <cuda_runtime.h>
#include <cuda_bf16.h>
#include <mma.h>
#include <math.h>
#include <float.h>

using namespace nvcuda;

// ---------------- problem constants ----------------
#define NB      2
#define SEQ     1024
#define TOK     2048
#define DMODEL  1024
#define NH      16
#define NKV     4
#define HDIM    64
#define NEXP    8
#define TOPK    2
#define NLAYER  2
#define VOCAB   32000
#define FFI     3584
#define QKVN    1536
#define NSLOT   (TOK*TOPK)
#define NSLOTP  (NSLOT + NEXP*128)   // 5120

#define BK   32
#define BKP  40
#define ASME (128*BKP)     // A tile elems (one buffer)
// B tile elems depend on BN = NJ*64
#define SMEM_NT(NJ) ((4*ASME + 4*(NJ)*64*BKP) * 2)
// NJ=4 -> 122880 ; NJ=2 -> 81920

// flash smem layout (bytes)
#define FSB 72
#define FSF 68
#define FO_QH 0
#define FO_QL (FO_QH + 64*FSB*2)
#define FO_KH (FO_QL + 64*FSB*2)
#define FO_KL (FO_KH + 64*FSB*2)
#define FO_VH (FO_KL + 64*FSB*2)
#define FO_VL (FO_VH + 64*FSB*2)
#define FO_SS (FO_VL + 64*FSB*2)
#define FO_OS (FO_SS + 64*FSF*4)
#define FO_PH (FO_OS + 64*FSF*4)
#define FO_PL (FO_PH + 64*FSB*2)
#define FLASH_SMEM_BYTES (FO_PL + 64*FSB*2)   // 108544

// ---------------- scratch ----------------
__device__ float g_x  [TOK*DMODEL];
__device__ float g_xn [TOK*DMODEL];
__device__ float g_qkv[TOK*QKVN];
__device__ float g_y  [TOK*DMODEL];
__device__ float g_h1 [NSLOTP*FFI];
__device__ float g_h3 [NSLOTP*FFI];
__device__ float g_so [NSLOTP*DMODEL];
__device__ int   g_counts[NEXP];
__device__ int   g_offs[NEXP+1];
__device__ int   g_cursor[NEXP];
__device__ int   g_slot_token[NSLOTP];
__device__ float g_slot_w[NSLOTP];
__device__ int   g_token_slot[NSLOT];
__device__ int   g_tok_e[TOK*TOPK];
__device__ float g_tok_w[TOK*TOPK];

// ---------------- small kernels ----------------
__global__ void embed_kernel(const int* __restrict__ idx,
                             const float* __restrict__ emb,
                             float* __restrict__ x) {
    int t = blockIdx.x;
    int row = idx[t];
    const float* src = emb + (size_t)row * DMODEL;
    float* dst = x + (size_t)t * DMODEL;
    for (int d = threadIdx.x; d < DMODEL; d += blockDim.x) dst[d] = src[d];
}

__global__ __launch_bounds__(256) void rmsnorm_kernel(const float* __restrict__ x,
                                                      const float* __restrict__ w,
                                                      float* __restrict__ o) {
    int t = blockIdx.x;
    const float* xr = x + (size_t)t * DMODEL;
    float ss = 0.f;
    for (int d = threadIdx.x; d < DMODEL; d += 256) { float v = xr[d]; ss += v * v; }
    for (int off = 16; off; off >>= 1) ss += __shfl_xor_sync(0xffffffffu, ss, off);
    __shared__ float red[8];
    __shared__ float s_inv;
    int warp = threadIdx.x >> 5, lane = threadIdx.x & 31;
    if (lane == 0) red[warp] = ss;
    __syncthreads();
    if (threadIdx.x == 0) {
        float tot = 0.f;
        #pragma unroll
        for (int i = 0; i < 8; i++) tot += red[i];
        s_inv = rsqrtf(tot / (float)DMODEL + 1e-5f);
    }
    __syncthreads();
    float inv = s_inv;
    float* op = o + (size_t)t * DMODEL;
    for (int d = threadIdx.x; d < DMODEL; d += 256) op[d] = xr[d] * inv * w[d];
}

__global__ void rope_kernel(float* __restrict__ qkv) {
    int i = blockIdx.x * blockDim.x + threadIdx.x;
    const int total = TOK * (NH + NKV) * (HDIM / 2);
    if (i >= total) return;
    int pair = i & 31;
    int r = i >> 5;
    int head = r % (NH + NKV);
    int t = r / (NH + NKV);
    int s = t & (SEQ - 1);
    float freq = expf((float)pair * -0.43173470493638357f);
    float ang = (float)s * freq;
    float sn, c;
    sincosf(ang, &sn, &c);
    float* p = qkv + (size_t)t * QKVN + head * HDIM + 2 * pair;
    float x0 = p[0], x1 = p[1];
    p[0] = x0 * c - x1 * sn;
    p[1] = x1 * c + x0 * sn;
}

// ---------------- split helpers ----------------
__device__ __forceinline__ void split_store4(float4 v, float sc,
                                             __nv_bfloat16* hi, __nv_bfloat16* lo) {
    float f0 = v.x * sc, f1 = v.y * sc, f2 = v.z * sc, f3 = v.w * sc;
    __nv_bfloat162 h01, h23, l01, l23;
    h01.x = __float2bfloat16(f0); h01.y = __float2bfloat16(f1);
    h23.x = __float2bfloat16(f2); h23.y = __float2bfloat16(f3);
    l01.x = __float2bfloat16(f0 - __bfloat162float(h01.x));
    l01.y = __float2bfloat16(f1 - __bfloat162float(h01.y));
    l23.x = __float2bfloat16(f2 - __bfloat162float(h23.x));
    l23.y = __float2bfloat16(f3 - __bfloat162float(h23.y));
    *reinterpret_cast<__nv_bfloat162*>(hi)     = h01;
    *reinterpret_cast<__nv_bfloat162*>(hi + 2) = h23;
    *reinterpret_cast<__nv_bfloat162*>(lo)     = l01;
    *reinterpret_cast<__nv_bfloat162*>(lo + 2) = l23;
}

__device__ __forceinline__ void stage16(const float4 v[4], float sc,
                                        __nv_bfloat16* hiArr, __nv_bfloat16* loArr,
                                        int row, int scol) {
    #pragma unroll
    for (int q = 0; q < 4; q++)
        split_store4(v[q], sc, hiArr + row * BKP + scol + q * 4,
                             loArr + row * BKP + scol + q * 4);
}

// 64 x (NJ*16) warp-tile MMA over one staged BK chunk
template<int NJ>
__device__ __forceinline__ void mma_chunk(const __nv_bfloat16* Ah, const __nv_bfloat16* Al,
                                          const __nv_bfloat16* Bh, const __nv_bfloat16* Bl,
                                          int wm, int wn,
                                          wmma::fragment<wmma::accumulator,16,16,16,float> (&acc)[4][NJ]) {
    #pragma unroll
    for (int ks = 0; ks < BK; ks += 16) {
        wmma::fragment<wmma::matrix_a, 16, 16, 16, __nv_bfloat16, wmma::row_major> ah[4], al[4];
        #pragma unroll
        for (int i = 0; i < 4; i++) {
            wmma::load_matrix_sync(ah[i], Ah + (wm + i * 16) * BKP + ks, BKP);
            wmma::load_matrix_sync(al[i], Al + (wm + i * 16) * BKP + ks, BKP);
        }
        #pragma unroll
        for (int j = 0; j < NJ; j++) {
            wmma::fragment<wmma::matrix_b, 16, 16, 16, __nv_bfloat16, wmma::col_major> bf;
            wmma::load_matrix_sync(bf, Bh + (wn + j * 16) * BKP + ks, BKP);
            #pragma unroll
            for (int i = 0; i < 4; i++) wmma::mma_sync(acc[i][j], ah[i], bf, acc[i][j]);
            #pragma unroll
            for (int i = 0; i < 4; i++) wmma::mma_sync(acc[i][j], al[i], bf, acc[i][j]);
            wmma::load_matrix_sync(bf, Bl + (wn + j * 16) * BKP + ks, BKP);
            #pragma unroll
            for (int i = 0; i < 4; i++) wmma::mma_sync(acc[i][j], ah[i], bf, acc[i][j]);
        }
    }
}

// ---------------- pipelined bf16-split GEMM, 128 x (NJ*64) CTA tile ----------------
template<int NJ, bool RESID>
__global__ __launch_bounds__(256, 1) void gemm_nt(const float* __restrict__ A,
                                                  const float* __restrict__ Bw,
                                                  const float* __restrict__ R,
                                                  float* __restrict__ C,
                                                  int N, int K) {
    constexpr int BN = NJ * 64;
    constexpr int NR = BN / 128;           // B staging rows per thread (1 or 2)
    constexpr int BSME = BN * BKP;
    extern __shared__ __nv_bfloat16 smem_[];
    __nv_bfloat16* Ah = smem_;
    __nv_bfloat16* Al = Ah + 2 * ASME;
    __nv_bfloat16* Bh = Al + 2 * ASME;
    __nv_bfloat16* Bl = Bh + 2 * BSME;

    const int tid = threadIdx.x;
    const int bm = blockIdx.y * 128, bn = blockIdx.x * BN;
    const int srow = tid >> 1;
    const int scol = (tid & 1) * 16;
    const int wid = tid >> 5;
    const int wm = (wid & 1) * 64;
    const int wn = (wid >> 1) * (NJ * 16);

    const float* ap = A + (size_t)(bm + srow) * K + scol;
    const float* bp[NR];
    #pragma unroll
    for (int r = 0; r < NR; r++)
        bp[r] = Bw + (size_t)(bn + r * 128 + srow) * K + scol;

    wmma::fragment<wmma::accumulator, 16, 16, 16, float> acc[4][NJ];
    #pragma unroll
    for (int i = 0; i < 4; i++)
        #pragma unroll
        for (int j = 0; j < NJ; j++) {
            if (RESID)
                wmma::load_matrix_sync(acc[i][j],
                    R + (size_t)(bm + wm + i * 16) * N + bn + wn + j * 16, N, wmma::mem_row_major);
            else
                wmma::fill_fragment(acc[i][j], 0.f);
        }

    float4 va[4], vb[NR][4];
    #pragma unroll
    for (int q = 0; q < 4; q++) {
        va[q] = *reinterpret_cast<const float4*>(ap + q * 4);
        #pragma unroll
        for (int r = 0; r < NR; r++)
            vb[r][q] = *reinterpret_cast<const float4*>(bp[r] + q * 4);
    }
    stage16(va, 1.f, Ah, Al, srow, scol);
    #pragma unroll
    for (int r = 0; r < NR; r++)
        stage16(vb[r], 1.f, Bh, Bl, r * 128 + srow, scol);
    __syncthreads();

    const int nk = K / BK;
    for (int kk = 0; kk < nk; kk++) {
        const int cur = kk & 1;
        if (kk + 1 < nk) {
            const int k0 = (kk + 1) * BK;
            #pragma unroll
            for (int q = 0; q < 4; q++) {
                va[q] = *reinterpret_cast<const float4*>(ap + k0 + q * 4);
                #pragma unroll
                for (int r = 0; r < NR; r++)
                    vb[r][q] = *reinterpret_cast<const float4*>(bp[r] + k0 + q * 4);
            }
        }
        mma_chunk<NJ>(Ah + cur * ASME, Al + cur * ASME, Bh + cur * BSME, Bl + cur * BSME,
                      wm, wn, acc);
        if (kk + 1 < nk) {
            const int nxt = cur ^ 1;
            stage16(va, 1.f, Ah + nxt * ASME, Al + nxt * ASME, srow, scol);
            #pragma unroll
            for (int r = 0; r < NR; r++)
                stage16(vb[r], 1.f, Bh + nxt * BSME, Bl + nxt * BSME, r * 128 + srow, scol);
            __syncthreads();
        }
    }
    #pragma unroll
    for (int i = 0; i < 4; i++)
        #pragma unroll
        for (int j = 0; j < NJ; j++)
            wmma::store_matrix_sync(C + (size_t)(bm + wm + i * 16) * N + bn + wn + j * 16,
                                    acc[i][j], N, wmma::mem_row_major);
}

// ---------------- MoE gather GEMM (w1/w3), 128x256 tile ----------------
__global__ __launch_bounds__(256, 1) void gemm_moe_gather(const float* __restrict__ X,
                                                          const float* __restrict__ Wbase,
                                                          long wstride,
                                                          float* __restrict__ C,
                                                          int N, int K,
                                                          const int* __restrict__ offs,
                                                          const int* __restrict__ slot_token) {
    constexpr int NJ = 4;
    constexpr int BN = 256;
    constexpr int BSME = BN * BKP;
    const int e = blockIdx.z;
    const int row0 = offs[e] + blockIdx.y * 128;
    if (row0 >= offs[e + 1]) return;
    const float* W = Wbase + (long)e * wstride;

    extern __shared__ __nv_bfloat16 smem_[];
    __nv_bfloat16* Ah = smem_;
    __nv_bfloat16* Al = Ah + 2 * ASME;
    __nv_bfloat16* Bh = Al + 2 * ASME;
    __nv_bfloat16* Bl = Bh + 2 * BSME;

    const int tid = threadIdx.x;
    const int bn = blockIdx.x * BN;
    const int srow = tid >> 1;
    const int scol = (tid & 1) * 16;
    const int wid = tid >> 5;
    const int wm = (wid & 1) * 64;
    const int wn = (wid >> 1) * 64;

    int arow = slot_token[row0 + srow];
    const float* ap  = X + (size_t)arow * K + scol;
    const float* bp0 = W + (size_t)(bn + srow) * K + scol;
    const float* bp1 = W + (size_t)(bn + 128 + srow) * K + scol;

    wmma::fragment<wmma::accumulator, 16, 16, 16, float> acc[4][NJ];
    #pragma unroll
    for (int i = 0; i < 4; i++)
        #pragma unroll
        for (int j = 0; j < NJ; j++) wmma::fill_fragment(acc[i][j], 0.f);

    float4 va[4], vb0[4], vb1[4];
    #pragma unroll
    for (int q = 0; q < 4; q++) {
        va[q]  = *reinterpret_cast<const float4*>(ap  + q * 4);
        vb0[q] = *reinterpret_cast<const float4*>(bp0 + q * 4);
        vb1[q] = *reinterpret_cast<const float4*>(bp1 + q * 4);
    }
    stage16(va,  1.f, Ah, Al, srow, scol);
    stage16(vb0, 1.f, Bh, Bl, srow, scol);
    stage16(vb1, 1.f, Bh, Bl, 128 + srow, scol);
    __syncthreads();

    const int nk = K / BK;
    for (int kk = 0; kk < nk; kk++) {
        const int cur = kk & 1;
        if (kk + 1 < nk) {
            const int k0 = (kk + 1) * BK;
            #pragma unroll
            for (int q = 0; q < 4; q++) {
                va[q]  = *reinterpret_cast<const float4*>(ap  + k0 + q * 4);
                vb0[q] = *reinterpret_cast<const float4*>(bp0 + k0 + q * 4);
                vb1[q] = *reinterpret_cast<const float4*>(bp1 + k0 + q * 4);
            }
        }
        mma_chunk<NJ>(Ah + cur * ASME, Al + cur * ASME, Bh + cur * BSME, Bl + cur * BSME,
                      wm, wn, acc);
        if (kk + 1 < nk) {
            const int nxt = cur ^ 1;
            stage16(va,  1.f, Ah + nxt * ASME, Al + nxt * ASME, srow, scol);
            stage16(vb0, 1.f, Bh + nxt * BSME, Bl + nxt * BSME, srow, scol);
            stage16(vb1, 1.f, Bh + nxt * BSME, Bl + nxt * BSME, 128 + srow, scol);
            __syncthreads();
        }
    }
    #pragma unroll
    for (int i = 0; i < 4; i++)
        #pragma unroll
        for (int j = 0; j < NJ; j++)
            wmma::store_matrix_sync(C + (size_t)(row0 + wm + i * 16) * N + bn + wn + j * 16,
                                    acc[i][j], N, wmma::mem_row_major);
}

// ---------------- MoE w2 GEMM with fused silu(h1)*h3*slot_w A-staging, 128x128 tile ----------------
__device__ __forceinline__ float4 silu_mul4(float4 a, float4 b, float w) {
    float4 r;
    r.x = (a.x / (1.f + __expf(-a.x))) * b.x * w;
    r.y = (a.y / (1.f + __expf(-a.y))) * b.y * w;
    r.z = (a.z / (1.f + __expf(-a.z))) * b.z * w;
    r.w = (a.w / (1.f + __expf(-a.w))) * b.w * w;
    return r;
}

__global__ __launch_bounds__(256, 1) void gemm_w2_moe(const float* __restrict__ H1,
                                                      const float* __restrict__ H3,
                                                      const float* __restrict__ Wbase,
                                                      long wstride,
                                                      float* __restrict__ C,
                                                      int N, int K,
                                                      const int* __restrict__ offs,
                                                      const float* __restrict__ slot_w) {
    constexpr int NJ = 2;
    constexpr int BN = 128;
    constexpr int BSME = BN * BKP;
    const int e = blockIdx.z;
    const int row0 = offs[e] + blockIdx.y * 128;
    if (row0 >= offs[e + 1]) return;
    const float* W = Wbase + (long)e * wstride;

    extern __shared__ __nv_bfloat16 smem_[];
    __nv_bfloat16* Ah = smem_;
    __nv_bfloat16* Al = Ah + 2 * ASME;
    __nv_bfloat16* Bh = Al + 2 * ASME;
    __nv_bfloat16* Bl = Bh + 2 * BSME;

    const int tid = threadIdx.x;
    const int bn = blockIdx.x * BN;
    const int srow = tid >> 1;
    const int scol = (tid & 1) * 16;
    const int wid = tid >> 5;
    const int wm = (wid & 1) * 64;
    const int wn = (wid >> 1) * 32;

    const int grow = row0 + srow;
    const float sw = slot_w[grow];
    const float* a1 = H1 + (size_t)grow * K + scol;
    const float* a3 = H3 + (size_t)grow * K + scol;
    const float* bp = W + (size_t)(bn + srow) * K + scol;

    wmma::fragment<wmma::accumulator, 16, 16, 16, float> acc[4][NJ];
    #pragma unroll
    for (int i = 0; i < 4; i++)
        #pragma unroll
        for (int j = 0; j < NJ; j++) wmma::fill_fragment(acc[i][j], 0.f);

    float4 v1[4], v3[4], vb[4];
    #pragma unroll
    for (int q = 0; q < 4; q++) {
        v1[q] = *reinterpret_cast<const float4*>(a1 + q * 4);
        v3[q] = *reinterpret_cast<const float4*>(a3 + q * 4);
        vb[q] = *reinterpret_cast<const float4*>(bp + q * 4);
    }
    {
        float4 fa[4];
        #pragma unroll
        for (int q = 0; q < 4; q++) fa[q] = silu_mul4(v1[q], v3[q], sw);
        stage16(fa, 1.f, Ah, Al, srow, scol);
        stage16(vb, 1.f, Bh, Bl, srow, scol);
    }
    __syncthreads();

    const int nk = K / BK;
    for (int kk = 0; kk < nk; kk++) {
        const int cur = kk & 1;
        if (kk + 1 < nk) {
            const int k0 = (kk + 1) * BK;
            #pragma unroll
            for (int q = 0; q < 4; q++) {
                v1[q] = *reinterpret_cast<const float4*>(a1 + k0 + q * 4);
                v3[q] = *reinterpret_cast<const float4*>(a3 + k0 + q * 4);
                vb[q] = *reinterpret_cast<const float4*>(bp + k0 + q * 4);
            }
        }
        mma_chunk<NJ>(Ah + cur * ASME, Al + cur * ASME, Bh + cur * BSME, Bl + cur * BSME,
                      wm, wn, acc);
        if (kk + 1 < nk) {
            const int nxt = cur ^ 1;
            float4 fa[4];
            #pragma unroll
            for (int q = 0; q < 4; q++) fa[q] = silu_mul4(v1[q], v3[q], sw);
            stage16(fa, 1.f, Ah + nxt * ASME, Al + nxt * ASME, srow, scol);
            stage16(vb, 1.f, Bh + nxt * BSME, Bl + nxt * BSME, srow, scol);
            __syncthreads();
        }
    }
    #pragma unroll
    for (int i = 0; i < 4; i++)
        #pragma unroll
        for (int j = 0; j < NJ; j++)
            wmma::store_matrix_sync(C + (size_t)(row0 + wm + i * 16) * N + bn + wn + j * 16,
                                    acc[i][j], N, wmma::mem_row_major);
}

// ---------------- tensor-core flash attention (bf16-split wmma, proven R7) ----------------
__device__ __forceinline__ void fsplit16(const float* __restrict__ src,
                                         __nv_bfloat16* hi, __nv_bfloat16* lo) {
    #pragma unroll
    for (int q = 0; q < 4; q++) {
        float4 v = *reinterpret_cast<const float4*>(src + q * 4);
        split_store4(v, 1.f, hi + q * 4, lo + q * 4);
    }
}

__global__ __launch_bounds__(256) void flash_kernel(const float* __restrict__ qkv,
                                                    float* __restrict__ y) {
    extern __shared__ char fsm[];
    __nv_bfloat16* Qh = (__nv_bfloat16*)(fsm + FO_QH);
    __nv_bfloat16* Ql = (__nv_bfloat16*)(fsm + FO_QL);
    __nv_bfloat16* Kh = (__nv_bfloat16*)(fsm + FO_KH);
    __nv_bfloat16* Kl = (__nv_bfloat16*)(fsm + FO_KL);
    __nv_bfloat16* Vh = (__nv_bfloat16*)(fsm + FO_VH);
    __nv_bfloat16* Vl = (__nv_bfloat16*)(fsm + FO_VL);
    float*         Ss = (float*)(fsm + FO_SS);
    float*         Os = (float*)(fsm + FO_OS);
    __nv_bfloat16* Ph = (__nv_bfloat16*)(fsm + FO_PH);
    __nv_bfloat16* Pl = (__nv_bfloat16*)(fsm + FO_PL);

    const int b = blockIdx.z, h = blockIdx.y;
    const int q0 = blockIdx.x * 64;
    const int kvh = h >> 2;
    const int tid = threadIdx.x;
    const int tx = tid & 15, ty = tid >> 4;
    const int wq = tid >> 5;
    const int wm2 = (wq >> 1) * 16;
    const int wn2 = (wq & 1) * 32;
    const int lr = tid >> 2;
    const int lc = (tid & 3) * 16;

    fsplit16(qkv + (size_t)(b * SEQ + q0 + lr) * QKVN + h * HDIM + lc,
             Qh + lr * FSB + lc, Ql + lr * FSB + lc);

    float m[4], l[4], O[4][4];
    #pragma unroll
    for (int i = 0; i < 4; i++) {
        m[i] = -FLT_MAX; l[i] = 0.f;
        #pragma unroll
        for (int j = 0; j < 4; j++) O[i][j] = 0.f;
    }

    const int ntile = q0 / 64 + 1;
    for (int kt = 0; kt < ntile; kt++) {
        const int k0 = kt * 64;
        fsplit16(qkv + (size_t)(b * SEQ + k0 + lr) * QKVN + DMODEL + kvh * HDIM + lc,
                 Kh + lr * FSB + lc, Kl + lr * FSB + lc);
        fsplit16(qkv + (size_t)(b * SEQ + k0 + lr) * QKVN + DMODEL + NKV * HDIM + kvh * HDIM + lc,
                 Vh + lr * FSB + lc, Vl + lr * FSB + lc);
        __syncthreads();

        {
            wmma::fragment<wmma::accumulator, 16, 16, 16, float> sfr[2];
            wmma::fill_fragment(sfr[0], 0.f);
            wmma::fill_fragment(sfr[1], 0.f);
            #pragma unroll
            for (int ks = 0; ks < 64; ks += 16) {
                wmma::fragment<wmma::matrix_a, 16, 16, 16, __nv_bfloat16, wmma::row_major> qh, ql;
                wmma::load_matrix_sync(qh, Qh + wm2 * FSB + ks, FSB);
                wmma::load_matrix_sync(ql, Ql + wm2 * FSB + ks, FSB);
                #pragma unroll
                for (int j = 0; j < 2; j++) {
                    wmma::fragment<wmma::matrix_b, 16, 16, 16, __nv_bfloat16, wmma::col_major> kf;
                    wmma::load_matrix_sync(kf, Kh + (wn2 + j * 16) * FSB + ks, FSB);
                    wmma::mma_sync(sfr[j], qh, kf, sfr[j]);
                    wmma::mma_sync(sfr[j], ql, kf, sfr[j]);
                    wmma::load_matrix_sync(kf, Kl + (wn2 + j * 16) * FSB + ks, FSB);
                    wmma::mma_sync(sfr[j], qh, kf, sfr[j]);
                }
            }
            wmma::store_matrix_sync(Ss + wm2 * FSF + wn2,      sfr[0], FSF, wmma::mem_row_major);
            wmma::store_matrix_sync(Ss + wm2 * FSF + wn2 + 16, sfr[1], FSF, wmma::mem_row_major);
        }
        __syncthreads();

        float corr[4];
        #pragma unroll
        for (int i = 0; i < 4; i++) {
            int row = ty * 4 + i;
            int qg = q0 + row;
            float s[4];
            float rm = -FLT_MAX;
            #pragma unroll
            for (int j = 0; j < 4; j++) {
                int kg = k0 + tx * 4 + j;
                float v = (kg <= qg) ? Ss[row * FSF + tx * 4 + j] * 0.125f : -FLT_MAX;
                s[j] = v;
                rm = fmaxf(rm, v);
            }
            for (int off = 8; off; off >>= 1)
                rm = fmaxf(rm, __shfl_xor_sync(0xffffffffu, rm, off, 16));
            float mn = fmaxf(m[i], rm);
            corr[i] = __expf(m[i] - mn);
            float rs = 0.f;
            #pragma unroll
            for (int j = 0; j < 4; j++) {
                float p = __expf(s[j] - mn);
                rs += p;
                __nv_bfloat16 ph = __float2bfloat16(p);
                Ph[row * FSB + tx * 4 + j] = ph;
                Pl[row * FSB + tx * 4 + j] = __float2bfloat16(p - __bfloat162float(ph));
            }
            for (int off = 8; off; off >>= 1)
                rs += __shfl_xor_sync(0xffffffffu, rs, off, 16);
            l[i] = l[i] * corr[i] + rs;
            m[i] = mn;
        }
        __syncthreads();

        {
            wmma::fragment<wmma::accumulator, 16, 16, 16, float> ofr[2];
            wmma::fill_fragment(ofr[0], 0.f);
            wmma::fill_fragment(ofr[1], 0.f);
            #pragma unroll
            for (int ks = 0; ks < 64; ks += 16) {
                wmma::fragment<wmma::matrix_a, 16, 16, 16, __nv_bfloat16, wmma::row_major> ph, pl;
                wmma::load_matrix_sync(ph, Ph + wm2 * FSB + ks, FSB);
                wmma::load_matrix_sync(pl, Pl + wm2 * FSB + ks, FSB);
                #pragma unroll
                for (int j = 0; j < 2; j++) {
                    wmma::fragment<wmma::matrix_b, 16, 16, 16, __nv_bfloat16, wmma::row_major> vf;
                    wmma::load_matrix_sync(vf, Vh + ks * FSB + wn2 + j * 16, FSB);
                    wmma::mma_sync(ofr[j], ph, vf, ofr[j]);
                    wmma::mma_sync(ofr[j], pl, vf, ofr[j]);
                    wmma::load_matrix_sync(vf, Vl + ks * FSB + wn2 + j * 16, FSB);
                    wmma::mma_sync(ofr[j], ph, vf, ofr[j]);
                }
            }
            wmma::store_matrix_sync(Os + wm2 * FSF + wn2,      ofr[0], FSF, wmma::mem_row_major);
            wmma::store_matrix_sync(Os + wm2 * FSF + wn2 + 16, ofr[1], FSF, wmma::mem_row_major);
        }
        __syncthreads();

        #pragma unroll
        for (int i = 0; i < 4; i++) {
            int row = ty * 4 + i;
            #pragma unroll
            for (int j = 0; j < 4; j++)
                O[i][j] = O[i][j] * corr[i] + Os[row * FSF + tx * 4 + j];
        }
        __syncthreads();
    }

    #pragma unroll
    for (int i = 0; i < 4; i++) {
        float inv = 1.f / l[i];
        #pragma unroll
        for (int j = 0; j < 4; j++)
            y[(size_t)(b * SEQ + q0 + ty * 4 + i) * DMODEL + h * HDIM + tx * 4 + j] = O[i][j] * inv;
    }
}

// ---------------- MoE routing ----------------
__global__ void zero_counts_kernel(int* counts) {
    if (threadIdx.x < NEXP) counts[threadIdx.x] = 0;
}

__global__ void init_slots_kernel(int* slot_token, float* slot_w) {
    int i = blockIdx.x * blockDim.x + threadIdx.x;
    if (i < NSLOTP) { slot_token[i] = 0; slot_w[i] = 0.f; }
}

__global__ __launch_bounds__(256) void gate_kernel(const float* __restrict__ xn,
                                                   const float* __restrict__ gw,
                                                   int* __restrict__ tok_e,
                                                   float* __restrict__ tok_w,
                                                   int* __restrict__ counts) {
    int t = blockIdx.x;
    int w = threadIdx.x >> 5, lane = threadIdx.x & 31;
    __shared__ float sc[NEXP];
    const float* x = xn + (size_t)t * DMODEL;
    const float* g = gw + (size_t)w * DMODEL;
    float s = 0.f;
    for (int d = lane; d < DMODEL; d += 32) s += x[d] * g[d];
    for (int off = 16; off; off >>= 1) s += __shfl_xor_sync(0xffffffffu, s, off);
    if (lane == 0) sc[w] = s;
    __syncthreads();
    if (threadIdx.x == 0) {
        float mx = sc[0];
        #pragma unroll
        for (int e = 1; e < NEXP; e++) mx = fmaxf(mx, sc[e]);
        float p[NEXP], sum = 0.f;
        #pragma unroll
        for (int e = 0; e < NEXP; e++) { p[e] = __expf(sc[e] - mx); sum += p[e]; }
        int i0 = 0;
        #pragma unroll
        for (int e = 1; e < NEXP; e++) if (p[e] > p[i0]) i0 = e;
        int i1 = (i0 == 0) ? 1 : 0;
        #pragma unroll
        for (int e = 0; e < NEXP; e++) if (e != i0 && p[e] > p[i1]) i1 = e;
        float v0 = p[i0] / sum, v1 = p[i1] / sum;
        float inv = 1.f / (v0 + v1);
        tok_e[2 * t] = i0;  tok_e[2 * t + 1] = i1;
        tok_w[2 * t] = v0 * inv; tok_w[2 * t + 1] = v1 * inv;
        atomicAdd(&counts[i0], 1); atomicAdd(&counts[i1], 1);
    }
}

__global__ void scan_kernel(const int* __restrict__ counts, int* __restrict__ offs,
                            int* __restrict__ cursor) {
    if (threadIdx.x == 0) {
        int acc = 0;
        for (int e = 0; e < NEXP; e++) {
            offs[e] = acc; cursor[e] = acc;
            acc += ((counts[e] + 127) >> 7) << 7;
        }
        offs[NEXP] = acc;
    }
}

__global__ void scatter_kernel(const int* __restrict__ tok_e, const float* __restrict__ tok_w,
                               int* __restrict__ cursor, int* __restrict__ slot_token,
                               float* __restrict__ slot_w, int* __restrict__ token_slot) {
    int t = blockIdx.x * blockDim.x + threadIdx.x;
    if (t >= TOK) return;
    #pragma unroll
    for (int j = 0; j < TOPK; j++) {
        int e = tok_e[2 * t + j];
        int slot = atomicAdd(&cursor[e], 1);
        slot_token[slot] = t;
        slot_w[slot] = tok_w[2 * t + j];
        token_slot[2 * t + j] = slot;
    }
}

__global__ void combine_kernel(float* __restrict__ x, const float* __restrict__ so,
                               const int* __restrict__ token_slot) {
    int t = blockIdx.x;
    int s0 = token_slot[2 * t], s1 = token_slot[2 * t + 1];
    float* xp = x + (size_t)t * DMODEL;
    const float* a = so + (size_t)s0 * DMODEL;
    const float* b = so + (size_t)s1 * DMODEL;
    for (int d = threadIdx.x; d < DMODEL; d += blockDim.x) xp[d] += a[d] + b[d];
}

// ---------------- orchestration ----------------
extern "C" void kernel_launch(void* const* d_in, const int* in_sizes, int n_in,
                              void* d_out, int out_size) {
    const int*   idx      = (const int*)  d_in[0];
    const float* tok_emb  = (const float*)d_in[1];
    const float* attn_nw  = (const float*)d_in[2];
    const float* wqkv     = (const float*)d_in[3];
    const float* wo       = (const float*)d_in[4];
    const float* ffn_nw   = (const float*)d_in[5];
    const float* gate_w   = (const float*)d_in[6];
    const float* w1       = (const float*)d_in[7];
    const float* w2       = (const float*)d_in[8];
    const float* w3       = (const float*)d_in[9];
    const float* final_nw = (const float*)d_in[10];
    const float* out_w    = (const float*)d_in[11];
    float* logits = (float*)d_out;

    cudaFuncSetAttribute(gemm_nt<2, false>, cudaFuncAttributeMaxDynamicSharedMemorySize, SMEM_NT(2));
    cudaFuncSetAttribute(gemm_nt<2, true>,  cudaFuncAttributeMaxDynamicSharedMemorySize, SMEM_NT(2));
    cudaFuncSetAttribute(gemm_nt<4, false>, cudaFuncAttributeMaxDynamicSharedMemorySize, SMEM_NT(4));
    cudaFuncSetAttribute(gemm_moe_gather,   cudaFuncAttributeMaxDynamicSharedMemorySize, SMEM_NT(4));
    cudaFuncSetAttribute(gemm_w2_moe,       cudaFuncAttributeMaxDynamicSharedMemorySize, SMEM_NT(2));
    cudaFuncSetAttribute(flash_kernel,      cudaFuncAttributeMaxDynamicSharedMemorySize, FLASH_SMEM_BYTES);

    float *px, *pxn, *pqkv, *py, *ph1, *ph3, *pso, *pslot_w, *ptok_w;
    int *pcounts, *poffs, *pcursor, *pslot_token, *ptoken_slot, *ptok_e;
    cudaGetSymbolAddress((void**)&px, g_x);
    cudaGetSymbolAddress((void**)&pxn, g_xn);
    cudaGetSymbolAddress((void**)&pqkv, g_qkv);
    cudaGetSymbolAddress((void**)&py, g_y);
    cudaGetSymbolAddress((void**)&ph1, g_h1);
    cudaGetSymbolAddress((void**)&ph3, g_h3);
    cudaGetSymbolAddress((void**)&pso, g_so);
    cudaGetSymbolAddress((void**)&pcounts, g_counts);
    cudaGetSymbolAddress((void**)&poffs, g_offs);
    cudaGetSymbolAddress((void**)&pcursor, g_cursor);
    cudaGetSymbolAddress((void**)&pslot_token, g_slot_token);
    cudaGetSymbolAddress((void**)&pslot_w, g_slot_w);
    cudaGetSymbolAddress((void**)&ptoken_slot, g_token_slot);
    cudaGetSymbolAddress((void**)&ptok_e, g_tok_e);
    cudaGetSymbolAddress((void**)&ptok_w, g_tok_w);

    embed_kernel<<<TOK, 256>>>(idx, tok_emb, px);

    for (int l = 0; l < NLAYER; l++) {
        // ---- attention block ----
        rmsnorm_kernel<<<TOK, 256>>>(px, attn_nw + (size_t)l * DMODEL, pxn);
        gemm_nt<2, false><<<dim3(QKVN / 128, TOK / 128), 256, SMEM_NT(2)>>>(
            pxn, wqkv + (size_t)l * QKVN * DMODEL, nullptr, pqkv, QKVN, DMODEL);
        {
            int total = TOK * (NH + NKV) * (HDIM / 2);
            rope_kernel<<<(total + 255) / 256, 256>>>(pqkv);
        }
        flash_kernel<<<dim3(SEQ / 64, NH, NB), 256, FLASH_SMEM_BYTES>>>(pqkv, py);
        gemm_nt<2, true><<<dim3(DMODEL / 128, TOK / 128), 256, SMEM_NT(2)>>>(
            py, wo + (size_t)l * DMODEL * DMODEL, px, px, DMODEL, DMODEL);

        // ---- MoE block ----
        rmsnorm_kernel<<<TOK, 256>>>(px, ffn_nw + (size_t)l * DMODEL, pxn);
        zero_counts_kernel<<<1, 32>>>(pcounts);
        init_slots_kernel<<<(NSLOTP + 255) / 256, 256>>>(pslot_token, pslot_w);
        gate_kernel<<<TOK, 256>>>(pxn, gate_w + (size_t)l * NEXP * DMODEL,
                                  ptok_e, ptok_w, pcounts);
        scan_kernel<<<1, 1>>>(pcounts, poffs, pcursor);
        scatter_kernel<<<(TOK + 255) / 256, 256>>>(ptok_e, ptok_w, pcursor,
                                                   pslot_token, pslot_w, ptoken_slot);
        gemm_moe_gather<<<dim3(FFI / 256, NSLOTP / 128, NEXP), 256, SMEM_NT(4)>>>(
            pxn, w1 + (size_t)l * NEXP * FFI * DMODEL, (long)FFI * DMODEL,
            ph1, FFI, DMODEL, poffs, pslot_token);
        gemm_moe_gather<<<dim3(FFI / 256, NSLOTP / 128, NEXP), 256, SMEM_NT(4)>>>(
            pxn, w3 + (size_t)l * NEXP * FFI * DMODEL, (long)FFI * DMODEL,
            ph3, FFI, DMODEL, poffs, pslot_token);
        gemm_w2_moe<<<dim3(DMODEL / 128, NSLOTP / 128, NEXP), 256, SMEM_NT(2)>>>(
            ph1, ph3, w2 + (size_t)l * NEXP * DMODEL * FFI, (long)DMODEL * FFI,
            pso, DMODEL, FFI, poffs, pslot_w);
        combine_kernel<<<TOK, 256>>>(px, pso, ptoken_slot);
    }

    // ---- final norm + LM head ----
    rmsnorm_kernel<<<TOK, 256>>>(px, final_nw, pxn);
    gemm_nt<4, false><<<dim3(VOCAB / 256, TOK / 128), 256, SMEM_NT(4)>>>(
        pxn, out_w, nullptr, logits, VOCAB, DMODEL);
}

// round 12
// speedup vs baseline: 1.0943x; 1.0943x over previous
#include <cstdint>
#include <stdint.h>
#include <cuda_runtime.h>
#include <cuda_bf16.h>
#include <mma.h>
#include <math.h>
#include <float.h>

using namespace nvcuda;

// ---------------- problem constants ----------------
#define NB      2
#define SEQ     1024
#define TOK     2048
#define DMODEL  1024
#define NH      16
#define NKV     4
#define HDIM    64
#define NEXP    8
#define TOPK    2
#define NLAYER  2
#define VOCAB   32000
#define FFI     3584
#define QKVN    1536
#define NSLOT   (TOK*TOPK)
#define NSLOTP  (NSLOT + NEXP*128)   // 5120

#define BK   32
#define BKP  40
#define ASME (128*BKP)     // A tile elems (one buffer)
#define BSME (256*BKP)     // B tile elems (one buffer)
#define GEMM_SMEM_BYTES ((4*ASME + 4*BSME) * 2)   // 122880

// flash smem layout (bytes)
#define FSB 72
#define FSF 68
#define FO_QH 0
#define FO_QL (FO_QH + 64*FSB*2)
#define FO_KH (FO_QL + 64*FSB*2)
#define FO_KL (FO_KH + 64*FSB*2)
#define FO_VH (FO_KL + 64*FSB*2)
#define FO_VL (FO_VH + 64*FSB*2)
#define FO_SS (FO_VL + 64*FSB*2)
#define FO_OS (FO_SS + 64*FSF*4)
#define FO_PH (FO_OS + 64*FSF*4)
#define FO_PL (FO_PH + 64*FSB*2)
#define FLASH_SMEM_BYTES (FO_PL + 64*FSB*2)   // 108544

// ---------------- scratch ----------------
__device__ float g_x  [TOK*DMODEL];
__device__ float g_xn [TOK*DMODEL];
__device__ float g_qkv[TOK*QKVN];
__device__ float g_y  [TOK*DMODEL];
__device__ float g_h1 [NSLOTP*FFI];
__device__ float g_h3 [NSLOTP*FFI];
__device__ float g_so [NSLOTP*DMODEL];
__device__ int   g_counts[NEXP];
__device__ int   g_offs[NEXP+1];
__device__ int   g_cursor[NEXP];
__device__ int   g_slot_token[NSLOTP];
__device__ float g_slot_w[NSLOTP];
__device__ int   g_token_slot[NSLOT];
__device__ int   g_tok_e[TOK*TOPK];
__device__ float g_tok_w[TOK*TOPK];

// ---------------- small kernels ----------------
__global__ void embed_kernel(const int* __restrict__ idx,
                             const float* __restrict__ emb,
                             float* __restrict__ x) {
    int t = blockIdx.x;
    int row = idx[t];
    const float* src = emb + (size_t)row * DMODEL;
    float* dst = x + (size_t)t * DMODEL;
    for (int d = threadIdx.x; d < DMODEL; d += blockDim.x) dst[d] = src[d];
}

__global__ __launch_bounds__(256) void rmsnorm_kernel(const float* __restrict__ x,
                                                      const float* __restrict__ w,
                                                      float* __restrict__ o) {
    int t = blockIdx.x;
    const float* xr = x + (size_t)t * DMODEL;
    float ss = 0.f;
    for (int d = threadIdx.x; d < DMODEL; d += 256) { float v = xr[d]; ss += v * v; }
    for (int off = 16; off; off >>= 1) ss += __shfl_xor_sync(0xffffffffu, ss, off);
    __shared__ float red[8];
    __shared__ float s_inv;
    int warp = threadIdx.x >> 5, lane = threadIdx.x & 31;
    if (lane == 0) red[warp] = ss;
    __syncthreads();
    if (threadIdx.x == 0) {
        float tot = 0.f;
        #pragma unroll
        for (int i = 0; i < 8; i++) tot += red[i];
        s_inv = rsqrtf(tot / (float)DMODEL + 1e-5f);
    }
    __syncthreads();
    float inv = s_inv;
    float* op = o + (size_t)t * DMODEL;
    for (int d = threadIdx.x; d < DMODEL; d += 256) op[d] = xr[d] * inv * w[d];
}

__global__ void rope_kernel(float* __restrict__ qkv) {
    int i = blockIdx.x * blockDim.x + threadIdx.x;
    const int total = TOK * (NH + NKV) * (HDIM / 2);
    if (i >= total) return;
    int pair = i & 31;
    int r = i >> 5;
    int head = r % (NH + NKV);
    int t = r / (NH + NKV);
    int s = t & (SEQ - 1);
    float freq = expf((float)pair * -0.43173470493638357f);
    float ang = (float)s * freq;
    float sn, c;
    sincosf(ang, &sn, &c);
    float* p = qkv + (size_t)t * QKVN + head * HDIM + 2 * pair;
    float x0 = p[0], x1 = p[1];
    p[0] = x0 * c - x1 * sn;
    p[1] = x1 * c + x0 * sn;
}

// ---------------- split helpers ----------------
__device__ __forceinline__ void split_store4(float4 v, float sc,
                                             __nv_bfloat16* hi, __nv_bfloat16* lo) {
    float f0 = v.x * sc, f1 = v.y * sc, f2 = v.z * sc, f3 = v.w * sc;
    __nv_bfloat162 h01, h23, l01, l23;
    h01.x = __float2bfloat16(f0); h01.y = __float2bfloat16(f1);
    h23.x = __float2bfloat16(f2); h23.y = __float2bfloat16(f3);
    l01.x = __float2bfloat16(f0 - __bfloat162float(h01.x));
    l01.y = __float2bfloat16(f1 - __bfloat162float(h01.y));
    l23.x = __float2bfloat16(f2 - __bfloat162float(h23.x));
    l23.y = __float2bfloat16(f3 - __bfloat162float(h23.y));
    *reinterpret_cast<__nv_bfloat162*>(hi)     = h01;
    *reinterpret_cast<__nv_bfloat162*>(hi + 2) = h23;
    *reinterpret_cast<__nv_bfloat162*>(lo)     = l01;
    *reinterpret_cast<__nv_bfloat162*>(lo + 2) = l23;
}

__device__ __forceinline__ void stage16(const float4 v[4], float sc,
                                        __nv_bfloat16* hiArr, __nv_bfloat16* loArr,
                                        int row, int scol) {
    #pragma unroll
    for (int q = 0; q < 4; q++)
        split_store4(v[q], sc, hiArr + row * BKP + scol + q * 4,
                             loArr + row * BKP + scol + q * 4);
}

// 64x64-warp-tile MMA over one staged BK chunk (proven R10)
__device__ __forceinline__ void mma_chunk(const __nv_bfloat16* Ah, const __nv_bfloat16* Al,
                                          const __nv_bfloat16* Bh, const __nv_bfloat16* Bl,
                                          int wm, int wn,
                                          wmma::fragment<wmma::accumulator,16,16,16,float> (&acc)[4][4]) {
    #pragma unroll
    for (int ks = 0; ks < BK; ks += 16) {
        wmma::fragment<wmma::matrix_a, 16, 16, 16, __nv_bfloat16, wmma::row_major> ah[4], al[4];
        #pragma unroll
        for (int i = 0; i < 4; i++) {
            wmma::load_matrix_sync(ah[i], Ah + (wm + i * 16) * BKP + ks, BKP);
            wmma::load_matrix_sync(al[i], Al + (wm + i * 16) * BKP + ks, BKP);
        }
        #pragma unroll
        for (int j = 0; j < 4; j++) {
            wmma::fragment<wmma::matrix_b, 16, 16, 16, __nv_bfloat16, wmma::col_major> bf;
            wmma::load_matrix_sync(bf, Bh + (wn + j * 16) * BKP + ks, BKP);
            #pragma unroll
            for (int i = 0; i < 4; i++) wmma::mma_sync(acc[i][j], ah[i], bf, acc[i][j]);
            #pragma unroll
            for (int i = 0; i < 4; i++) wmma::mma_sync(acc[i][j], al[i], bf, acc[i][j]);
            wmma::load_matrix_sync(bf, Bl + (wn + j * 16) * BKP + ks, BKP);
            #pragma unroll
            for (int i = 0; i < 4; i++) wmma::mma_sync(acc[i][j], ah[i], bf, acc[i][j]);
        }
    }
}

// ---------------- pipelined bf16-split GEMM, 128x256 CTA tile (R10 proven) ----------------
template<bool RESID>
__global__ __launch_bounds__(256, 1) void gemm_bf16_nt(const float* __restrict__ A,
                                                       const float* __restrict__ Bw,
                                                       const float* __restrict__ R,
                                                       float* __restrict__ C,
                                                       int N, int K) {
    extern __shared__ __nv_bfloat16 smem_[];
    __nv_bfloat16* Ah = smem_;
    __nv_bfloat16* Al = Ah + 2 * ASME;
    __nv_bfloat16* Bh = Al + 2 * ASME;
    __nv_bfloat16* Bl = Bh + 2 * BSME;

    const int tid = threadIdx.x;
    const int bm = blockIdx.y * 128, bn = blockIdx.x * 256;
    const int srow = tid >> 1;
    const int scol = (tid & 1) * 16;
    const int wid = tid >> 5;
    const int wm = (wid & 1) * 64;
    const int wn = (wid >> 1) * 64;

    const float* ap  = A  + (size_t)(bm + srow) * K + scol;
    const float* bp0 = Bw + (size_t)(bn + srow) * K + scol;
    const float* bp1 = Bw + (size_t)(bn + 128 + srow) * K + scol;

    wmma::fragment<wmma::accumulator, 16, 16, 16, float> acc[4][4];
    #pragma unroll
    for (int i = 0; i < 4; i++)
        #pragma unroll
        for (int j = 0; j < 4; j++) {
            if (RESID)
                wmma::load_matrix_sync(acc[i][j],
                    R + (size_t)(bm + wm + i * 16) * N + bn + wn + j * 16, N, wmma::mem_row_major);
            else
                wmma::fill_fragment(acc[i][j], 0.f);
        }

    float4 va[4], vb0[4], vb1[4];
    #pragma unroll
    for (int q = 0; q < 4; q++) {
        va[q]  = *reinterpret_cast<const float4*>(ap  + q * 4);
        vb0[q] = *reinterpret_cast<const float4*>(bp0 + q * 4);
        vb1[q] = *reinterpret_cast<const float4*>(bp1 + q * 4);
    }
    stage16(va,  1.f, Ah, Al, srow, scol);
    stage16(vb0, 1.f, Bh, Bl, srow, scol);
    stage16(vb1, 1.f, Bh, Bl, 128 + srow, scol);
    __syncthreads();

    const int nk = K / BK;
    for (int kk = 0; kk < nk; kk++) {
        const int cur = kk & 1;
        if (kk + 1 < nk) {
            const int k0 = (kk + 1) * BK;
            #pragma unroll
            for (int q = 0; q < 4; q++) {
                va[q]  = *reinterpret_cast<const float4*>(ap  + k0 + q * 4);
                vb0[q] = *reinterpret_cast<const float4*>(bp0 + k0 + q * 4);
                vb1[q] = *reinterpret_cast<const float4*>(bp1 + k0 + q * 4);
            }
        }
        mma_chunk(Ah + cur * ASME, Al + cur * ASME, Bh + cur * BSME, Bl + cur * BSME,
                  wm, wn, acc);
        if (kk + 1 < nk) {
            const int nxt = cur ^ 1;
            stage16(va,  1.f, Ah + nxt * ASME, Al + nxt * ASME, srow, scol);
            stage16(vb0, 1.f, Bh + nxt * BSME, Bl + nxt * BSME, srow, scol);
            stage16(vb1, 1.f, Bh + nxt * BSME, Bl + nxt * BSME, 128 + srow, scol);
            __syncthreads();
        }
    }
    #pragma unroll
    for (int i = 0; i < 4; i++)
        #pragma unroll
        for (int j = 0; j < 4; j++)
            wmma::store_matrix_sync(C + (size_t)(bm + wm + i * 16) * N + bn + wn + j * 16,
                                    acc[i][j], N, wmma::mem_row_major);
}

// ---------------- MoE gather GEMM (w1/w3), 128x256 tile (R10 proven) ----------------
__global__ __launch_bounds__(256, 1) void gemm_moe_gather(const float* __restrict__ X,
                                                          const float* __restrict__ Wbase,
                                                          long wstride,
                                                          float* __restrict__ C,
                                                          int N, int K,
                                                          const int* __restrict__ offs,
                                                          const int* __restrict__ slot_token) {
    const int e = blockIdx.z;
    const int row0 = offs[e] + blockIdx.y * 128;
    if (row0 >= offs[e + 1]) return;
    const float* W = Wbase + (long)e * wstride;

    extern __shared__ __nv_bfloat16 smem_[];
    __nv_bfloat16* Ah = smem_;
    __nv_bfloat16* Al = Ah + 2 * ASME;
    __nv_bfloat16* Bh = Al + 2 * ASME;
    __nv_bfloat16* Bl = Bh + 2 * BSME;

    const int tid = threadIdx.x;
    const int bn = blockIdx.x * 256;
    const int srow = tid >> 1;
    const int scol = (tid & 1) * 16;
    const int wid = tid >> 5;
    const int wm = (wid & 1) * 64;
    const int wn = (wid >> 1) * 64;

    int arow = slot_token[row0 + srow];
    const float* ap  = X + (size_t)arow * K + scol;
    const float* bp0 = W + (size_t)(bn + srow) * K + scol;
    const float* bp1 = W + (size_t)(bn + 128 + srow) * K + scol;

    wmma::fragment<wmma::accumulator, 16, 16, 16, float> acc[4][4];
    #pragma unroll
    for (int i = 0; i < 4; i++)
        #pragma unroll
        for (int j = 0; j < 4; j++) wmma::fill_fragment(acc[i][j], 0.f);

    float4 va[4], vb0[4], vb1[4];
    #pragma unroll
    for (int q = 0; q < 4; q++) {
        va[q]  = *reinterpret_cast<const float4*>(ap  + q * 4);
        vb0[q] = *reinterpret_cast<const float4*>(bp0 + q * 4);
        vb1[q] = *reinterpret_cast<const float4*>(bp1 + q * 4);
    }
    stage16(va,  1.f, Ah, Al, srow, scol);
    stage16(vb0, 1.f, Bh, Bl, srow, scol);
    stage16(vb1, 1.f, Bh, Bl, 128 + srow, scol);
    __syncthreads();

    const int nk = K / BK;
    for (int kk = 0; kk < nk; kk++) {
        const int cur = kk & 1;
        if (kk + 1 < nk) {
            const int k0 = (kk + 1) * BK;
            #pragma unroll
            for (int q = 0; q < 4; q++) {
                va[q]  = *reinterpret_cast<const float4*>(ap  + k0 + q * 4);
                vb0[q] = *reinterpret_cast<const float4*>(bp0 + k0 + q * 4);
                vb1[q] = *reinterpret_cast<const float4*>(bp1 + k0 + q * 4);
            }
        }
        mma_chunk(Ah + cur * ASME, Al + cur * ASME, Bh + cur * BSME, Bl + cur * BSME,
                  wm, wn, acc);
        if (kk + 1 < nk) {
            const int nxt = cur ^ 1;
            stage16(va,  1.f, Ah + nxt * ASME, Al + nxt * ASME, srow, scol);
            stage16(vb0, 1.f, Bh + nxt * BSME, Bl + nxt * BSME, srow, scol);
            stage16(vb1, 1.f, Bh + nxt * BSME, Bl + nxt * BSME, 128 + srow, scol);
            __syncthreads();
        }
    }
    #pragma unroll
    for (int i = 0; i < 4; i++)
        #pragma unroll
        for (int j = 0; j < 4; j++)
            wmma::store_matrix_sync(C + (size_t)(row0 + wm + i * 16) * N + bn + wn + j * 16,
                                    acc[i][j], N, wmma::mem_row_major);
}

// ---------------- MoE w2 GEMM, 128x256 tile, fused silu(h1)*h3*slot_w A-staging ----------------
__device__ __forceinline__ float4 silu_mul4(float4 a, float4 b, float w) {
    float4 r;
    r.x = (a.x / (1.f + __expf(-a.x))) * b.x * w;
    r.y = (a.y / (1.f + __expf(-a.y))) * b.y * w;
    r.z = (a.z / (1.f + __expf(-a.z))) * b.z * w;
    r.w = (a.w / (1.f + __expf(-a.w))) * b.w * w;
    return r;
}

__global__ __launch_bounds__(256, 1) void gemm_w2_moe(const float* __restrict__ H1,
                                                      const float* __restrict__ H3,
                                                      const float* __restrict__ Wbase,
                                                      long wstride,
                                                      float* __restrict__ C,
                                                      int N, int K,
                                                      const int* __restrict__ offs,
                                                      const float* __restrict__ slot_w) {
    const int e = blockIdx.z;
    const int row0 = offs[e] + blockIdx.y * 128;
    if (row0 >= offs[e + 1]) return;
    const float* W = Wbase + (long)e * wstride;

    extern __shared__ __nv_bfloat16 smem_[];
    __nv_bfloat16* Ah = smem_;
    __nv_bfloat16* Al = Ah + 2 * ASME;
    __nv_bfloat16* Bh = Al + 2 * ASME;
    __nv_bfloat16* Bl = Bh + 2 * BSME;

    const int tid = threadIdx.x;
    const int bn = blockIdx.x * 256;
    const int srow = tid >> 1;
    const int scol = (tid & 1) * 16;
    const int wid = tid >> 5;
    const int wm = (wid & 1) * 64;
    const int wn = (wid >> 1) * 64;

    const int grow = row0 + srow;
    const float sw = slot_w[grow];
    const float* a1  = H1 + (size_t)grow * K + scol;
    const float* a3  = H3 + (size_t)grow * K + scol;
    const float* bp0 = W + (size_t)(bn + srow) * K + scol;
    const float* bp1 = W + (size_t)(bn + 128 + srow) * K + scol;

    wmma::fragment<wmma::accumulator, 16, 16, 16, float> acc[4][4];
    #pragma unroll
    for (int i = 0; i < 4; i++)
        #pragma unroll
        for (int j = 0; j < 4; j++) wmma::fill_fragment(acc[i][j], 0.f);

    float4 v1[4], v3[4], vb0[4], vb1[4];
    #pragma unroll
    for (int q = 0; q < 4; q++) {
        v1[q]  = *reinterpret_cast<const float4*>(a1  + q * 4);
        v3[q]  = *reinterpret_cast<const float4*>(a3  + q * 4);
        vb0[q] = *reinterpret_cast<const float4*>(bp0 + q * 4);
        vb1[q] = *reinterpret_cast<const float4*>(bp1 + q * 4);
    }
    {
        float4 fa[4];
        #pragma unroll
        for (int q = 0; q < 4; q++) fa[q] = silu_mul4(v1[q], v3[q], sw);
        stage16(fa,  1.f, Ah, Al, srow, scol);
        stage16(vb0, 1.f, Bh, Bl, srow, scol);
        stage16(vb1, 1.f, Bh, Bl, 128 + srow, scol);
    }
    __syncthreads();

    const int nk = K / BK;
    for (int kk = 0; kk < nk; kk++) {
        const int cur = kk & 1;
        if (kk + 1 < nk) {
            const int k0 = (kk + 1) * BK;
            #pragma unroll
            for (int q = 0; q < 4; q++) {
                v1[q]  = *reinterpret_cast<const float4*>(a1  + k0 + q * 4);
                v3[q]  = *reinterpret_cast<const float4*>(a3  + k0 + q * 4);
                vb0[q] = *reinterpret_cast<const float4*>(bp0 + k0 + q * 4);
                vb1[q] = *reinterpret_cast<const float4*>(bp1 + k0 + q * 4);
            }
        }
        mma_chunk(Ah + cur * ASME, Al + cur * ASME, Bh + cur * BSME, Bl + cur * BSME,
                  wm, wn, acc);
        if (kk + 1 < nk) {
            const int nxt = cur ^ 1;
            float4 fa[4];
            #pragma unroll
            for (int q = 0; q < 4; q++) fa[q] = silu_mul4(v1[q], v3[q], sw);
            stage16(fa,  1.f, Ah + nxt * ASME, Al + nxt * ASME, srow, scol);
            stage16(vb0, 1.f, Bh + nxt * BSME, Bl + nxt * BSME, srow, scol);
            stage16(vb1, 1.f, Bh + nxt * BSME, Bl + nxt * BSME, 128 + srow, scol);
            __syncthreads();
        }
    }
    #pragma unroll
    for (int i = 0; i < 4; i++)
        #pragma unroll
        for (int j = 0; j < 4; j++)
            wmma::store_matrix_sync(C + (size_t)(row0 + wm + i * 16) * N + bn + wn + j * 16,
                                    acc[i][j], N, wmma::mem_row_major);
}

// ---------------- tensor-core flash attention (bf16-split wmma, proven R7) ----------------
__device__ __forceinline__ void fsplit16(const float* __restrict__ src,
                                         __nv_bfloat16* hi, __nv_bfloat16* lo) {
    #pragma unroll
    for (int q = 0; q < 4; q++) {
        float4 v = *reinterpret_cast<const float4*>(src + q * 4);
        split_store4(v, 1.f, hi + q * 4, lo + q * 4);
    }
}

__global__ __launch_bounds__(256) void flash_kernel(const float* __restrict__ qkv,
                                                    float* __restrict__ y) {
    extern __shared__ char fsm[];
    __nv_bfloat16* Qh = (__nv_bfloat16*)(fsm + FO_QH);
    __nv_bfloat16* Ql = (__nv_bfloat16*)(fsm + FO_QL);
    __nv_bfloat16* Kh = (__nv_bfloat16*)(fsm + FO_KH);
    __nv_bfloat16* Kl = (__nv_bfloat16*)(fsm + FO_KL);
    __nv_bfloat16* Vh = (__nv_bfloat16*)(fsm + FO_VH);
    __nv_bfloat16* Vl = (__nv_bfloat16*)(fsm + FO_VL);
    float*         Ss = (float*)(fsm + FO_SS);
    float*         Os = (float*)(fsm + FO_OS);
    __nv_bfloat16* Ph = (__nv_bfloat16*)(fsm + FO_PH);
    __nv_bfloat16* Pl = (__nv_bfloat16*)(fsm + FO_PL);

    const int b = blockIdx.z, h = blockIdx.y;
    const int q0 = blockIdx.x * 64;
    const int kvh = h >> 2;
    const int tid = threadIdx.x;
    const int tx = tid & 15, ty = tid >> 4;
    const int wq = tid >> 5;
    const int wm2 = (wq >> 1) * 16;
    const int wn2 = (wq & 1) * 32;
    const int lr = tid >> 2;
    const int lc = (tid & 3) * 16;

    fsplit16(qkv + (size_t)(b * SEQ + q0 + lr) * QKVN + h * HDIM + lc,
             Qh + lr * FSB + lc, Ql + lr * FSB + lc);

    float m[4], l[4], O[4][4];
    #pragma unroll
    for (int i = 0; i < 4; i++) {
        m[i] = -FLT_MAX; l[i] = 0.f;
        #pragma unroll
        for (int j = 0; j < 4; j++) O[i][j] = 0.f;
    }

    const int ntile = q0 / 64 + 1;
    for (int kt = 0; kt < ntile; kt++) {
        const int k0 = kt * 64;
        fsplit16(qkv + (size_t)(b * SEQ + k0 + lr) * QKVN + DMODEL + kvh * HDIM + lc,
                 Kh + lr * FSB + lc, Kl + lr * FSB + lc);
        fsplit16(qkv + (size_t)(b * SEQ + k0 + lr) * QKVN + DMODEL + NKV * HDIM + kvh * HDIM + lc,
                 Vh + lr * FSB + lc, Vl + lr * FSB + lc);
        __syncthreads();

        {
            wmma::fragment<wmma::accumulator, 16, 16, 16, float> sfr[2];
            wmma::fill_fragment(sfr[0], 0.f);
            wmma::fill_fragment(sfr[1], 0.f);
            #pragma unroll
            for (int ks = 0; ks < 64; ks += 16) {
                wmma::fragment<wmma::matrix_a, 16, 16, 16, __nv_bfloat16, wmma::row_major> qh, ql;
                wmma::load_matrix_sync(qh, Qh + wm2 * FSB + ks, FSB);
                wmma::load_matrix_sync(ql, Ql + wm2 * FSB + ks, FSB);
                #pragma unroll
                for (int j = 0; j < 2; j++) {
                    wmma::fragment<wmma::matrix_b, 16, 16, 16, __nv_bfloat16, wmma::col_major> kf;
                    wmma::load_matrix_sync(kf, Kh + (wn2 + j * 16) * FSB + ks, FSB);
                    wmma::mma_sync(sfr[j], qh, kf, sfr[j]);
                    wmma::mma_sync(sfr[j], ql, kf, sfr[j]);
                    wmma::load_matrix_sync(kf, Kl + (wn2 + j * 16) * FSB + ks, FSB);
                    wmma::mma_sync(sfr[j], qh, kf, sfr[j]);
                }
            }
            wmma::store_matrix_sync(Ss + wm2 * FSF + wn2,      sfr[0], FSF, wmma::mem_row_major);
            wmma::store_matrix_sync(Ss + wm2 * FSF + wn2 + 16, sfr[1], FSF, wmma::mem_row_major);
        }
        __syncthreads();

        float corr[4];
        #pragma unroll
        for (int i = 0; i < 4; i++) {
            int row = ty * 4 + i;
            int qg = q0 + row;
            float s[4];
            float rm = -FLT_MAX;
            #pragma unroll
            for (int j = 0; j < 4; j++) {
                int kg = k0 + tx * 4 + j;
                float v = (kg <= qg) ? Ss[row * FSF + tx * 4 + j] * 0.125f : -FLT_MAX;
                s[j] = v;
                rm = fmaxf(rm, v);
            }
            for (int off = 8; off; off >>= 1)
                rm = fmaxf(rm, __shfl_xor_sync(0xffffffffu, rm, off, 16));
            float mn = fmaxf(m[i], rm);
            corr[i] = __expf(m[i] - mn);
            float rs = 0.f;
            #pragma unroll
            for (int j = 0; j < 4; j++) {
                float p = __expf(s[j] - mn);
                rs += p;
                __nv_bfloat16 ph = __float2bfloat16(p);
                Ph[row * FSB + tx * 4 + j] = ph;
                Pl[row * FSB + tx * 4 + j] = __float2bfloat16(p - __bfloat162float(ph));
            }
            for (int off = 8; off; off >>= 1)
                rs += __shfl_xor_sync(0xffffffffu, rs, off, 16);
            l[i] = l[i] * corr[i] + rs;
            m[i] = mn;
        }
        __syncthreads();

        {
            wmma::fragment<wmma::accumulator, 16, 16, 16, float> ofr[2];
            wmma::fill_fragment(ofr[0], 0.f);
            wmma::fill_fragment(ofr[1], 0.f);
            #pragma unroll
            for (int ks = 0; ks < 64; ks += 16) {
                wmma::fragment<wmma::matrix_a, 16, 16, 16, __nv_bfloat16, wmma::row_major> ph, pl;
                wmma::load_matrix_sync(ph, Ph + wm2 * FSB + ks, FSB);
                wmma::load_matrix_sync(pl, Pl + wm2 * FSB + ks, FSB);
                #pragma unroll
                for (int j = 0; j < 2; j++) {
                    wmma::fragment<wmma::matrix_b, 16, 16, 16, __nv_bfloat16, wmma::row_major> vf;
                    wmma::load_matrix_sync(vf, Vh + ks * FSB + wn2 + j * 16, FSB);
                    wmma::mma_sync(ofr[j], ph, vf, ofr[j]);
                    wmma::mma_sync(ofr[j], pl, vf, ofr[j]);
                    wmma::load_matrix_sync(vf, Vl + ks * FSB + wn2 + j * 16, FSB);
                    wmma::mma_sync(ofr[j], ph, vf, ofr[j]);
                }
            }
            wmma::store_matrix_sync(Os + wm2 * FSF + wn2,      ofr[0], FSF, wmma::mem_row_major);
            wmma::store_matrix_sync(Os + wm2 * FSF + wn2 + 16, ofr[1], FSF, wmma::mem_row_major);
        }
        __syncthreads();

        #pragma unroll
        for (int i = 0; i < 4; i++) {
            int row = ty * 4 + i;
            #pragma unroll
            for (int j = 0; j < 4; j++)
                O[i][j] = O[i][j] * corr[i] + Os[row * FSF + tx * 4 + j];
        }
        __syncthreads();
    }

    #pragma unroll
    for (int i = 0; i < 4; i++) {
        float inv = 1.f / l[i];
        #pragma unroll
        for (int j = 0; j < 4; j++)
            y[(size_t)(b * SEQ + q0 + ty * 4 + i) * DMODEL + h * HDIM + tx * 4 + j] = O[i][j] * inv;
    }
}

// ---------------- MoE routing ----------------
__global__ void zero_counts_kernel(int* counts) {
    if (threadIdx.x < NEXP) counts[threadIdx.x] = 0;
}

__global__ void init_slots_kernel(int* slot_token, float* slot_w) {
    int i = blockIdx.x * blockDim.x + threadIdx.x;
    if (i < NSLOTP) { slot_token[i] = 0; slot_w[i] = 0.f; }
}

__global__ __launch_bounds__(256) void gate_kernel(const float* __restrict__ xn,
                                                   const float* __restrict__ gw,
                                                   int* __restrict__ tok_e,
                                                   float* __restrict__ tok_w,
                                                   int* __restrict__ counts) {
    int t = blockIdx.x;
    int w = threadIdx.x >> 5, lane = threadIdx.x & 31;
    __shared__ float sc[NEXP];
    const float* x = xn + (size_t)t * DMODEL;
    const float* g = gw + (size_t)w * DMODEL;
    float s = 0.f;
    for (int d = lane; d < DMODEL; d += 32) s += x[d] * g[d];
    for (int off = 16; off; off >>= 1) s += __shfl_xor_sync(0xffffffffu, s, off);
    if (lane == 0) sc[w] = s;
    __syncthreads();
    if (threadIdx.x == 0) {
        float mx = sc[0];
        #pragma unroll
        for (int e = 1; e < NEXP; e++) mx = fmaxf(mx, sc[e]);
        float p[NEXP], sum = 0.f;
        #pragma unroll
        for (int e = 0; e < NEXP; e++) { p[e] = __expf(sc[e] - mx); sum += p[e]; }
        int i0 = 0;
        #pragma unroll
        for (int e = 1; e < NEXP; e++) if (p[e] > p[i0]) i0 = e;
        int i1 = (i0 == 0) ? 1 : 0;
        #pragma unroll
        for (int e = 0; e < NEXP; e++) if (e != i0 && p[e] > p[i1]) i1 = e;
        float v0 = p[i0] / sum, v1 = p[i1] / sum;
        float inv = 1.f / (v0 + v1);
        tok_e[2 * t] = i0;  tok_e[2 * t + 1] = i1;
        tok_w[2 * t] = v0 * inv; tok_w[2 * t + 1] = v1 * inv;
        atomicAdd(&counts[i0], 1); atomicAdd(&counts[i1], 1);
    }
}

__global__ void scan_kernel(const int* __restrict__ counts, int* __restrict__ offs,
                            int* __restrict__ cursor) {
    if (threadIdx.x == 0) {
        int acc = 0;
        for (int e = 0; e < NEXP; e++) {
            offs[e] = acc; cursor[e] = acc;
            acc += ((counts[e] + 127) >> 7) << 7;
        }
        offs[NEXP] = acc;
    }
}

__global__ void scatter_kernel(const int* __restrict__ tok_e, const float* __restrict__ tok_w,
                               int* __restrict__ cursor, int* __restrict__ slot_token,
                               float* __restrict__ slot_w, int* __restrict__ token_slot) {
    int t = blockIdx.x * blockDim.x + threadIdx.x;
    if (t >= TOK) return;
    #pragma unroll
    for (int j = 0; j < TOPK; j++) {
        int e = tok_e[2 * t + j];
        int slot = atomicAdd(&cursor[e], 1);
        slot_token[slot] = t;
        slot_w[slot] = tok_w[2 * t + j];
        token_slot[2 * t + j] = slot;
    }
}

__global__ void combine_kernel(float* __restrict__ x, const float* __restrict__ so,
                               const int* __restrict__ token_slot) {
    int t = blockIdx.x;
    int s0 = token_slot[2 * t], s1 = token_slot[2 * t + 1];
    float* xp = x + (size_t)t * DMODEL;
    const float* a = so + (size_t)s0 * DMODEL;
    const float* b = so + (size_t)s1 * DMODEL;
    for (int d = threadIdx.x; d < DMODEL; d += blockDim.x) xp[d] += a[d] + b[d];
}

// ---------------- orchestration ----------------
extern "C" void kernel_launch(void* const* d_in, const int* in_sizes, int n_in,
                              void* d_out, int out_size) {
    const int*   idx      = (const int*)  d_in[0];
    const float* tok_emb  = (const float*)d_in[1];
    const float* attn_nw  = (const float*)d_in[2];
    const float* wqkv     = (const float*)d_in[3];
    const float* wo       = (const float*)d_in[4];
    const float* ffn_nw   = (const float*)d_in[5];
    const float* gate_w   = (const float*)d_in[6];
    const float* w1       = (const float*)d_in[7];
    const float* w2       = (const float*)d_in[8];
    const float* w3       = (const float*)d_in[9];
    const float* final_nw = (const float*)d_in[10];
    const float* out_w    = (const float*)d_in[11];
    float* logits = (float*)d_out;

    cudaFuncSetAttribute(gemm_bf16_nt<false>,
        cudaFuncAttributeMaxDynamicSharedMemorySize, GEMM_SMEM_BYTES);
    cudaFuncSetAttribute(gemm_bf16_nt<true>,
        cudaFuncAttributeMaxDynamicSharedMemorySize, GEMM_SMEM_BYTES);
    cudaFuncSetAttribute(gemm_moe_gather,
        cudaFuncAttributeMaxDynamicSharedMemorySize, GEMM_SMEM_BYTES);
    cudaFuncSetAttribute(gemm_w2_moe,
        cudaFuncAttributeMaxDynamicSharedMemorySize, GEMM_SMEM_BYTES);
    cudaFuncSetAttribute(flash_kernel,
        cudaFuncAttributeMaxDynamicSharedMemorySize, FLASH_SMEM_BYTES);

    float *px, *pxn, *pqkv, *py, *ph1, *ph3, *pso, *pslot_w, *ptok_w;
    int *pcounts, *poffs, *pcursor, *pslot_token, *ptoken_slot, *ptok_e;
    cudaGetSymbolAddress((void**)&px, g_x);
    cudaGetSymbolAddress((void**)&pxn, g_xn);
    cudaGetSymbolAddress((void**)&pqkv, g_qkv);
    cudaGetSymbolAddress((void**)&py, g_y);
    cudaGetSymbolAddress((void**)&ph1, g_h1);
    cudaGetSymbolAddress((void**)&ph3, g_h3);
    cudaGetSymbolAddress((void**)&pso, g_so);
    cudaGetSymbolAddress((void**)&pcounts, g_counts);
    cudaGetSymbolAddress((void**)&poffs, g_offs);
    cudaGetSymbolAddress((void**)&pcursor, g_cursor);
    cudaGetSymbolAddress((void**)&pslot_token, g_slot_token);
    cudaGetSymbolAddress((void**)&pslot_w, g_slot_w);
    cudaGetSymbolAddress((void**)&ptoken_slot, g_token_slot);
    cudaGetSymbolAddress((void**)&ptok_e, g_tok_e);
    cudaGetSymbolAddress((void**)&ptok_w, g_tok_w);

    embed_kernel<<<TOK, 256>>>(idx, tok_emb, px);

    for (int l = 0; l < NLAYER; l++) {
        // ---- attention block ----
        rmsnorm_kernel<<<TOK, 256>>>(px, attn_nw + (size_t)l * DMODEL, pxn);
        gemm_bf16_nt<false><<<dim3(QKVN / 256, TOK / 128), 256, GEMM_SMEM_BYTES>>>(
            pxn, wqkv + (size_t)l * QKVN * DMODEL, nullptr, pqkv, QKVN, DMODEL);
        {
            int total = TOK * (NH + NKV) * (HDIM / 2);
            rope_kernel<<<(total + 255) / 256, 256>>>(pqkv);
        }
        flash_kernel<<<dim3(SEQ / 64, NH, NB), 256, FLASH_SMEM_BYTES>>>(pqkv, py);
        gemm_bf16_nt<true><<<dim3(DMODEL / 256, TOK / 128), 256, GEMM_SMEM_BYTES>>>(
            py, wo + (size_t)l * DMODEL * DMODEL, px, px, DMODEL, DMODEL);

        // ---- MoE block ----
        rmsnorm_kernel<<<TOK, 256>>>(px, ffn_nw + (size_t)l * DMODEL, pxn);
        zero_counts_kernel<<<1, 32>>>(pcounts);
        init_slots_kernel<<<(NSLOTP + 255) / 256, 256>>>(pslot_token, pslot_w);
        gate_kernel<<<TOK, 256>>>(pxn, gate_w + (size_t)l * NEXP * DMODEL,
                                  ptok_e, ptok_w, pcounts);
        scan_kernel<<<1, 1>>>(pcounts, poffs, pcursor);
        scatter_kernel<<<(TOK + 255) / 256, 256>>>(ptok_e, ptok_w, pcursor,
                                                   pslot_token, pslot_w, ptoken_slot);
        gemm_moe_gather<<<dim3(FFI / 256, NSLOTP / 128, NEXP), 256, GEMM_SMEM_BYTES>>>(
            pxn, w1 + (size_t)l * NEXP * FFI * DMODEL, (long)FFI * DMODEL,
            ph1, FFI, DMODEL, poffs, pslot_token);
        gemm_moe_gather<<<dim3(FFI / 256, NSLOTP / 128, NEXP), 256, GEMM_SMEM_BYTES>>>(
            pxn, w3 + (size_t)l * NEXP * FFI * DMODEL, (long)FFI * DMODEL,
            ph3, FFI, DMODEL, poffs, pslot_token);
        gemm_w2_moe<<<dim3(DMODEL / 256, NSLOTP / 128, NEXP), 256, GEMM_SMEM_BYTES>>>(
            ph1, ph3, w2 + (size_t)l * NEXP * DMODEL * FFI, (long)DMODEL * FFI,
            pso, DMODEL, FFI, poffs, pslot_w);
        combine_kernel<<<TOK, 256>>>(px, pso, ptoken_slot);
    }

    // ---- final norm + LM head ----
    rmsnorm_kernel<<<TOK, 256>>>(px, final_nw, pxn);
    gemm_bf16_nt<false><<<dim3(VOCAB / 256, TOK / 128), 256, GEMM_SMEM_BYTES>>>(
        pxn, out_w, nullptr, logits, VOCAB, DMODEL);
}

// round 15
// speedup vs baseline: 1.2505x; 1.1427x over previous
#include <cstdint>
#include <stdint.h>
#include <cuda_runtime.h>
#include <cuda_bf16.h>
#include <cuda_fp16.h>
#include <mma.h>
#include <math.h>
#include <float.h>

using namespace nvcuda;

// ---------------- problem constants ----------------
#define NB      2
#define SEQ     1024
#define TOK     2048
#define DMODEL  1024
#define NH      16
#define NKV     4
#define HDIM    64
#define NEXP    8
#define TOPK    2
#define NLAYER  2
#define VOCAB   32000
#define FFI     3584
#define QKVN    1536
#define NSLOT   (TOK*TOPK)
#define NSLOTP  (NSLOT + NEXP*128)   // 5120

#define BK   32
#define BKP  40
#define ASME (128*BKP)
#define BSME (256*BKP)
#define GEMM_SMEM_BYTES ((4*ASME + 4*BSME) * 2)   // 122880 (bf16 3-term)
#define HEAD_SMEM_BYTES ((4*ASME + 2*BSME) * 2)   // 81920  (fp16 2-term head)

// flash smem layout (bytes)
#define FSB 72
#define FSF 68
#define FO_QH 0
#define FO_QL (FO_QH + 64*FSB*2)
#define FO_KH (FO_QL + 64*FSB*2)
#define FO_KL (FO_KH + 64*FSB*2)
#define FO_VH (FO_KL + 64*FSB*2)
#define FO_VL (FO_VH + 64*FSB*2)
#define FO_SS (FO_VL + 64*FSB*2)
#define FO_OS (FO_SS + 64*FSF*4)
#define FO_PH (FO_OS + 64*FSF*4)
#define FO_PL (FO_PH + 64*FSB*2)
#define FLASH_SMEM_BYTES (FO_PL + 64*FSB*2)   // 108544

// ---------------- scratch ----------------
__device__ float g_x  [TOK*DMODEL];
__device__ float g_xn [TOK*DMODEL];
__device__ float g_qkv[TOK*QKVN];
__device__ float g_y  [TOK*DMODEL];
__device__ float g_h1 [NSLOTP*FFI];
__device__ float g_h3 [NSLOTP*FFI];
__device__ float g_so [NSLOTP*DMODEL];
__device__ int   g_counts[NEXP];
__device__ int   g_offs[NEXP+1];
__device__ int   g_cursor[NEXP];
__device__ int   g_slot_token[NSLOTP];
__device__ float g_slot_w[NSLOTP];
__device__ int   g_token_slot[NSLOT];
__device__ int   g_tok_e[TOK*TOPK];
__device__ float g_tok_w[TOK*TOPK];

// ---------------- small kernels ----------------
__global__ void embed_kernel(const int* __restrict__ idx,
                             const float* __restrict__ emb,
                             float* __restrict__ x) {
    int t = blockIdx.x;
    int row = idx[t];
    const float* src = emb + (size_t)row * DMODEL;
    float* dst = x + (size_t)t * DMODEL;
    for (int d = threadIdx.x; d < DMODEL; d += blockDim.x) dst[d] = src[d];
}

__global__ __launch_bounds__(256) void rmsnorm_kernel(const float* __restrict__ x,
                                                      const float* __restrict__ w,
                                                      float* __restrict__ o) {
    int t = blockIdx.x;
    const float* xr = x + (size_t)t * DMODEL;
    float ss = 0.f;
    for (int d = threadIdx.x; d < DMODEL; d += 256) { float v = xr[d]; ss += v * v; }
    for (int off = 16; off; off >>= 1) ss += __shfl_xor_sync(0xffffffffu, ss, off);
    __shared__ float red[8];
    __shared__ float s_inv;
    int warp = threadIdx.x >> 5, lane = threadIdx.x & 31;
    if (lane == 0) red[warp] = ss;
    __syncthreads();
    if (threadIdx.x == 0) {
        float tot = 0.f;
        #pragma unroll
        for (int i = 0; i < 8; i++) tot += red[i];
        s_inv = rsqrtf(tot / (float)DMODEL + 1e-5f);
    }
    __syncthreads();
    float inv = s_inv;
    float* op = o + (size_t)t * DMODEL;
    for (int d = threadIdx.x; d < DMODEL; d += 256) op[d] = xr[d] * inv * w[d];
}

__global__ void rope_kernel(float* __restrict__ qkv) {
    int i = blockIdx.x * blockDim.x + threadIdx.x;
    const int total = TOK * (NH + NKV) * (HDIM / 2);
    if (i >= total) return;
    int pair = i & 31;
    int r = i >> 5;
    int head = r % (NH + NKV);
    int t = r / (NH + NKV);
    int s = t & (SEQ - 1);
    float freq = expf((float)pair * -0.43173470493638357f);
    float ang = (float)s * freq;
    float sn, c;
    sincosf(ang, &sn, &c);
    float* p = qkv + (size_t)t * QKVN + head * HDIM + 2 * pair;
    float x0 = p[0], x1 = p[1];
    p[0] = x0 * c - x1 * sn;
    p[1] = x1 * c + x0 * sn;
}

// ---------------- bf16 split helpers (R10 proven) ----------------
__device__ __forceinline__ void split_store4(float4 v, float sc,
                                             __nv_bfloat16* hi, __nv_bfloat16* lo) {
    float f0 = v.x * sc, f1 = v.y * sc, f2 = v.z * sc, f3 = v.w * sc;
    __nv_bfloat162 h01, h23, l01, l23;
    h01.x = __float2bfloat16(f0); h01.y = __float2bfloat16(f1);
    h23.x = __float2bfloat16(f2); h23.y = __float2bfloat16(f3);
    l01.x = __float2bfloat16(f0 - __bfloat162float(h01.x));
    l01.y = __float2bfloat16(f1 - __bfloat162float(h01.y));
    l23.x = __float2bfloat16(f2 - __bfloat162float(h23.x));
    l23.y = __float2bfloat16(f3 - __bfloat162float(h23.y));
    *reinterpret_cast<__nv_bfloat162*>(hi)     = h01;
    *reinterpret_cast<__nv_bfloat162*>(hi + 2) = h23;
    *reinterpret_cast<__nv_bfloat162*>(lo)     = l01;
    *reinterpret_cast<__nv_bfloat162*>(lo + 2) = l23;
}

__device__ __forceinline__ void stage16(const float4 v[4], float sc,
                                        __nv_bfloat16* hiArr, __nv_bfloat16* loArr,
                                        int row, int scol) {
    #pragma unroll
    for (int q = 0; q < 4; q++)
        split_store4(v[q], sc, hiArr + row * BKP + scol + q * 4,
                             loArr + row * BKP + scol + q * 4);
}

__device__ __forceinline__ void mma_chunk(const __nv_bfloat16* Ah, const __nv_bfloat16* Al,
                                          const __nv_bfloat16* Bh, const __nv_bfloat16* Bl,
                                          int wm, int wn,
                                          wmma::fragment<wmma::accumulator,16,16,16,float> (&acc)[4][4]) {
    #pragma unroll
    for (int ks = 0; ks < BK; ks += 16) {
        wmma::fragment<wmma::matrix_a, 16, 16, 16, __nv_bfloat16, wmma::row_major> ah[4], al[4];
        #pragma unroll
        for (int i = 0; i < 4; i++) {
            wmma::load_matrix_sync(ah[i], Ah + (wm + i * 16) * BKP + ks, BKP);
            wmma::load_matrix_sync(al[i], Al + (wm + i * 16) * BKP + ks, BKP);
        }
        #pragma unroll
        for (int j = 0; j < 4; j++) {
            wmma::fragment<wmma::matrix_b, 16, 16, 16, __nv_bfloat16, wmma::col_major> bf;
            wmma::load_matrix_sync(bf, Bh + (wn + j * 16) * BKP + ks, BKP);
            #pragma unroll
            for (int i = 0; i < 4; i++) wmma::mma_sync(acc[i][j], ah[i], bf, acc[i][j]);
            #pragma unroll
            for (int i = 0; i < 4; i++) wmma::mma_sync(acc[i][j], al[i], bf, acc[i][j]);
            wmma::load_matrix_sync(bf, Bl + (wn + j * 16) * BKP + ks, BKP);
            #pragma unroll
            for (int i = 0; i < 4; i++) wmma::mma_sync(acc[i][j], ah[i], bf, acc[i][j]);
        }
    }
}

// ---------------- bf16-3term GEMM, 128x256 tile (R10 proven) ----------------
template<bool RESID>
__global__ __launch_bounds__(256, 1) void gemm_bf16_nt(const float* __restrict__ A,
                                                       const float* __restrict__ Bw,
                                                       const float* __restrict__ R,
                                                       float* __restrict__ C,
                                                       int N, int K) {
    extern __shared__ __nv_bfloat16 smem_[];
    __nv_bfloat16* Ah = smem_;
    __nv_bfloat16* Al = Ah + 2 * ASME;
    __nv_bfloat16* Bh = Al + 2 * ASME;
    __nv_bfloat16* Bl = Bh + 2 * BSME;

    const int tid = threadIdx.x;
    const int bm = blockIdx.y * 128, bn = blockIdx.x * 256;
    const int srow = tid >> 1;
    const int scol = (tid & 1) * 16;
    const int wid = tid >> 5;
    const int wm = (wid & 1) * 64;
    const int wn = (wid >> 1) * 64;

    const float* ap  = A  + (size_t)(bm + srow) * K + scol;
    const float* bp0 = Bw + (size_t)(bn + srow) * K + scol;
    const float* bp1 = Bw + (size_t)(bn + 128 + srow) * K + scol;

    wmma::fragment<wmma::accumulator, 16, 16, 16, float> acc[4][4];
    #pragma unroll
    for (int i = 0; i < 4; i++)
        #pragma unroll
        for (int j = 0; j < 4; j++) {
            if (RESID)
                wmma::load_matrix_sync(acc[i][j],
                    R + (size_t)(bm + wm + i * 16) * N + bn + wn + j * 16, N, wmma::mem_row_major);
            else
                wmma::fill_fragment(acc[i][j], 0.f);
        }

    float4 va[4], vb0[4], vb1[4];
    #pragma unroll
    for (int q = 0; q < 4; q++) {
        va[q]  = *reinterpret_cast<const float4*>(ap  + q * 4);
        vb0[q] = *reinterpret_cast<const float4*>(bp0 + q * 4);
        vb1[q] = *reinterpret_cast<const float4*>(bp1 + q * 4);
    }
    stage16(va,  1.f, Ah, Al, srow, scol);
    stage16(vb0, 1.f, Bh, Bl, srow, scol);
    stage16(vb1, 1.f, Bh, Bl, 128 + srow, scol);
    __syncthreads();

    const int nk = K / BK;
    for (int kk = 0; kk < nk; kk++) {
        const int cur = kk & 1;
        if (kk + 1 < nk) {
            const int k0 = (kk + 1) * BK;
            #pragma unroll
            for (int q = 0; q < 4; q++) {
                va[q]  = *reinterpret_cast<const float4*>(ap  + k0 + q * 4);
                vb0[q] = *reinterpret_cast<const float4*>(bp0 + k0 + q * 4);
                vb1[q] = *reinterpret_cast<const float4*>(bp1 + k0 + q * 4);
            }
        }
        mma_chunk(Ah + cur * ASME, Al + cur * ASME, Bh + cur * BSME, Bl + cur * BSME,
                  wm, wn, acc);
        if (kk + 1 < nk) {
            const int nxt = cur ^ 1;
            stage16(va,  1.f, Ah + nxt * ASME, Al + nxt * ASME, srow, scol);
            stage16(vb0, 1.f, Bh + nxt * BSME, Bl + nxt * BSME, srow, scol);
            stage16(vb1, 1.f, Bh + nxt * BSME, Bl + nxt * BSME, 128 + srow, scol);
            __syncthreads();
        }
    }
    #pragma unroll
    for (int i = 0; i < 4; i++)
        #pragma unroll
        for (int j = 0; j < 4; j++)
            wmma::store_matrix_sync(C + (size_t)(bm + wm + i * 16) * N + bn + wn + j * 16,
                                    acc[i][j], N, wmma::mem_row_major);
}

// ---------------- MoE grouped GEMM bf16-3term, 128x256 tile (R10 proven) ----------------
template<bool GATHER, bool SCALE>
__global__ __launch_bounds__(256, 1) void gemm_bf16_moe(const float* __restrict__ X,
                                                        const float* __restrict__ Wbase,
                                                        long wstride,
                                                        float* __restrict__ C,
                                                        int N, int K,
                                                        const int* __restrict__ offs,
                                                        const int* __restrict__ slot_token,
                                                        const float* __restrict__ slot_w) {
    const int e = blockIdx.z;
    const int row0 = offs[e] + blockIdx.y * 128;
    if (row0 >= offs[e + 1]) return;
    const float* W = Wbase + (long)e * wstride;

    extern __shared__ __nv_bfloat16 smem_[];
    __nv_bfloat16* Ah = smem_;
    __nv_bfloat16* Al = Ah + 2 * ASME;
    __nv_bfloat16* Bh = Al + 2 * ASME;
    __nv_bfloat16* Bl = Bh + 2 * BSME;

    const int tid = threadIdx.x;
    const int bn = blockIdx.x * 256;
    const int srow = tid >> 1;
    const int scol = (tid & 1) * 16;
    const int wid = tid >> 5;
    const int wm = (wid & 1) * 64;
    const int wn = (wid >> 1) * 64;

    int grow = row0 + srow;
    int arow = GATHER ? slot_token[grow] : grow;
    float asc = (!GATHER && SCALE) ? slot_w[grow] : 1.f;
    const float* ap  = X + (size_t)arow * K + scol;
    const float* bp0 = W + (size_t)(bn + srow) * K + scol;
    const float* bp1 = W + (size_t)(bn + 128 + srow) * K + scol;

    wmma::fragment<wmma::accumulator, 16, 16, 16, float> acc[4][4];
    #pragma unroll
    for (int i = 0; i < 4; i++)
        #pragma unroll
        for (int j = 0; j < 4; j++) wmma::fill_fragment(acc[i][j], 0.f);

    float4 va[4], vb0[4], vb1[4];
    #pragma unroll
    for (int q = 0; q < 4; q++) {
        va[q]  = *reinterpret_cast<const float4*>(ap  + q * 4);
        vb0[q] = *reinterpret_cast<const float4*>(bp0 + q * 4);
        vb1[q] = *reinterpret_cast<const float4*>(bp1 + q * 4);
    }
    stage16(va,  asc, Ah, Al, srow, scol);
    stage16(vb0, 1.f, Bh, Bl, srow, scol);
    stage16(vb1, 1.f, Bh, Bl, 128 + srow, scol);
    __syncthreads();

    const int nk = K / BK;
    for (int kk = 0; kk < nk; kk++) {
        const int cur = kk & 1;
        if (kk + 1 < nk) {
            const int k0 = (kk + 1) * BK;
            #pragma unroll
            for (int q = 0; q < 4; q++) {
                va[q]  = *reinterpret_cast<const float4*>(ap  + k0 + q * 4);
                vb0[q] = *reinterpret_cast<const float4*>(bp0 + k0 + q * 4);
                vb1[q] = *reinterpret_cast<const float4*>(bp1 + k0 + q * 4);
            }
        }
        mma_chunk(Ah + cur * ASME, Al + cur * ASME, Bh + cur * BSME, Bl + cur * BSME,
                  wm, wn, acc);
        if (kk + 1 < nk) {
            const int nxt = cur ^ 1;
            stage16(va,  asc, Ah + nxt * ASME, Al + nxt * ASME, srow, scol);
            stage16(vb0, 1.f, Bh + nxt * BSME, Bl + nxt * BSME, srow, scol);
            stage16(vb1, 1.f, Bh + nxt * BSME, Bl + nxt * BSME, 128 + srow, scol);
            __syncthreads();
        }
    }
    #pragma unroll
    for (int i = 0; i < 4; i++)
        #pragma unroll
        for (int j = 0; j < 4; j++)
            wmma::store_matrix_sync(C + (size_t)(row0 + wm + i * 16) * N + bn + wn + j * 16,
                                    acc[i][j], N, wmma::mem_row_major);
}

// ---------------- fp16-2term LM-head GEMM, 128x256 tile (linear path only) ----------------
__device__ __forceinline__ void hsplit_store4(float4 v, __half* hi, __half* lo) {
    __half2 h01, h23, l01, l23;
    h01.x = __float2half(v.x); h01.y = __float2half(v.y);
    h23.x = __float2half(v.z); h23.y = __float2half(v.w);
    l01.x = __float2half(v.x - __half2float(h01.x));
    l01.y = __float2half(v.y - __half2float(h01.y));
    l23.x = __float2half(v.z - __half2float(h23.x));
    l23.y = __float2half(v.w - __half2float(h23.y));
    *reinterpret_cast<__half2*>(hi)     = h01;
    *reinterpret_cast<__half2*>(hi + 2) = h23;
    *reinterpret_cast<__half2*>(lo)     = l01;
    *reinterpret_cast<__half2*>(lo + 2) = l23;
}

__device__ __forceinline__ void hconv_store4(float4 v, __half* dst) {
    __half2 h01, h23;
    h01.x = __float2half(v.x); h01.y = __float2half(v.y);
    h23.x = __float2half(v.z); h23.y = __float2half(v.w);
    *reinterpret_cast<__half2*>(dst)     = h01;
    *reinterpret_cast<__half2*>(dst + 2) = h23;
}

__global__ __launch_bounds__(256, 1) void gemm_head_fp16(const float* __restrict__ A,
                                                         const float* __restrict__ Bw,
                                                         float* __restrict__ C,
                                                         int N, int K) {
    extern __shared__ __half hsm_[];
    __half* Ah = hsm_;
    __half* Al = Ah + 2 * ASME;
    __half* Bh = Al + 2 * ASME;

    const int tid = threadIdx.x;
    const int bm = blockIdx.y * 128, bn = blockIdx.x * 256;
    const int srow = tid >> 1;
    const int scol = (tid & 1) * 16;
    const int wid = tid >> 5;
    const int wm = (wid & 1) * 64;
    const int wn = (wid >> 1) * 64;

    const float* ap  = A  + (size_t)(bm + srow) * K + scol;
    const float* bp0 = Bw + (size_t)(bn + srow) * K + scol;
    const float* bp1 = Bw + (size_t)(bn + 128 + srow) * K + scol;

    wmma::fragment<wmma::accumulator, 16, 16, 16, float> acc[4][4];
    #pragma unroll
    for (int i = 0; i < 4; i++)
        #pragma unroll
        for (int j = 0; j < 4; j++) wmma::fill_fragment(acc[i][j], 0.f);

    float4 va[4], vb0[4], vb1[4];
    #pragma unroll
    for (int q = 0; q < 4; q++) {
        va[q]  = *reinterpret_cast<const float4*>(ap  + q * 4);
        vb0[q] = *reinterpret_cast<const float4*>(bp0 + q * 4);
        vb1[q] = *reinterpret_cast<const float4*>(bp1 + q * 4);
    }
    #pragma unroll
    for (int q = 0; q < 4; q++) {
        hsplit_store4(va[q], Ah + srow * BKP + scol + q * 4, Al + srow * BKP + scol + q * 4);
        hconv_store4(vb0[q], Bh + srow * BKP + scol + q * 4);
        hconv_store4(vb1[q], Bh + (128 + srow) * BKP + scol + q * 4);
    }
    __syncthreads();

    const int nk = K / BK;
    for (int kk = 0; kk < nk; kk++) {
        const int cur = kk & 1;
        if (kk + 1 < nk) {
            const int k0 = (kk + 1) * BK;
            #pragma unroll
            for (int q = 0; q < 4; q++) {
                va[q]  = *reinterpret_cast<const float4*>(ap  + k0 + q * 4);
                vb0[q] = *reinterpret_cast<const float4*>(bp0 + k0 + q * 4);
                vb1[q] = *reinterpret_cast<const float4*>(bp1 + k0 + q * 4);
            }
        }
        {
            const __half* cAh = Ah + cur * ASME;
            const __half* cAl = Al + cur * ASME;
            const __half* cBh = Bh + cur * BSME;
            #pragma unroll
            for (int ks = 0; ks < BK; ks += 16) {
                wmma::fragment<wmma::matrix_a, 16, 16, 16, __half, wmma::row_major> ah[4], al[4];
                #pragma unroll
                for (int i = 0; i < 4; i++) {
                    wmma::load_matrix_sync(ah[i], cAh + (wm + i * 16) * BKP + ks, BKP);
                    wmma::load_matrix_sync(al[i], cAl + (wm + i * 16) * BKP + ks, BKP);
                }
                #pragma unroll
                for (int j = 0; j < 4; j++) {
                    wmma::fragment<wmma::matrix_b, 16, 16, 16, __half, wmma::col_major> bf;
                    wmma::load_matrix_sync(bf, cBh + (wn + j * 16) * BKP + ks, BKP);
                    #pragma unroll
                    for (int i = 0; i < 4; i++) wmma::mma_sync(acc[i][j], ah[i], bf, acc[i][j]);
                    #pragma unroll
                    for (int i = 0; i < 4; i++) wmma::mma_sync(acc[i][j], al[i], bf, acc[i][j]);
                }
            }
        }
        if (kk + 1 < nk) {
            const int nxt = cur ^ 1;
            #pragma unroll
            for (int q = 0; q < 4; q++) {
                hsplit_store4(va[q], Ah + nxt * ASME + srow * BKP + scol + q * 4,
                                     Al + nxt * ASME + srow * BKP + scol + q * 4);
                hconv_store4(vb0[q], Bh + nxt * BSME + srow * BKP + scol + q * 4);
                hconv_store4(vb1[q], Bh + nxt * BSME + (128 + srow) * BKP + scol + q * 4);
            }
            __syncthreads();
        }
    }
    #pragma unroll
    for (int i = 0; i < 4; i++)
        #pragma unroll
        for (int j = 0; j < 4; j++)
            wmma::store_matrix_sync(C + (size_t)(bm + wm + i * 16) * N + bn + wn + j * 16,
                                    acc[i][j], N, wmma::mem_row_major);
}

// ---------------- tensor-core flash attention (bf16-split wmma, proven R7) ----------------
__device__ __forceinline__ void fsplit16(const float* __restrict__ src,
                                         __nv_bfloat16* hi, __nv_bfloat16* lo) {
    #pragma unroll
    for (int q = 0; q < 4; q++) {
        float4 v = *reinterpret_cast<const float4*>(src + q * 4);
        split_store4(v, 1.f, hi + q * 4, lo + q * 4);
    }
}

__global__ __launch_bounds__(256) void flash_kernel(const float* __restrict__ qkv,
                                                    float* __restrict__ y) {
    extern __shared__ char fsm[];
    __nv_bfloat16* Qh = (__nv_bfloat16*)(fsm + FO_QH);
    __nv_bfloat16* Ql = (__nv_bfloat16*)(fsm + FO_QL);
    __nv_bfloat16* Kh = (__nv_bfloat16*)(fsm + FO_KH);
    __nv_bfloat16* Kl = (__nv_bfloat16*)(fsm + FO_KL);
    __nv_bfloat16* Vh = (__nv_bfloat16*)(fsm + FO_VH);
    __nv_bfloat16* Vl = (__nv_bfloat16*)(fsm + FO_VL);
    float*         Ss = (float*)(fsm + FO_SS);
    float*         Os = (float*)(fsm + FO_OS);
    __nv_bfloat16* Ph = (__nv_bfloat16*)(fsm + FO_PH);
    __nv_bfloat16* Pl = (__nv_bfloat16*)(fsm + FO_PL);

    const int b = blockIdx.z, h = blockIdx.y;
    const int q0 = blockIdx.x * 64;
    const int kvh = h >> 2;
    const int tid = threadIdx.x;
    const int tx = tid & 15, ty = tid >> 4;
    const int wq = tid >> 5;
    const int wm2 = (wq >> 1) * 16;
    const int wn2 = (wq & 1) * 32;
    const int lr = tid >> 2;
    const int lc = (tid & 3) * 16;

    fsplit16(qkv + (size_t)(b * SEQ + q0 + lr) * QKVN + h * HDIM + lc,
             Qh + lr * FSB + lc, Ql + lr * FSB + lc);

    float m[4], l[4], O[4][4];
    #pragma unroll
    for (int i = 0; i < 4; i++) {
        m[i] = -FLT_MAX; l[i] = 0.f;
        #pragma unroll
        for (int j = 0; j < 4; j++) O[i][j] = 0.f;
    }

    const int ntile = q0 / 64 + 1;
    for (int kt = 0; kt < ntile; kt++) {
        const int k0 = kt * 64;
        fsplit16(qkv + (size_t)(b * SEQ + k0 + lr) * QKVN + DMODEL + kvh * HDIM + lc,
                 Kh + lr * FSB + lc, Kl + lr * FSB + lc);
        fsplit16(qkv + (size_t)(b * SEQ + k0 + lr) * QKVN + DMODEL + NKV * HDIM + kvh * HDIM + lc,
                 Vh + lr * FSB + lc, Vl + lr * FSB + lc);
        __syncthreads();

        {
            wmma::fragment<wmma::accumulator, 16, 16, 16, float> sfr[2];
            wmma::fill_fragment(sfr[0], 0.f);
            wmma::fill_fragment(sfr[1], 0.f);
            #pragma unroll
            for (int ks = 0; ks < 64; ks += 16) {
                wmma::fragment<wmma::matrix_a, 16, 16, 16, __nv_bfloat16, wmma::row_major> qh, ql;
                wmma::load_matrix_sync(qh, Qh + wm2 * FSB + ks, FSB);
                wmma::load_matrix_sync(ql, Ql + wm2 * FSB + ks, FSB);
                #pragma unroll
                for (int j = 0; j < 2; j++) {
                    wmma::fragment<wmma::matrix_b, 16, 16, 16, __nv_bfloat16, wmma::col_major> kf;
                    wmma::load_matrix_sync(kf, Kh + (wn2 + j * 16) * FSB + ks, FSB);
                    wmma::mma_sync(sfr[j], qh, kf, sfr[j]);
                    wmma::mma_sync(sfr[j], ql, kf, sfr[j]);
                    wmma::load_matrix_sync(kf, Kl + (wn2 + j * 16) * FSB + ks, FSB);
                    wmma::mma_sync(sfr[j], qh, kf, sfr[j]);
                }
            }
            wmma::store_matrix_sync(Ss + wm2 * FSF + wn2,      sfr[0], FSF, wmma::mem_row_major);
            wmma::store_matrix_sync(Ss + wm2 * FSF + wn2 + 16, sfr[1], FSF, wmma::mem_row_major);
        }
        __syncthreads();

        float corr[4];
        #pragma unroll
        for (int i = 0; i < 4; i++) {
            int row = ty * 4 + i;
            int qg = q0 + row;
            float s[4];
            float rm = -FLT_MAX;
            #pragma unroll
            for (int j = 0; j < 4; j++) {
                int kg = k0 + tx * 4 + j;
                float v = (kg <= qg) ? Ss[row * FSF + tx * 4 + j] * 0.125f : -FLT_MAX;
                s[j] = v;
                rm = fmaxf(rm, v);
            }
            for (int off = 8; off; off >>= 1)
                rm = fmaxf(rm, __shfl_xor_sync(0xffffffffu, rm, off, 16));
            float mn = fmaxf(m[i], rm);
            corr[i] = __expf(m[i] - mn);
            float rs = 0.f;
            #pragma unroll
            for (int j = 0; j < 4; j++) {
                float p = __expf(s[j] - mn);
                rs += p;
                __nv_bfloat16 ph = __float2bfloat16(p);
                Ph[row * FSB + tx * 4 + j] = ph;
                Pl[row * FSB + tx * 4 + j] = __float2bfloat16(p - __bfloat162float(ph));
            }
            for (int off = 8; off; off >>= 1)
                rs += __shfl_xor_sync(0xffffffffu, rs, off, 16);
            l[i] = l[i] * corr[i] + rs;
            m[i] = mn;
        }
        __syncthreads();

        {
            wmma::fragment<wmma::accumulator, 16, 16, 16, float> ofr[2];
            wmma::fill_fragment(ofr[0], 0.f);
            wmma::fill_fragment(ofr[1], 0.f);
            #pragma unroll
            for (int ks = 0; ks < 64; ks += 16) {
                wmma::fragment<wmma::matrix_a, 16, 16, 16, __nv_bfloat16, wmma::row_major> ph, pl;
                wmma::load_matrix_sync(ph, Ph + wm2 * FSB + ks, FSB);
                wmma::load_matrix_sync(pl, Pl + wm2 * FSB + ks, FSB);
                #pragma unroll
                for (int j = 0; j < 2; j++) {
                    wmma::fragment<wmma::matrix_b, 16, 16, 16, __nv_bfloat16, wmma::row_major> vf;
                    wmma::load_matrix_sync(vf, Vh + ks * FSB + wn2 + j * 16, FSB);
                    wmma::mma_sync(ofr[j], ph, vf, ofr[j]);
                    wmma::mma_sync(ofr[j], pl, vf, ofr[j]);
                    wmma::load_matrix_sync(vf, Vl + ks * FSB + wn2 + j * 16, FSB);
                    wmma::mma_sync(ofr[j], ph, vf, ofr[j]);
                }
            }
            wmma::store_matrix_sync(Os + wm2 * FSF + wn2,      ofr[0], FSF, wmma::mem_row_major);
            wmma::store_matrix_sync(Os + wm2 * FSF + wn2 + 16, ofr[1], FSF, wmma::mem_row_major);
        }
        __syncthreads();

        #pragma unroll
        for (int i = 0; i < 4; i++) {
            int row = ty * 4 + i;
            #pragma unroll
            for (int j = 0; j < 4; j++)
                O[i][j] = O[i][j] * corr[i] + Os[row * FSF + tx * 4 + j];
        }
        __syncthreads();
    }

    #pragma unroll
    for (int i = 0; i < 4; i++) {
        float inv = 1.f / l[i];
        #pragma unroll
        for (int j = 0; j < 4; j++)
            y[(size_t)(b * SEQ + q0 + ty * 4 + i) * DMODEL + h * HDIM + tx * 4 + j] = O[i][j] * inv;
    }
}

// ---------------- MoE routing ----------------
__global__ void zero_counts_kernel(int* counts) {
    if (threadIdx.x < NEXP) counts[threadIdx.x] = 0;
}

__global__ void init_slots_kernel(int* slot_token, float* slot_w) {
    int i = blockIdx.x * blockDim.x + threadIdx.x;
    if (i < NSLOTP) { slot_token[i] = 0; slot_w[i] = 0.f; }
}

__global__ __launch_bounds__(256) void gate_kernel(const float* __restrict__ xn,
                                                   const float* __restrict__ gw,
                                                   int* __restrict__ tok_e,
                                                   float* __restrict__ tok_w,
                                                   int* __restrict__ counts) {
    int t = blockIdx.x;
    int w = threadIdx.x >> 5, lane = threadIdx.x & 31;
    __shared__ float sc[NEXP];
    const float* x = xn + (size_t)t * DMODEL;
    const float* g = gw + (size_t)w * DMODEL;
    float s = 0.f;
    for (int d = lane; d < DMODEL; d += 32) s += x[d] * g[d];
    for (int off = 16; off; off >>= 1) s += __shfl_xor_sync(0xffffffffu, s, off);
    if (lane == 0) sc[w] = s;
    __syncthreads();
    if (threadIdx.x == 0) {
        float mx = sc[0];
        #pragma unroll
        for (int e = 1; e < NEXP; e++) mx = fmaxf(mx, sc[e]);
        float p[NEXP], sum = 0.f;
        #pragma unroll
        for (int e = 0; e < NEXP; e++) { p[e] = __expf(sc[e] - mx); sum += p[e]; }
        int i0 = 0;
        #pragma unroll
        for (int e = 1; e < NEXP; e++) if (p[e] > p[i0]) i0 = e;
        int i1 = (i0 == 0) ? 1 : 0;
        #pragma unroll
        for (int e = 0; e < NEXP; e++) if (e != i0 && p[e] > p[i1]) i1 = e;
        float v0 = p[i0] / sum, v1 = p[i1] / sum;
        float inv = 1.f / (v0 + v1);
        tok_e[2 * t] = i0;  tok_e[2 * t + 1] = i1;
        tok_w[2 * t] = v0 * inv; tok_w[2 * t + 1] = v1 * inv;
        atomicAdd(&counts[i0], 1); atomicAdd(&counts[i1], 1);
    }
}

__global__ void scan_kernel(const int* __restrict__ counts, int* __restrict__ offs,
                            int* __restrict__ cursor) {
    if (threadIdx.x == 0) {
        int acc = 0;
        for (int e = 0; e < NEXP; e++) {
            offs[e] = acc; cursor[e] = acc;
            acc += ((counts[e] + 127) >> 7) << 7;
        }
        offs[NEXP] = acc;
    }
}

__global__ void scatter_kernel(const int* __restrict__ tok_e, const float* __restrict__ tok_w,
                               int* __restrict__ cursor, int* __restrict__ slot_token,
                               float* __restrict__ slot_w, int* __restrict__ token_slot) {
    int t = blockIdx.x * blockDim.x + threadIdx.x;
    if (t >= TOK) return;
    #pragma unroll
    for (int j = 0; j < TOPK; j++) {
        int e = tok_e[2 * t + j];
        int slot = atomicAdd(&cursor[e], 1);
        slot_token[slot] = t;
        slot_w[slot] = tok_w[2 * t + j];
        token_slot[2 * t + j] = slot;
    }
}

__global__ void silu_mul_kernel(float* __restrict__ h1, const float* __restrict__ h3) {
    long i = (long)blockIdx.x * blockDim.x + threadIdx.x;
    if (i < (long)NSLOTP * FFI) {
        float a = h1[i];
        h1[i] = (a / (1.f + __expf(-a))) * h3[i];
    }
}

__global__ void combine_kernel(float* __restrict__ x, const float* __restrict__ so,
                               const int* __restrict__ token_slot) {
    int t = blockIdx.x;
    int s0 = token_slot[2 * t], s1 = token_slot[2 * t + 1];
    float* xp = x + (size_t)t * DMODEL;
    const float* a = so + (size_t)s0 * DMODEL;
    const float* b = so + (size_t)s1 * DMODEL;
    for (int d = threadIdx.x; d < DMODEL; d += blockDim.x) xp[d] += a[d] + b[d];
}

// ---------------- orchestration ----------------
extern "C" void kernel_launch(void* const* d_in, const int* in_sizes, int n_in,
                              void* d_out, int out_size) {
    const int*   idx      = (const int*)  d_in[0];
    const float* tok_emb  = (const float*)d_in[1];
    const float* attn_nw  = (const float*)d_in[2];
    const float* wqkv     = (const float*)d_in[3];
    const float* wo       = (const float*)d_in[4];
    const float* ffn_nw   = (const float*)d_in[5];
    const float* gate_w   = (const float*)d_in[6];
    const float* w1       = (const float*)d_in[7];
    const float* w2       = (const float*)d_in[8];
    const float* w3       = (const float*)d_in[9];
    const float* final_nw = (const float*)d_in[10];
    const float* out_w    = (const float*)d_in[11];
    float* logits = (float*)d_out;

    cudaFuncSetAttribute(gemm_bf16_nt<false>,
        cudaFuncAttributeMaxDynamicSharedMemorySize, GEMM_SMEM_BYTES);
    cudaFuncSetAttribute(gemm_bf16_nt<true>,
        cudaFuncAttributeMaxDynamicSharedMemorySize, GEMM_SMEM_BYTES);
    cudaFuncSetAttribute(gemm_bf16_moe<true, false>,
        cudaFuncAttributeMaxDynamicSharedMemorySize, GEMM_SMEM_BYTES);
    cudaFuncSetAttribute(gemm_bf16_moe<false, true>,
        cudaFuncAttributeMaxDynamicSharedMemorySize, GEMM_SMEM_BYTES);
    cudaFuncSetAttribute(gemm_head_fp16,
        cudaFuncAttributeMaxDynamicSharedMemorySize, HEAD_SMEM_BYTES);
    cudaFuncSetAttribute(flash_kernel,
        cudaFuncAttributeMaxDynamicSharedMemorySize, FLASH_SMEM_BYTES);

    float *px, *pxn, *pqkv, *py, *ph1, *ph3, *pso, *pslot_w, *ptok_w;
    int *pcounts, *poffs, *pcursor, *pslot_token, *ptoken_slot, *ptok_e;
    cudaGetSymbolAddress((void**)&px, g_x);
    cudaGetSymbolAddress((void**)&pxn, g_xn);
    cudaGetSymbolAddress((void**)&pqkv, g_qkv);
    cudaGetSymbolAddress((void**)&py, g_y);
    cudaGetSymbolAddress((void**)&ph1, g_h1);
    cudaGetSymbolAddress((void**)&ph3, g_h3);
    cudaGetSymbolAddress((void**)&pso, g_so);
    cudaGetSymbolAddress((void**)&pcounts, g_counts);
    cudaGetSymbolAddress((void**)&poffs, g_offs);
    cudaGetSymbolAddress((void**)&pcursor, g_cursor);
    cudaGetSymbolAddress((void**)&pslot_token, g_slot_token);
    cudaGetSymbolAddress((void**)&pslot_w, g_slot_w);
    cudaGetSymbolAddress((void**)&ptoken_slot, g_token_slot);
    cudaGetSymbolAddress((void**)&ptok_e, g_tok_e);
    cudaGetSymbolAddress((void**)&ptok_w, g_tok_w);

    embed_kernel<<<TOK, 256>>>(idx, tok_emb, px);

    for (int l = 0; l < NLAYER; l++) {
        // ---- attention block ----
        rmsnorm_kernel<<<TOK, 256>>>(px, attn_nw + (size_t)l * DMODEL, pxn);
        gemm_bf16_nt<false><<<dim3(QKVN / 256, TOK / 128), 256, GEMM_SMEM_BYTES>>>(
            pxn, wqkv + (size_t)l * QKVN * DMODEL, nullptr, pqkv, QKVN, DMODEL);
        {
            int total = TOK * (NH + NKV) * (HDIM / 2);
            rope_kernel<<<(total + 255) / 256, 256>>>(pqkv);
        }
        flash_kernel<<<dim3(SEQ / 64, NH, NB), 256, FLASH_SMEM_BYTES>>>(pqkv, py);
        gemm_bf16_nt<true><<<dim3(DMODEL / 256, TOK / 128), 256, GEMM_SMEM_BYTES>>>(
            py, wo + (size_t)l * DMODEL * DMODEL, px, px, DMODEL, DMODEL);

        // ---- MoE block ----
        rmsnorm_kernel<<<TOK, 256>>>(px, ffn_nw + (size_t)l * DMODEL, pxn);
        zero_counts_kernel<<<1, 32>>>(pcounts);
        init_slots_kernel<<<(NSLOTP + 255) / 256, 256>>>(pslot_token, pslot_w);
        gate_kernel<<<TOK, 256>>>(pxn, gate_w + (size_t)l * NEXP * DMODEL,
                                  ptok_e, ptok_w, pcounts);
        scan_kernel<<<1, 1>>>(pcounts, poffs, pcursor);
        scatter_kernel<<<(TOK + 255) / 256, 256>>>(ptok_e, ptok_w, pcursor,
                                                   pslot_token, pslot_w, ptoken_slot);
        gemm_bf16_moe<true, false><<<dim3(FFI / 256, NSLOTP / 128, NEXP), 256, GEMM_SMEM_BYTES>>>(
            pxn, w1 + (size_t)l * NEXP * FFI * DMODEL, (long)FFI * DMODEL,
            ph1, FFI, DMODEL, poffs, pslot_token, pslot_w);
        gemm_bf16_moe<true, false><<<dim3(FFI / 256, NSLOTP / 128, NEXP), 256, GEMM_SMEM_BYTES>>>(
            pxn, w3 + (size_t)l * NEXP * FFI * DMODEL, (long)FFI * DMODEL,
            ph3, FFI, DMODEL, poffs, pslot_token, pslot_w);
        {
            long n = (long)NSLOTP * FFI;
            silu_mul_kernel<<<(unsigned)((n + 255) / 256), 256>>>(ph1, ph3);
        }
        gemm_bf16_moe<false, true><<<dim3(DMODEL / 256, NSLOTP / 128, NEXP), 256, GEMM_SMEM_BYTES>>>(
            ph1, w2 + (size_t)l * NEXP * DMODEL * FFI, (long)DMODEL * FFI,
            pso, DMODEL, FFI, poffs, pslot_token, pslot_w);
        combine_kernel<<<TOK, 256>>>(px, pso, ptoken_slot);
    }

    // ---- final norm + LM head (fp16 2-term: linear path, no routing downstream) ----
    rmsnorm_kernel<<<TOK, 256>>>(px, final_nw, pxn);
    gemm_head_fp16<<<dim3(VOCAB / 256, TOK / 128), 256, HEAD_SMEM_BYTES>>>(
        pxn, out_w, logits, VOCAB, DMODEL);
}

// round 16
// speedup vs baseline: 1.3934x; 1.1143x over previous
#include <cstdint>
#include <stdint.h>
#include <cuda_runtime.h>
#include <cuda_bf16.h>
#include <cuda_fp16.h>
#include <mma.h>
#include <math.h>
#include <float.h>

using namespace nvcuda;

// ---------------- problem constants ----------------
#define NB      2
#define SEQ     1024
#define TOK     2048
#define DMODEL  1024
#define NH      16
#define NKV     4
#define HDIM    64
#define NEXP    8
#define TOPK    2
#define NLAYER  2
#define VOCAB   32000
#define FFI     3584
#define QKVN    1536
#define NSLOT   (TOK*TOPK)
#define NSLOTP  (NSLOT + NEXP*128)   // 5120

#define BK   32
#define BKP  40
#define ASME (128*BKP)
#define BSME (256*BKP)
#define GEMM_SMEM_BYTES ((4*ASME + 4*BSME) * 2)   // 122880 (bf16 3-term)
#define FP16_SMEM_BYTES ((4*ASME + 2*BSME) * 2)   // 81920  (fp16 2-term)

// flash smem layout (bytes)
#define FSB 72
#define FSF 68
#define FO_QH 0
#define FO_QL (FO_QH + 64*FSB*2)
#define FO_KH (FO_QL + 64*FSB*2)
#define FO_KL (FO_KH + 64*FSB*2)
#define FO_VH (FO_KL + 64*FSB*2)
#define FO_VL (FO_VH + 64*FSB*2)
#define FO_SS (FO_VL + 64*FSB*2)
#define FO_OS (FO_SS + 64*FSF*4)
#define FO_PH (FO_OS + 64*FSF*4)
#define FO_PL (FO_PH + 64*FSB*2)
#define FLASH_SMEM_BYTES (FO_PL + 64*FSB*2)   // 108544

// ---------------- scratch ----------------
__device__ float g_x  [TOK*DMODEL];
__device__ float g_xn [TOK*DMODEL];
__device__ float g_qkv[TOK*QKVN];
__device__ float g_y  [TOK*DMODEL];
__device__ float g_h1 [NSLOTP*FFI];
__device__ float g_h3 [NSLOTP*FFI];
__device__ float g_so [NSLOTP*DMODEL];
__device__ int   g_counts[NEXP];
__device__ int   g_offs[NEXP+1];
__device__ int   g_cursor[NEXP];
__device__ int   g_slot_token[NSLOTP];
__device__ float g_slot_w[NSLOTP];
__device__ int   g_token_slot[NSLOT];
__device__ int   g_tok_e[TOK*TOPK];
__device__ float g_tok_w[TOK*TOPK];

// ---------------- small kernels ----------------
__global__ void embed_kernel(const int* __restrict__ idx,
                             const float* __restrict__ emb,
                             float* __restrict__ x) {
    int t = blockIdx.x;
    int row = idx[t];
    const float* src = emb + (size_t)row * DMODEL;
    float* dst = x + (size_t)t * DMODEL;
    for (int d = threadIdx.x; d < DMODEL; d += blockDim.x) dst[d] = src[d];
}

__global__ __launch_bounds__(256) void rmsnorm_kernel(const float* __restrict__ x,
                                                      const float* __restrict__ w,
                                                      float* __restrict__ o) {
    int t = blockIdx.x;
    const float* xr = x + (size_t)t * DMODEL;
    float ss = 0.f;
    for (int d = threadIdx.x; d < DMODEL; d += 256) { float v = xr[d]; ss += v * v; }
    for (int off = 16; off; off >>= 1) ss += __shfl_xor_sync(0xffffffffu, ss, off);
    __shared__ float red[8];
    __shared__ float s_inv;
    int warp = threadIdx.x >> 5, lane = threadIdx.x & 31;
    if (lane == 0) red[warp] = ss;
    __syncthreads();
    if (threadIdx.x == 0) {
        float tot = 0.f;
        #pragma unroll
        for (int i = 0; i < 8; i++) tot += red[i];
        s_inv = rsqrtf(tot / (float)DMODEL + 1e-5f);
    }
    __syncthreads();
    float inv = s_inv;
    float* op = o + (size_t)t * DMODEL;
    for (int d = threadIdx.x; d < DMODEL; d += 256) op[d] = xr[d] * inv * w[d];
}

__global__ void rope_kernel(float* __restrict__ qkv) {
    int i = blockIdx.x * blockDim.x + threadIdx.x;
    const int total = TOK * (NH + NKV) * (HDIM / 2);
    if (i >= total) return;
    int pair = i & 31;
    int r = i >> 5;
    int head = r % (NH + NKV);
    int t = r / (NH + NKV);
    int s = t & (SEQ - 1);
    float freq = expf((float)pair * -0.43173470493638357f);
    float ang = (float)s * freq;
    float sn, c;
    sincosf(ang, &sn, &c);
    float* p = qkv + (size_t)t * QKVN + head * HDIM + 2 * pair;
    float x0 = p[0], x1 = p[1];
    p[0] = x0 * c - x1 * sn;
    p[1] = x1 * c + x0 * sn;
}

// ---------------- bf16 split helpers (R10 proven) ----------------
__device__ __forceinline__ void split_store4(float4 v, float sc,
                                             __nv_bfloat16* hi, __nv_bfloat16* lo) {
    float f0 = v.x * sc, f1 = v.y * sc, f2 = v.z * sc, f3 = v.w * sc;
    __nv_bfloat162 h01, h23, l01, l23;
    h01.x = __float2bfloat16(f0); h01.y = __float2bfloat16(f1);
    h23.x = __float2bfloat16(f2); h23.y = __float2bfloat16(f3);
    l01.x = __float2bfloat16(f0 - __bfloat162float(h01.x));
    l01.y = __float2bfloat16(f1 - __bfloat162float(h01.y));
    l23.x = __float2bfloat16(f2 - __bfloat162float(h23.x));
    l23.y = __float2bfloat16(f3 - __bfloat162float(h23.y));
    *reinterpret_cast<__nv_bfloat162*>(hi)     = h01;
    *reinterpret_cast<__nv_bfloat162*>(hi + 2) = h23;
    *reinterpret_cast<__nv_bfloat162*>(lo)     = l01;
    *reinterpret_cast<__nv_bfloat162*>(lo + 2) = l23;
}

__device__ __forceinline__ void stage16(const float4 v[4], float sc,
                                        __nv_bfloat16* hiArr, __nv_bfloat16* loArr,
                                        int row, int scol) {
    #pragma unroll
    for (int q = 0; q < 4; q++)
        split_store4(v[q], sc, hiArr + row * BKP + scol + q * 4,
                             loArr + row * BKP + scol + q * 4);
}

__device__ __forceinline__ void mma_chunk(const __nv_bfloat16* Ah, const __nv_bfloat16* Al,
                                          const __nv_bfloat16* Bh, const __nv_bfloat16* Bl,
                                          int wm, int wn,
                                          wmma::fragment<wmma::accumulator,16,16,16,float> (&acc)[4][4]) {
    #pragma unroll
    for (int ks = 0; ks < BK; ks += 16) {
        wmma::fragment<wmma::matrix_a, 16, 16, 16, __nv_bfloat16, wmma::row_major> ah[4], al[4];
        #pragma unroll
        for (int i = 0; i < 4; i++) {
            wmma::load_matrix_sync(ah[i], Ah + (wm + i * 16) * BKP + ks, BKP);
            wmma::load_matrix_sync(al[i], Al + (wm + i * 16) * BKP + ks, BKP);
        }
        #pragma unroll
        for (int j = 0; j < 4; j++) {
            wmma::fragment<wmma::matrix_b, 16, 16, 16, __nv_bfloat16, wmma::col_major> bf;
            wmma::load_matrix_sync(bf, Bh + (wn + j * 16) * BKP + ks, BKP);
            #pragma unroll
            for (int i = 0; i < 4; i++) wmma::mma_sync(acc[i][j], ah[i], bf, acc[i][j]);
            #pragma unroll
            for (int i = 0; i < 4; i++) wmma::mma_sync(acc[i][j], al[i], bf, acc[i][j]);
            wmma::load_matrix_sync(bf, Bl + (wn + j * 16) * BKP + ks, BKP);
            #pragma unroll
            for (int i = 0; i < 4; i++) wmma::mma_sync(acc[i][j], ah[i], bf, acc[i][j]);
        }
    }
}

// ---------------- bf16-3term GEMM, 128x256 tile (R10 proven) ----------------
template<bool RESID>
__global__ __launch_bounds__(256, 1) void gemm_bf16_nt(const float* __restrict__ A,
                                                       const float* __restrict__ Bw,
                                                       const float* __restrict__ R,
                                                       float* __restrict__ C,
                                                       int N, int K) {
    extern __shared__ __nv_bfloat16 smem_[];
    __nv_bfloat16* Ah = smem_;
    __nv_bfloat16* Al = Ah + 2 * ASME;
    __nv_bfloat16* Bh = Al + 2 * ASME;
    __nv_bfloat16* Bl = Bh + 2 * BSME;

    const int tid = threadIdx.x;
    const int bm = blockIdx.y * 128, bn = blockIdx.x * 256;
    const int srow = tid >> 1;
    const int scol = (tid & 1) * 16;
    const int wid = tid >> 5;
    const int wm = (wid & 1) * 64;
    const int wn = (wid >> 1) * 64;

    const float* ap  = A  + (size_t)(bm + srow) * K + scol;
    const float* bp0 = Bw + (size_t)(bn + srow) * K + scol;
    const float* bp1 = Bw + (size_t)(bn + 128 + srow) * K + scol;

    wmma::fragment<wmma::accumulator, 16, 16, 16, float> acc[4][4];
    #pragma unroll
    for (int i = 0; i < 4; i++)
        #pragma unroll
        for (int j = 0; j < 4; j++) {
            if (RESID)
                wmma::load_matrix_sync(acc[i][j],
                    R + (size_t)(bm + wm + i * 16) * N + bn + wn + j * 16, N, wmma::mem_row_major);
            else
                wmma::fill_fragment(acc[i][j], 0.f);
        }

    float4 va[4], vb0[4], vb1[4];
    #pragma unroll
    for (int q = 0; q < 4; q++) {
        va[q]  = *reinterpret_cast<const float4*>(ap  + q * 4);
        vb0[q] = *reinterpret_cast<const float4*>(bp0 + q * 4);
        vb1[q] = *reinterpret_cast<const float4*>(bp1 + q * 4);
    }
    stage16(va,  1.f, Ah, Al, srow, scol);
    stage16(vb0, 1.f, Bh, Bl, srow, scol);
    stage16(vb1, 1.f, Bh, Bl, 128 + srow, scol);
    __syncthreads();

    const int nk = K / BK;
    for (int kk = 0; kk < nk; kk++) {
        const int cur = kk & 1;
        if (kk + 1 < nk) {
            const int k0 = (kk + 1) * BK;
            #pragma unroll
            for (int q = 0; q < 4; q++) {
                va[q]  = *reinterpret_cast<const float4*>(ap  + k0 + q * 4);
                vb0[q] = *reinterpret_cast<const float4*>(bp0 + k0 + q * 4);
                vb1[q] = *reinterpret_cast<const float4*>(bp1 + k0 + q * 4);
            }
        }
        mma_chunk(Ah + cur * ASME, Al + cur * ASME, Bh + cur * BSME, Bl + cur * BSME,
                  wm, wn, acc);
        if (kk + 1 < nk) {
            const int nxt = cur ^ 1;
            stage16(va,  1.f, Ah + nxt * ASME, Al + nxt * ASME, srow, scol);
            stage16(vb0, 1.f, Bh + nxt * BSME, Bl + nxt * BSME, srow, scol);
            stage16(vb1, 1.f, Bh + nxt * BSME, Bl + nxt * BSME, 128 + srow, scol);
            __syncthreads();
        }
    }
    #pragma unroll
    for (int i = 0; i < 4; i++)
        #pragma unroll
        for (int j = 0; j < 4; j++)
            wmma::store_matrix_sync(C + (size_t)(bm + wm + i * 16) * N + bn + wn + j * 16,
                                    acc[i][j], N, wmma::mem_row_major);
}

// ---------------- MoE grouped GEMM bf16-3term, 128x256 tile (R10 proven; layer 1) ----------------
template<bool GATHER, bool SCALE>
__global__ __launch_bounds__(256, 1) void gemm_bf16_moe(const float* __restrict__ X,
                                                        const float* __restrict__ Wbase,
                                                        long wstride,
                                                        float* __restrict__ C,
                                                        int N, int K,
                                                        const int* __restrict__ offs,
                                                        const int* __restrict__ slot_token,
                                                        const float* __restrict__ slot_w) {
    const int e = blockIdx.z;
    const int row0 = offs[e] + blockIdx.y * 128;
    if (row0 >= offs[e + 1]) return;
    const float* W = Wbase + (long)e * wstride;

    extern __shared__ __nv_bfloat16 smem_[];
    __nv_bfloat16* Ah = smem_;
    __nv_bfloat16* Al = Ah + 2 * ASME;
    __nv_bfloat16* Bh = Al + 2 * ASME;
    __nv_bfloat16* Bl = Bh + 2 * BSME;

    const int tid = threadIdx.x;
    const int bn = blockIdx.x * 256;
    const int srow = tid >> 1;
    const int scol = (tid & 1) * 16;
    const int wid = tid >> 5;
    const int wm = (wid & 1) * 64;
    const int wn = (wid >> 1) * 64;

    int grow = row0 + srow;
    int arow = GATHER ? slot_token[grow] : grow;
    float asc = (!GATHER && SCALE) ? slot_w[grow] : 1.f;
    const float* ap  = X + (size_t)arow * K + scol;
    const float* bp0 = W + (size_t)(bn + srow) * K + scol;
    const float* bp1 = W + (size_t)(bn + 128 + srow) * K + scol;

    wmma::fragment<wmma::accumulator, 16, 16, 16, float> acc[4][4];
    #pragma unroll
    for (int i = 0; i < 4; i++)
        #pragma unroll
        for (int j = 0; j < 4; j++) wmma::fill_fragment(acc[i][j], 0.f);

    float4 va[4], vb0[4], vb1[4];
    #pragma unroll
    for (int q = 0; q < 4; q++) {
        va[q]  = *reinterpret_cast<const float4*>(ap  + q * 4);
        vb0[q] = *reinterpret_cast<const float4*>(bp0 + q * 4);
        vb1[q] = *reinterpret_cast<const float4*>(bp1 + q * 4);
    }
    stage16(va,  asc, Ah, Al, srow, scol);
    stage16(vb0, 1.f, Bh, Bl, srow, scol);
    stage16(vb1, 1.f, Bh, Bl, 128 + srow, scol);
    __syncthreads();

    const int nk = K / BK;
    for (int kk = 0; kk < nk; kk++) {
        const int cur = kk & 1;
        if (kk + 1 < nk) {
            const int k0 = (kk + 1) * BK;
            #pragma unroll
            for (int q = 0; q < 4; q++) {
                va[q]  = *reinterpret_cast<const float4*>(ap  + k0 + q * 4);
                vb0[q] = *reinterpret_cast<const float4*>(bp0 + k0 + q * 4);
                vb1[q] = *reinterpret_cast<const float4*>(bp1 + k0 + q * 4);
            }
        }
        mma_chunk(Ah + cur * ASME, Al + cur * ASME, Bh + cur * BSME, Bl + cur * BSME,
                  wm, wn, acc);
        if (kk + 1 < nk) {
            const int nxt = cur ^ 1;
            stage16(va,  asc, Ah + nxt * ASME, Al + nxt * ASME, srow, scol);
            stage16(vb0, 1.f, Bh + nxt * BSME, Bl + nxt * BSME, srow, scol);
            stage16(vb1, 1.f, Bh + nxt * BSME, Bl + nxt * BSME, 128 + srow, scol);
            __syncthreads();
        }
    }
    #pragma unroll
    for (int i = 0; i < 4; i++)
        #pragma unroll
        for (int j = 0; j < 4; j++)
            wmma::store_matrix_sync(C + (size_t)(row0 + wm + i * 16) * N + bn + wn + j * 16,
                                    acc[i][j], N, wmma::mem_row_major);
}

// ---------------- fp16 2-term helpers ----------------
__device__ __forceinline__ void hsplit_store4(float4 v, float sc, __half* hi, __half* lo) {
    float f0 = v.x * sc, f1 = v.y * sc, f2 = v.z * sc, f3 = v.w * sc;
    __half2 h01, h23, l01, l23;
    h01.x = __float2half(f0); h01.y = __float2half(f1);
    h23.x = __float2half(f2); h23.y = __float2half(f3);
    l01.x = __float2half(f0 - __half2float(h01.x));
    l01.y = __float2half(f1 - __half2float(h01.y));
    l23.x = __float2half(f2 - __half2float(h23.x));
    l23.y = __float2half(f3 - __half2float(h23.y));
    *reinterpret_cast<__half2*>(hi)     = h01;
    *reinterpret_cast<__half2*>(hi + 2) = h23;
    *reinterpret_cast<__half2*>(lo)     = l01;
    *reinterpret_cast<__half2*>(lo + 2) = l23;
}

__device__ __forceinline__ void hconv_store4(float4 v, __half* dst) {
    __half2 h01, h23;
    h01.x = __float2half(v.x); h01.y = __float2half(v.y);
    h23.x = __float2half(v.z); h23.y = __float2half(v.w);
    *reinterpret_cast<__half2*>(dst)     = h01;
    *reinterpret_cast<__half2*>(dst + 2) = h23;
}

__device__ __forceinline__ void hmma_chunk(const __half* Ah, const __half* Al,
                                           const __half* Bh,
                                           int wm, int wn,
                                           wmma::fragment<wmma::accumulator,16,16,16,float> (&acc)[4][4]) {
    #pragma unroll
    for (int ks = 0; ks < BK; ks += 16) {
        wmma::fragment<wmma::matrix_a, 16, 16, 16, __half, wmma::row_major> ah[4], al[4];
        #pragma unroll
        for (int i = 0; i < 4; i++) {
            wmma::load_matrix_sync(ah[i], Ah + (wm + i * 16) * BKP + ks, BKP);
            wmma::load_matrix_sync(al[i], Al + (wm + i * 16) * BKP + ks, BKP);
        }
        #pragma unroll
        for (int j = 0; j < 4; j++) {
            wmma::fragment<wmma::matrix_b, 16, 16, 16, __half, wmma::col_major> bf;
            wmma::load_matrix_sync(bf, Bh + (wn + j * 16) * BKP + ks, BKP);
            #pragma unroll
            for (int i = 0; i < 4; i++) wmma::mma_sync(acc[i][j], ah[i], bf, acc[i][j]);
            #pragma unroll
            for (int i = 0; i < 4; i++) wmma::mma_sync(acc[i][j], al[i], bf, acc[i][j]);
        }
    }
}

// ---------------- fp16-2term plain GEMM (LM head), 128x256 tile ----------------
__global__ __launch_bounds__(256, 1) void gemm_head_fp16(const float* __restrict__ A,
                                                         const float* __restrict__ Bw,
                                                         float* __restrict__ C,
                                                         int N, int K) {
    extern __shared__ __half hsm_[];
    __half* Ah = hsm_;
    __half* Al = Ah + 2 * ASME;
    __half* Bh = Al + 2 * ASME;

    const int tid = threadIdx.x;
    const int bm = blockIdx.y * 128, bn = blockIdx.x * 256;
    const int srow = tid >> 1;
    const int scol = (tid & 1) * 16;
    const int wid = tid >> 5;
    const int wm = (wid & 1) * 64;
    const int wn = (wid >> 1) * 64;

    const float* ap  = A  + (size_t)(bm + srow) * K + scol;
    const float* bp0 = Bw + (size_t)(bn + srow) * K + scol;
    const float* bp1 = Bw + (size_t)(bn + 128 + srow) * K + scol;

    wmma::fragment<wmma::accumulator, 16, 16, 16, float> acc[4][4];
    #pragma unroll
    for (int i = 0; i < 4; i++)
        #pragma unroll
        for (int j = 0; j < 4; j++) wmma::fill_fragment(acc[i][j], 0.f);

    float4 va[4], vb0[4], vb1[4];
    #pragma unroll
    for (int q = 0; q < 4; q++) {
        va[q]  = *reinterpret_cast<const float4*>(ap  + q * 4);
        vb0[q] = *reinterpret_cast<const float4*>(bp0 + q * 4);
        vb1[q] = *reinterpret_cast<const float4*>(bp1 + q * 4);
    }
    #pragma unroll
    for (int q = 0; q < 4; q++) {
        hsplit_store4(va[q], 1.f, Ah + srow * BKP + scol + q * 4, Al + srow * BKP + scol + q * 4);
        hconv_store4(vb0[q], Bh + srow * BKP + scol + q * 4);
        hconv_store4(vb1[q], Bh + (128 + srow) * BKP + scol + q * 4);
    }
    __syncthreads();

    const int nk = K / BK;
    for (int kk = 0; kk < nk; kk++) {
        const int cur = kk & 1;
        if (kk + 1 < nk) {
            const int k0 = (kk + 1) * BK;
            #pragma unroll
            for (int q = 0; q < 4; q++) {
                va[q]  = *reinterpret_cast<const float4*>(ap  + k0 + q * 4);
                vb0[q] = *reinterpret_cast<const float4*>(bp0 + k0 + q * 4);
                vb1[q] = *reinterpret_cast<const float4*>(bp1 + k0 + q * 4);
            }
        }
        hmma_chunk(Ah + cur * ASME, Al + cur * ASME, Bh + cur * BSME, wm, wn, acc);
        if (kk + 1 < nk) {
            const int nxt = cur ^ 1;
            #pragma unroll
            for (int q = 0; q < 4; q++) {
                hsplit_store4(va[q], 1.f, Ah + nxt * ASME + srow * BKP + scol + q * 4,
                                          Al + nxt * ASME + srow * BKP + scol + q * 4);
                hconv_store4(vb0[q], Bh + nxt * BSME + srow * BKP + scol + q * 4);
                hconv_store4(vb1[q], Bh + nxt * BSME + (128 + srow) * BKP + scol + q * 4);
            }
            __syncthreads();
        }
    }
    #pragma unroll
    for (int i = 0; i < 4; i++)
        #pragma unroll
        for (int j = 0; j < 4; j++)
            wmma::store_matrix_sync(C + (size_t)(bm + wm + i * 16) * N + bn + wn + j * 16,
                                    acc[i][j], N, wmma::mem_row_major);
}

// ---------------- fp16-2term MoE grouped GEMM (layer-2 only: linear path) ----------------
template<bool GATHER, bool SCALE>
__global__ __launch_bounds__(256, 1) void gemm_fp16_moe(const float* __restrict__ X,
                                                        const float* __restrict__ Wbase,
                                                        long wstride,
                                                        float* __restrict__ C,
                                                        int N, int K,
                                                        const int* __restrict__ offs,
                                                        const int* __restrict__ slot_token,
                                                        const float* __restrict__ slot_w) {
    const int e = blockIdx.z;
    const int row0 = offs[e] + blockIdx.y * 128;
    if (row0 >= offs[e + 1]) return;
    const float* W = Wbase + (long)e * wstride;

    extern __shared__ __half hsm_[];
    __half* Ah = hsm_;
    __half* Al = Ah + 2 * ASME;
    __half* Bh = Al + 2 * ASME;

    const int tid = threadIdx.x;
    const int bn = blockIdx.x * 256;
    const int srow = tid >> 1;
    const int scol = (tid & 1) * 16;
    const int wid = tid >> 5;
    const int wm = (wid & 1) * 64;
    const int wn = (wid >> 1) * 64;

    int grow = row0 + srow;
    int arow = GATHER ? slot_token[grow] : grow;
    float asc = (!GATHER && SCALE) ? slot_w[grow] : 1.f;
    const float* ap  = X + (size_t)arow * K + scol;
    const float* bp0 = W + (size_t)(bn + srow) * K + scol;
    const float* bp1 = W + (size_t)(bn + 128 + srow) * K + scol;

    wmma::fragment<wmma::accumulator, 16, 16, 16, float> acc[4][4];
    #pragma unroll
    for (int i = 0; i < 4; i++)
        #pragma unroll
        for (int j = 0; j < 4; j++) wmma::fill_fragment(acc[i][j], 0.f);

    float4 va[4], vb0[4], vb1[4];
    #pragma unroll
    for (int q = 0; q < 4; q++) {
        va[q]  = *reinterpret_cast<const float4*>(ap  + q * 4);
        vb0[q] = *reinterpret_cast<const float4*>(bp0 + q * 4);
        vb1[q] = *reinterpret_cast<const float4*>(bp1 + q * 4);
    }
    #pragma unroll
    for (int q = 0; q < 4; q++) {
        hsplit_store4(va[q], asc, Ah + srow * BKP + scol + q * 4, Al + srow * BKP + scol + q * 4);
        hconv_store4(vb0[q], Bh + srow * BKP + scol + q * 4);
        hconv_store4(vb1[q], Bh + (128 + srow) * BKP + scol + q * 4);
    }
    __syncthreads();

    const int nk = K / BK;
    for (int kk = 0; kk < nk; kk++) {
        const int cur = kk & 1;
        if (kk + 1 < nk) {
            const int k0 = (kk + 1) * BK;
            #pragma unroll
            for (int q = 0; q < 4; q++) {
                va[q]  = *reinterpret_cast<const float4*>(ap  + k0 + q * 4);
                vb0[q] = *reinterpret_cast<const float4*>(bp0 + k0 + q * 4);
                vb1[q] = *reinterpret_cast<const float4*>(bp1 + k0 + q * 4);
            }
        }
        hmma_chunk(Ah + cur * ASME, Al + cur * ASME, Bh + cur * BSME, wm, wn, acc);
        if (kk + 1 < nk) {
            const int nxt = cur ^ 1;
            #pragma unroll
            for (int q = 0; q < 4; q++) {
                hsplit_store4(va[q], asc, Ah + nxt * ASME + srow * BKP + scol + q * 4,
                                          Al + nxt * ASME + srow * BKP + scol + q * 4);
                hconv_store4(vb0[q], Bh + nxt * BSME + srow * BKP + scol + q * 4);
                hconv_store4(vb1[q], Bh + nxt * BSME + (128 + srow) * BKP + scol + q * 4);
            }
            __syncthreads();
        }
    }
    #pragma unroll
    for (int i = 0; i < 4; i++)
        #pragma unroll
        for (int j = 0; j < 4; j++)
            wmma::store_matrix_sync(C + (size_t)(row0 + wm + i * 16) * N + bn + wn + j * 16,
                                    acc[i][j], N, wmma::mem_row_major);
}

// ---------------- tensor-core flash attention (bf16-split wmma, proven R7) ----------------
__device__ __forceinline__ void fsplit16(const float* __restrict__ src,
                                         __nv_bfloat16* hi, __nv_bfloat16* lo) {
    #pragma unroll
    for (int q = 0; q < 4; q++) {
        float4 v = *reinterpret_cast<const float4*>(src + q * 4);
        split_store4(v, 1.f, hi + q * 4, lo + q * 4);
    }
}

__global__ __launch_bounds__(256) void flash_kernel(const float* __restrict__ qkv,
                                                    float* __restrict__ y) {
    extern __shared__ char fsm[];
    __nv_bfloat16* Qh = (__nv_bfloat16*)(fsm + FO_QH);
    __nv_bfloat16* Ql = (__nv_bfloat16*)(fsm + FO_QL);
    __nv_bfloat16* Kh = (__nv_bfloat16*)(fsm + FO_KH);
    __nv_bfloat16* Kl = (__nv_bfloat16*)(fsm + FO_KL);
    __nv_bfloat16* Vh = (__nv_bfloat16*)(fsm + FO_VH);
    __nv_bfloat16* Vl = (__nv_bfloat16*)(fsm + FO_VL);
    float*         Ss = (float*)(fsm + FO_SS);
    float*         Os = (float*)(fsm + FO_OS);
    __nv_bfloat16* Ph = (__nv_bfloat16*)(fsm + FO_PH);
    __nv_bfloat16* Pl = (__nv_bfloat16*)(fsm + FO_PL);

    const int b = blockIdx.z, h = blockIdx.y;
    const int q0 = blockIdx.x * 64;
    const int kvh = h >> 2;
    const int tid = threadIdx.x;
    const int tx = tid & 15, ty = tid >> 4;
    const int wq = tid >> 5;
    const int wm2 = (wq >> 1) * 16;
    const int wn2 = (wq & 1) * 32;
    const int lr = tid >> 2;
    const int lc = (tid & 3) * 16;

    fsplit16(qkv + (size_t)(b * SEQ + q0 + lr) * QKVN + h * HDIM + lc,
             Qh + lr * FSB + lc, Ql + lr * FSB + lc);

    float m[4], l[4], O[4][4];
    #pragma unroll
    for (int i = 0; i < 4; i++) {
        m[i] = -FLT_MAX; l[i] = 0.f;
        #pragma unroll
        for (int j = 0; j < 4; j++) O[i][j] = 0.f;
    }

    const int ntile = q0 / 64 + 1;
    for (int kt = 0; kt < ntile; kt++) {
        const int k0 = kt * 64;
        fsplit16(qkv + (size_t)(b * SEQ + k0 + lr) * QKVN + DMODEL + kvh * HDIM + lc,
                 Kh + lr * FSB + lc, Kl + lr * FSB + lc);
        fsplit16(qkv + (size_t)(b * SEQ + k0 + lr) * QKVN + DMODEL + NKV * HDIM + kvh * HDIM + lc,
                 Vh + lr * FSB + lc, Vl + lr * FSB + lc);
        __syncthreads();

        {
            wmma::fragment<wmma::accumulator, 16, 16, 16, float> sfr[2];
            wmma::fill_fragment(sfr[0], 0.f);
            wmma::fill_fragment(sfr[1], 0.f);
            #pragma unroll
            for (int ks = 0; ks < 64; ks += 16) {
                wmma::fragment<wmma::matrix_a, 16, 16, 16, __nv_bfloat16, wmma::row_major> qh, ql;
                wmma::load_matrix_sync(qh, Qh + wm2 * FSB + ks, FSB);
                wmma::load_matrix_sync(ql, Ql + wm2 * FSB + ks, FSB);
                #pragma unroll
                for (int j = 0; j < 2; j++) {
                    wmma::fragment<wmma::matrix_b, 16, 16, 16, __nv_bfloat16, wmma::col_major> kf;
                    wmma::load_matrix_sync(kf, Kh + (wn2 + j * 16) * FSB + ks, FSB);
                    wmma::mma_sync(sfr[j], qh, kf, sfr[j]);
                    wmma::mma_sync(sfr[j], ql, kf, sfr[j]);
                    wmma::load_matrix_sync(kf, Kl + (wn2 + j * 16) * FSB + ks, FSB);
                    wmma::mma_sync(sfr[j], qh, kf, sfr[j]);
                }
            }
            wmma::store_matrix_sync(Ss + wm2 * FSF + wn2,      sfr[0], FSF, wmma::mem_row_major);
            wmma::store_matrix_sync(Ss + wm2 * FSF + wn2 + 16, sfr[1], FSF, wmma::mem_row_major);
        }
        __syncthreads();

        float corr[4];
        #pragma unroll
        for (int i = 0; i < 4; i++) {
            int row = ty * 4 + i;
            int qg = q0 + row;
            float s[4];
            float rm = -FLT_MAX;
            #pragma unroll
            for (int j = 0; j < 4; j++) {
                int kg = k0 + tx * 4 + j;
                float v = (kg <= qg) ? Ss[row * FSF + tx * 4 + j] * 0.125f : -FLT_MAX;
                s[j] = v;
                rm = fmaxf(rm, v);
            }
            for (int off = 8; off; off >>= 1)
                rm = fmaxf(rm, __shfl_xor_sync(0xffffffffu, rm, off, 16));
            float mn = fmaxf(m[i], rm);
            corr[i] = __expf(m[i] - mn);
            float rs = 0.f;
            #pragma unroll
            for (int j = 0; j < 4; j++) {
                float p = __expf(s[j] - mn);
                rs += p;
                __nv_bfloat16 ph = __float2bfloat16(p);
                Ph[row * FSB + tx * 4 + j] = ph;
                Pl[row * FSB + tx * 4 + j] = __float2bfloat16(p - __bfloat162float(ph));
            }
            for (int off = 8; off; off >>= 1)
                rs += __shfl_xor_sync(0xffffffffu, rs, off, 16);
            l[i] = l[i] * corr[i] + rs;
            m[i] = mn;
        }
        __syncthreads();

        {
            wmma::fragment<wmma::accumulator, 16, 16, 16, float> ofr[2];
            wmma::fill_fragment(ofr[0], 0.f);
            wmma::fill_fragment(ofr[1], 0.f);
            #pragma unroll
            for (int ks = 0; ks < 64; ks += 16) {
                wmma::fragment<wmma::matrix_a, 16, 16, 16, __nv_bfloat16, wmma::row_major> ph, pl;
                wmma::load_matrix_sync(ph, Ph + wm2 * FSB + ks, FSB);
                wmma::load_matrix_sync(pl, Pl + wm2 * FSB + ks, FSB);
                #pragma unroll
                for (int j = 0; j < 2; j++) {
                    wmma::fragment<wmma::matrix_b, 16, 16, 16, __nv_bfloat16, wmma::row_major> vf;
                    wmma::load_matrix_sync(vf, Vh + ks * FSB + wn2 + j * 16, FSB);
                    wmma::mma_sync(ofr[j], ph, vf, ofr[j]);
                    wmma::mma_sync(ofr[j], pl, vf, ofr[j]);
                    wmma::load_matrix_sync(vf, Vl + ks * FSB + wn2 + j * 16, FSB);
                    wmma::mma_sync(ofr[j], ph, vf, ofr[j]);
                }
            }
            wmma::store_matrix_sync(Os + wm2 * FSF + wn2,      ofr[0], FSF, wmma::mem_row_major);
            wmma::store_matrix_sync(Os + wm2 * FSF + wn2 + 16, ofr[1], FSF, wmma::mem_row_major);
        }
        __syncthreads();

        #pragma unroll
        for (int i = 0; i < 4; i++) {
            int row = ty * 4 + i;
            #pragma unroll
            for (int j = 0; j < 4; j++)
                O[i][j] = O[i][j] * corr[i] + Os[row * FSF + tx * 4 + j];
        }
        __syncthreads();
    }

    #pragma unroll
    for (int i = 0; i < 4; i++) {
        float inv = 1.f / l[i];
        #pragma unroll
        for (int j = 0; j < 4; j++)
            y[(size_t)(b * SEQ + q0 + ty * 4 + i) * DMODEL + h * HDIM + tx * 4 + j] = O[i][j] * inv;
    }
}

// ---------------- MoE routing ----------------
__global__ void zero_counts_kernel(int* counts) {
    if (threadIdx.x < NEXP) counts[threadIdx.x] = 0;
}

__global__ void init_slots_kernel(int* slot_token, float* slot_w) {
    int i = blockIdx.x * blockDim.x + threadIdx.x;
    if (i < NSLOTP) { slot_token[i] = 0; slot_w[i] = 0.f; }
}

__global__ __launch_bounds__(256) void gate_kernel(const float* __restrict__ xn,
                                                   const float* __restrict__ gw,
                                                   int* __restrict__ tok_e,
                                                   float* __restrict__ tok_w,
                                                   int* __restrict__ counts) {
    int t = blockIdx.x;
    int w = threadIdx.x >> 5, lane = threadIdx.x & 31;
    __shared__ float sc[NEXP];
    const float* x = xn + (size_t)t * DMODEL;
    const float* g = gw + (size_t)w * DMODEL;
    float s = 0.f;
    for (int d = lane; d < DMODEL; d += 32) s += x[d] * g[d];
    for (int off = 16; off; off >>= 1) s += __shfl_xor_sync(0xffffffffu, s, off);
    if (lane == 0) sc[w] = s;
    __syncthreads();
    if (threadIdx.x == 0) {
        float mx = sc[0];
        #pragma unroll
        for (int e = 1; e < NEXP; e++) mx = fmaxf(mx, sc[e]);
        float p[NEXP], sum = 0.f;
        #pragma unroll
        for (int e = 0; e < NEXP; e++) { p[e] = __expf(sc[e] - mx); sum += p[e]; }
        int i0 = 0;
        #pragma unroll
        for (int e = 1; e < NEXP; e++) if (p[e] > p[i0]) i0 = e;
        int i1 = (i0 == 0) ? 1 : 0;
        #pragma unroll
        for (int e = 0; e < NEXP; e++) if (e != i0 && p[e] > p[i1]) i1 = e;
        float v0 = p[i0] / sum, v1 = p[i1] / sum;
        float inv = 1.f / (v0 + v1);
        tok_e[2 * t] = i0;  tok_e[2 * t + 1] = i1;
        tok_w[2 * t] = v0 * inv; tok_w[2 * t + 1] = v1 * inv;
        atomicAdd(&counts[i0], 1); atomicAdd(&counts[i1], 1);
    }
}

__global__ void scan_kernel(const int* __restrict__ counts, int* __restrict__ offs,
                            int* __restrict__ cursor) {
    if (threadIdx.x == 0) {
        int acc = 0;
        for (int e = 0; e < NEXP; e++) {
            offs[e] = acc; cursor[e] = acc;
            acc += ((counts[e] + 127) >> 7) << 7;
        }
        offs[NEXP] = acc;
    }
}

__global__ void scatter_kernel(const int* __restrict__ tok_e, const float* __restrict__ tok_w,
                               int* __restrict__ cursor, int* __restrict__ slot_token,
                               float* __restrict__ slot_w, int* __restrict__ token_slot) {
    int t = blockIdx.x * blockDim.x + threadIdx.x;
    if (t >= TOK) return;
    #pragma unroll
    for (int j = 0; j < TOPK; j++) {
        int e = tok_e[2 * t + j];
        int slot = atomicAdd(&cursor[e], 1);
        slot_token[slot] = t;
        slot_w[slot] = tok_w[2 * t + j];
        token_slot[2 * t + j] = slot;
    }
}

__global__ void silu_mul_kernel(float* __restrict__ h1, const float* __restrict__ h3) {
    long i = (long)blockIdx.x * blockDim.x + threadIdx.x;
    if (i < (long)NSLOTP * FFI) {
        float a = h1[i];
        h1[i] = (a / (1.f + __expf(-a))) * h3[i];
    }
}

__global__ void combine_kernel(float* __restrict__ x, const float* __restrict__ so,
                               const int* __restrict__ token_slot) {
    int t = blockIdx.x;
    int s0 = token_slot[2 * t], s1 = token_slot[2 * t + 1];
    float* xp = x + (size_t)t * DMODEL;
    const float* a = so + (size_t)s0 * DMODEL;
    const float* b = so + (size_t)s1 * DMODEL;
    for (int d = threadIdx.x; d < DMODEL; d += blockDim.x) xp[d] += a[d] + b[d];
}

// ---------------- orchestration ----------------
extern "C" void kernel_launch(void* const* d_in, const int* in_sizes, int n_in,
                              void* d_out, int out_size) {
    const int*   idx      = (const int*)  d_in[0];
    const float* tok_emb  = (const float*)d_in[1];
    const float* attn_nw  = (const float*)d_in[2];
    const float* wqkv     = (const float*)d_in[3];
    const float* wo       = (const float*)d_in[4];
    const float* ffn_nw   = (const float*)d_in[5];
    const float* gate_w   = (const float*)d_in[6];
    const float* w1       = (const float*)d_in[7];
    const float* w2       = (const float*)d_in[8];
    const float* w3       = (const float*)d_in[9];
    const float* final_nw = (const float*)d_in[10];
    const float* out_w    = (const float*)d_in[11];
    float* logits = (float*)d_out;

    cudaFuncSetAttribute(gemm_bf16_nt<false>,
        cudaFuncAttributeMaxDynamicSharedMemorySize, GEMM_SMEM_BYTES);
    cudaFuncSetAttribute(gemm_bf16_nt<true>,
        cudaFuncAttributeMaxDynamicSharedMemorySize, GEMM_SMEM_BYTES);
    cudaFuncSetAttribute(gemm_bf16_moe<true, false>,
        cudaFuncAttributeMaxDynamicSharedMemorySize, GEMM_SMEM_BYTES);
    cudaFuncSetAttribute(gemm_bf16_moe<false, true>,
        cudaFuncAttributeMaxDynamicSharedMemorySize, GEMM_SMEM_BYTES);
    cudaFuncSetAttribute(gemm_fp16_moe<true, false>,
        cudaFuncAttributeMaxDynamicSharedMemorySize, FP16_SMEM_BYTES);
    cudaFuncSetAttribute(gemm_fp16_moe<false, true>,
        cudaFuncAttributeMaxDynamicSharedMemorySize, FP16_SMEM_BYTES);
    cudaFuncSetAttribute(gemm_head_fp16,
        cudaFuncAttributeMaxDynamicSharedMemorySize, FP16_SMEM_BYTES);
    cudaFuncSetAttribute(flash_kernel,
        cudaFuncAttributeMaxDynamicSharedMemorySize, FLASH_SMEM_BYTES);

    float *px, *pxn, *pqkv, *py, *ph1, *ph3, *pso, *pslot_w, *ptok_w;
    int *pcounts, *poffs, *pcursor, *pslot_token, *ptoken_slot, *ptok_e;
    cudaGetSymbolAddress((void**)&px, g_x);
    cudaGetSymbolAddress((void**)&pxn, g_xn);
    cudaGetSymbolAddress((void**)&pqkv, g_qkv);
    cudaGetSymbolAddress((void**)&py, g_y);
    cudaGetSymbolAddress((void**)&ph1, g_h1);
    cudaGetSymbolAddress((void**)&ph3, g_h3);
    cudaGetSymbolAddress((void**)&pso, g_so);
    cudaGetSymbolAddress((void**)&pcounts, g_counts);
    cudaGetSymbolAddress((void**)&poffs, g_offs);
    cudaGetSymbolAddress((void**)&pcursor, g_cursor);
    cudaGetSymbolAddress((void**)&pslot_token, g_slot_token);
    cudaGetSymbolAddress((void**)&pslot_w, g_slot_w);
    cudaGetSymbolAddress((void**)&ptoken_slot, g_token_slot);
    cudaGetSymbolAddress((void**)&ptok_e, g_tok_e);
    cudaGetSymbolAddress((void**)&ptok_w, g_tok_w);

    embed_kernel<<<TOK, 256>>>(idx, tok_emb, px);

    for (int l = 0; l < NLAYER; l++) {
        // ---- attention block (always bf16-3term: upstream of routing) ----
        rmsnorm_kernel<<<TOK, 256>>>(px, attn_nw + (size_t)l * DMODEL, pxn);
        gemm_bf16_nt<false><<<dim3(QKVN / 256, TOK / 128), 256, GEMM_SMEM_BYTES>>>(
            pxn, wqkv + (size_t)l * QKVN * DMODEL, nullptr, pqkv, QKVN, DMODEL);
        {
            int total = TOK * (NH + NKV) * (HDIM / 2);
            rope_kernel<<<(total + 255) / 256, 256>>>(pqkv);
        }
        flash_kernel<<<dim3(SEQ / 64, NH, NB), 256, FLASH_SMEM_BYTES>>>(pqkv, py);
        gemm_bf16_nt<true><<<dim3(DMODEL / 256, TOK / 128), 256, GEMM_SMEM_BYTES>>>(
            py, wo + (size_t)l * DMODEL * DMODEL, px, px, DMODEL, DMODEL);

        // ---- MoE block ----
        rmsnorm_kernel<<<TOK, 256>>>(px, ffn_nw + (size_t)l * DMODEL, pxn);
        zero_counts_kernel<<<1, 32>>>(pcounts);
        init_slots_kernel<<<(NSLOTP + 255) / 256, 256>>>(pslot_token, pslot_w);
        gate_kernel<<<TOK, 256>>>(pxn, gate_w + (size_t)l * NEXP * DMODEL,
                                  ptok_e, ptok_w, pcounts);
        scan_kernel<<<1, 1>>>(pcounts, poffs, pcursor);
        scatter_kernel<<<(TOK + 255) / 256, 256>>>(ptok_e, ptok_w, pcursor,
                                                   pslot_token, pslot_w, ptoken_slot);
        if (l == 0) {
            // layer-1 MoE feeds layer-2 routing: keep bf16-3term
            gemm_bf16_moe<true, false><<<dim3(FFI / 256, NSLOTP / 128, NEXP), 256, GEMM_SMEM_BYTES>>>(
                pxn, w1 + (size_t)l * NEXP * FFI * DMODEL, (long)FFI * DMODEL,
                ph1, FFI, DMODEL, poffs, pslot_token, pslot_w);
            gemm_bf16_moe<true, false><<<dim3(FFI / 256, NSLOTP / 128, NEXP), 256, GEMM_SMEM_BYTES>>>(
                pxn, w3 + (size_t)l * NEXP * FFI * DMODEL, (long)FFI * DMODEL,
                ph3, FFI, DMODEL, poffs, pslot_token, pslot_w);
            {
                long n = (long)NSLOTP * FFI;
                silu_mul_kernel<<<(unsigned)((n + 255) / 256), 256>>>(ph1, ph3);
            }
            gemm_bf16_moe<false, true><<<dim3(DMODEL / 256, NSLOTP / 128, NEXP), 256, GEMM_SMEM_BYTES>>>(
                ph1, w2 + (size_t)l * NEXP * DMODEL * FFI, (long)DMODEL * FFI,
                pso, DMODEL, FFI, poffs, pslot_token, pslot_w);
        } else {
            // layer-2 MoE: purely linear path (no routing downstream) -> fp16-2term
            gemm_fp16_moe<true, false><<<dim3(FFI / 256, NSLOTP / 128, NEXP), 256, FP16_SMEM_BYTES>>>(
                pxn, w1 + (size_t)l * NEXP * FFI * DMODEL, (long)FFI * DMODEL,
                ph1, FFI, DMODEL, poffs, pslot_token, pslot_w);
            gemm_fp16_moe<true, false><<<dim3(FFI / 256, NSLOTP / 128, NEXP), 256, FP16_SMEM_BYTES>>>(
                pxn, w3 + (size_t)l * NEXP * FFI * DMODEL, (long)FFI * DMODEL,
                ph3, FFI, DMODEL, poffs, pslot_token, pslot_w);
            {
                long n = (long)NSLOTP * FFI;
                silu_mul_kernel<<<(unsigned)((n + 255) / 256), 256>>>(ph1, ph3);
            }
            gemm_fp16_moe<false, true><<<dim3(DMODEL / 256, NSLOTP / 128, NEXP), 256, FP16_SMEM_BYTES>>>(
                ph1, w2 + (size_t)l * NEXP * DMODEL * FFI, (long)DMODEL * FFI,
                pso, DMODEL, FFI, poffs, pslot_token, pslot_w);
        }
        combine_kernel<<<TOK, 256>>>(px, pso, ptoken_slot);
    }

    // ---- final norm + LM head (fp16-2term: linear path) ----
    rmsnorm_kernel<<<TOK, 256>>>(px, final_nw, pxn);
    gemm_head_fp16<<<dim3(VOCAB / 256, TOK / 128), 256, FP16_SMEM_BYTES>>>(
        pxn, out_w, logits, VOCAB, DMODEL);
}

// round 17
// speedup vs baseline: 1.4758x; 1.0592x over previous
#include <cstdint>
#include <stdint.h>
#include <cuda_runtime.h>
#include <cuda_bf16.h>
#include <cuda_fp16.h>
#include <mma.h>
#include <math.h>
#include <float.h>

using namespace nvcuda;

// ---------------- problem constants ----------------
#define NB      2
#define SEQ     1024
#define TOK     2048
#define DMODEL  1024
#define NH      16
#define NKV     4
#define HDIM    64
#define NEXP    8
#define TOPK    2
#define NLAYER  2
#define VOCAB   32000
#define FFI     3584
#define QKVN    1536
#define NSLOT   (TOK*TOPK)
#define NSLOTP  (NSLOT + NEXP*128)   // 5120

#define BK   32
#define BKP  40
#define ASME (128*BKP)
#define BSME (256*BKP)
#define GEMM_SMEM_BYTES ((4*ASME + 4*BSME) * 2)   // 122880 (bf16 3-term)
#define FP16_SMEM_BYTES ((2*ASME + 2*BSME) * 2)   // 61440  (fp16 1-term)

// flash smem layout (bytes)
#define FSB 72
#define FSF 68
#define FO_QH 0
#define FO_QL (FO_QH + 64*FSB*2)
#define FO_KH (FO_QL + 64*FSB*2)
#define FO_KL (FO_KH + 64*FSB*2)
#define FO_VH (FO_KL + 64*FSB*2)
#define FO_VL (FO_VH + 64*FSB*2)
#define FO_SS (FO_VL + 64*FSB*2)
#define FO_OS (FO_SS + 64*FSF*4)
#define FO_PH (FO_OS + 64*FSF*4)
#define FO_PL (FO_PH + 64*FSB*2)
#define FLASH_SMEM_BYTES (FO_PL + 64*FSB*2)   // 108544

// ---------------- scratch ----------------
__device__ float g_x  [TOK*DMODEL];
__device__ float g_xn [TOK*DMODEL];
__device__ float g_qkv[TOK*QKVN];
__device__ float g_y  [TOK*DMODEL];
__device__ float g_h1 [NSLOTP*FFI];
__device__ float g_h3 [NSLOTP*FFI];
__device__ float g_so [NSLOTP*DMODEL];
__device__ int   g_counts[NEXP];
__device__ int   g_offs[NEXP+1];
__device__ int   g_cursor[NEXP];
__device__ int   g_slot_token[NSLOTP];
__device__ float g_slot_w[NSLOTP];
__device__ int   g_token_slot[NSLOT];
__device__ int   g_tok_e[TOK*TOPK];
__device__ float g_tok_w[TOK*TOPK];

// ---------------- small kernels ----------------
__global__ void embed_kernel(const int* __restrict__ idx,
                             const float* __restrict__ emb,
                             float* __restrict__ x) {
    int t = blockIdx.x;
    int row = idx[t];
    const float* src = emb + (size_t)row * DMODEL;
    float* dst = x + (size_t)t * DMODEL;
    for (int d = threadIdx.x; d < DMODEL; d += blockDim.x) dst[d] = src[d];
}

__global__ __launch_bounds__(256) void rmsnorm_kernel(const float* __restrict__ x,
                                                      const float* __restrict__ w,
                                                      float* __restrict__ o) {
    int t = blockIdx.x;
    const float* xr = x + (size_t)t * DMODEL;
    float ss = 0.f;
    for (int d = threadIdx.x; d < DMODEL; d += 256) { float v = xr[d]; ss += v * v; }
    for (int off = 16; off; off >>= 1) ss += __shfl_xor_sync(0xffffffffu, ss, off);
    __shared__ float red[8];
    __shared__ float s_inv;
    int warp = threadIdx.x >> 5, lane = threadIdx.x & 31;
    if (lane == 0) red[warp] = ss;
    __syncthreads();
    if (threadIdx.x == 0) {
        float tot = 0.f;
        #pragma unroll
        for (int i = 0; i < 8; i++) tot += red[i];
        s_inv = rsqrtf(tot / (float)DMODEL + 1e-5f);
    }
    __syncthreads();
    float inv = s_inv;
    float* op = o + (size_t)t * DMODEL;
    for (int d = threadIdx.x; d < DMODEL; d += 256) op[d] = xr[d] * inv * w[d];
}

__global__ void rope_kernel(float* __restrict__ qkv) {
    int i = blockIdx.x * blockDim.x + threadIdx.x;
    const int total = TOK * (NH + NKV) * (HDIM / 2);
    if (i >= total) return;
    int pair = i & 31;
    int r = i >> 5;
    int head = r % (NH + NKV);
    int t = r / (NH + NKV);
    int s = t & (SEQ - 1);
    float freq = expf((float)pair * -0.43173470493638357f);
    float ang = (float)s * freq;
    float sn, c;
    sincosf(ang, &sn, &c);
    float* p = qkv + (size_t)t * QKVN + head * HDIM + 2 * pair;
    float x0 = p[0], x1 = p[1];
    p[0] = x0 * c - x1 * sn;
    p[1] = x1 * c + x0 * sn;
}

// ---------------- bf16 split helpers (R10 proven) ----------------
__device__ __forceinline__ void split_store4(float4 v, float sc,
                                             __nv_bfloat16* hi, __nv_bfloat16* lo) {
    float f0 = v.x * sc, f1 = v.y * sc, f2 = v.z * sc, f3 = v.w * sc;
    __nv_bfloat162 h01, h23, l01, l23;
    h01.x = __float2bfloat16(f0); h01.y = __float2bfloat16(f1);
    h23.x = __float2bfloat16(f2); h23.y = __float2bfloat16(f3);
    l01.x = __float2bfloat16(f0 - __bfloat162float(h01.x));
    l01.y = __float2bfloat16(f1 - __bfloat162float(h01.y));
    l23.x = __float2bfloat16(f2 - __bfloat162float(h23.x));
    l23.y = __float2bfloat16(f3 - __bfloat162float(h23.y));
    *reinterpret_cast<__nv_bfloat162*>(hi)     = h01;
    *reinterpret_cast<__nv_bfloat162*>(hi + 2) = h23;
    *reinterpret_cast<__nv_bfloat162*>(lo)     = l01;
    *reinterpret_cast<__nv_bfloat162*>(lo + 2) = l23;
}

__device__ __forceinline__ void stage16(const float4 v[4], float sc,
                                        __nv_bfloat16* hiArr, __nv_bfloat16* loArr,
                                        int row, int scol) {
    #pragma unroll
    for (int q = 0; q < 4; q++)
        split_store4(v[q], sc, hiArr + row * BKP + scol + q * 4,
                             loArr + row * BKP + scol + q * 4);
}

__device__ __forceinline__ void mma_chunk(const __nv_bfloat16* Ah, const __nv_bfloat16* Al,
                                          const __nv_bfloat16* Bh, const __nv_bfloat16* Bl,
                                          int wm, int wn,
                                          wmma::fragment<wmma::accumulator,16,16,16,float> (&acc)[4][4]) {
    #pragma unroll
    for (int ks = 0; ks < BK; ks += 16) {
        wmma::fragment<wmma::matrix_a, 16, 16, 16, __nv_bfloat16, wmma::row_major> ah[4], al[4];
        #pragma unroll
        for (int i = 0; i < 4; i++) {
            wmma::load_matrix_sync(ah[i], Ah + (wm + i * 16) * BKP + ks, BKP);
            wmma::load_matrix_sync(al[i], Al + (wm + i * 16) * BKP + ks, BKP);
        }
        #pragma unroll
        for (int j = 0; j < 4; j++) {
            wmma::fragment<wmma::matrix_b, 16, 16, 16, __nv_bfloat16, wmma::col_major> bf;
            wmma::load_matrix_sync(bf, Bh + (wn + j * 16) * BKP + ks, BKP);
            #pragma unroll
            for (int i = 0; i < 4; i++) wmma::mma_sync(acc[i][j], ah[i], bf, acc[i][j]);
            #pragma unroll
            for (int i = 0; i < 4; i++) wmma::mma_sync(acc[i][j], al[i], bf, acc[i][j]);
            wmma::load_matrix_sync(bf, Bl + (wn + j * 16) * BKP + ks, BKP);
            #pragma unroll
            for (int i = 0; i < 4; i++) wmma::mma_sync(acc[i][j], ah[i], bf, acc[i][j]);
        }
    }
}

// ---------------- bf16-3term GEMM, 128x256 tile (R10 proven) ----------------
template<bool RESID>
__global__ __launch_bounds__(256, 1) void gemm_bf16_nt(const float* __restrict__ A,
                                                       const float* __restrict__ Bw,
                                                       const float* __restrict__ R,
                                                       float* __restrict__ C,
                                                       int N, int K) {
    extern __shared__ __nv_bfloat16 smem_[];
    __nv_bfloat16* Ah = smem_;
    __nv_bfloat16* Al = Ah + 2 * ASME;
    __nv_bfloat16* Bh = Al + 2 * ASME;
    __nv_bfloat16* Bl = Bh + 2 * BSME;

    const int tid = threadIdx.x;
    const int bm = blockIdx.y * 128, bn = blockIdx.x * 256;
    const int srow = tid >> 1;
    const int scol = (tid & 1) * 16;
    const int wid = tid >> 5;
    const int wm = (wid & 1) * 64;
    const int wn = (wid >> 1) * 64;

    const float* ap  = A  + (size_t)(bm + srow) * K + scol;
    const float* bp0 = Bw + (size_t)(bn + srow) * K + scol;
    const float* bp1 = Bw + (size_t)(bn + 128 + srow) * K + scol;

    wmma::fragment<wmma::accumulator, 16, 16, 16, float> acc[4][4];
    #pragma unroll
    for (int i = 0; i < 4; i++)
        #pragma unroll
        for (int j = 0; j < 4; j++) {
            if (RESID)
                wmma::load_matrix_sync(acc[i][j],
                    R + (size_t)(bm + wm + i * 16) * N + bn + wn + j * 16, N, wmma::mem_row_major);
            else
                wmma::fill_fragment(acc[i][j], 0.f);
        }

    float4 va[4], vb0[4], vb1[4];
    #pragma unroll
    for (int q = 0; q < 4; q++) {
        va[q]  = *reinterpret_cast<const float4*>(ap  + q * 4);
        vb0[q] = *reinterpret_cast<const float4*>(bp0 + q * 4);
        vb1[q] = *reinterpret_cast<const float4*>(bp1 + q * 4);
    }
    stage16(va,  1.f, Ah, Al, srow, scol);
    stage16(vb0, 1.f, Bh, Bl, srow, scol);
    stage16(vb1, 1.f, Bh, Bl, 128 + srow, scol);
    __syncthreads();

    const int nk = K / BK;
    for (int kk = 0; kk < nk; kk++) {
        const int cur = kk & 1;
        if (kk + 1 < nk) {
            const int k0 = (kk + 1) * BK;
            #pragma unroll
            for (int q = 0; q < 4; q++) {
                va[q]  = *reinterpret_cast<const float4*>(ap  + k0 + q * 4);
                vb0[q] = *reinterpret_cast<const float4*>(bp0 + k0 + q * 4);
                vb1[q] = *reinterpret_cast<const float4*>(bp1 + k0 + q * 4);
            }
        }
        mma_chunk(Ah + cur * ASME, Al + cur * ASME, Bh + cur * BSME, Bl + cur * BSME,
                  wm, wn, acc);
        if (kk + 1 < nk) {
            const int nxt = cur ^ 1;
            stage16(va,  1.f, Ah + nxt * ASME, Al + nxt * ASME, srow, scol);
            stage16(vb0, 1.f, Bh + nxt * BSME, Bl + nxt * BSME, srow, scol);
            stage16(vb1, 1.f, Bh + nxt * BSME, Bl + nxt * BSME, 128 + srow, scol);
            __syncthreads();
        }
    }
    #pragma unroll
    for (int i = 0; i < 4; i++)
        #pragma unroll
        for (int j = 0; j < 4; j++)
            wmma::store_matrix_sync(C + (size_t)(bm + wm + i * 16) * N + bn + wn + j * 16,
                                    acc[i][j], N, wmma::mem_row_major);
}

// ---------------- MoE grouped GEMM bf16-3term, 128x256 tile (layer 1) ----------------
template<bool GATHER, bool SCALE>
__global__ __launch_bounds__(256, 1) void gemm_bf16_moe(const float* __restrict__ X,
                                                        const float* __restrict__ Wbase,
                                                        long wstride,
                                                        float* __restrict__ C,
                                                        int N, int K,
                                                        const int* __restrict__ offs,
                                                        const int* __restrict__ slot_token,
                                                        const float* __restrict__ slot_w) {
    const int e = blockIdx.z;
    const int row0 = offs[e] + blockIdx.y * 128;
    if (row0 >= offs[e + 1]) return;
    const float* W = Wbase + (long)e * wstride;

    extern __shared__ __nv_bfloat16 smem_[];
    __nv_bfloat16* Ah = smem_;
    __nv_bfloat16* Al = Ah + 2 * ASME;
    __nv_bfloat16* Bh = Al + 2 * ASME;
    __nv_bfloat16* Bl = Bh + 2 * BSME;

    const int tid = threadIdx.x;
    const int bn = blockIdx.x * 256;
    const int srow = tid >> 1;
    const int scol = (tid & 1) * 16;
    const int wid = tid >> 5;
    const int wm = (wid & 1) * 64;
    const int wn = (wid >> 1) * 64;

    int grow = row0 + srow;
    int arow = GATHER ? slot_token[grow] : grow;
    float asc = (!GATHER && SCALE) ? slot_w[grow] : 1.f;
    const float* ap  = X + (size_t)arow * K + scol;
    const float* bp0 = W + (size_t)(bn + srow) * K + scol;
    const float* bp1 = W + (size_t)(bn + 128 + srow) * K + scol;

    wmma::fragment<wmma::accumulator, 16, 16, 16, float> acc[4][4];
    #pragma unroll
    for (int i = 0; i < 4; i++)
        #pragma unroll
        for (int j = 0; j < 4; j++) wmma::fill_fragment(acc[i][j], 0.f);

    float4 va[4], vb0[4], vb1[4];
    #pragma unroll
    for (int q = 0; q < 4; q++) {
        va[q]  = *reinterpret_cast<const float4*>(ap  + q * 4);
        vb0[q] = *reinterpret_cast<const float4*>(bp0 + q * 4);
        vb1[q] = *reinterpret_cast<const float4*>(bp1 + q * 4);
    }
    stage16(va,  asc, Ah, Al, srow, scol);
    stage16(vb0, 1.f, Bh, Bl, srow, scol);
    stage16(vb1, 1.f, Bh, Bl, 128 + srow, scol);
    __syncthreads();

    const int nk = K / BK;
    for (int kk = 0; kk < nk; kk++) {
        const int cur = kk & 1;
        if (kk + 1 < nk) {
            const int k0 = (kk + 1) * BK;
            #pragma unroll
            for (int q = 0; q < 4; q++) {
                va[q]  = *reinterpret_cast<const float4*>(ap  + k0 + q * 4);
                vb0[q] = *reinterpret_cast<const float4*>(bp0 + k0 + q * 4);
                vb1[q] = *reinterpret_cast<const float4*>(bp1 + k0 + q * 4);
            }
        }
        mma_chunk(Ah + cur * ASME, Al + cur * ASME, Bh + cur * BSME, Bl + cur * BSME,
                  wm, wn, acc);
        if (kk + 1 < nk) {
            const int nxt = cur ^ 1;
            stage16(va,  asc, Ah + nxt * ASME, Al + nxt * ASME, srow, scol);
            stage16(vb0, 1.f, Bh + nxt * BSME, Bl + nxt * BSME, srow, scol);
            stage16(vb1, 1.f, Bh + nxt * BSME, Bl + nxt * BSME, 128 + srow, scol);
            __syncthreads();
        }
    }
    #pragma unroll
    for (int i = 0; i < 4; i++)
        #pragma unroll
        for (int j = 0; j < 4; j++)
            wmma::store_matrix_sync(C + (size_t)(row0 + wm + i * 16) * N + bn + wn + j * 16,
                                    acc[i][j], N, wmma::mem_row_major);
}

// ---------------- fp16 1-term helpers ----------------
__device__ __forceinline__ void hconv_store4(float4 v, float sc, __half* dst) {
    __half2 h01, h23;
    h01.x = __float2half(v.x * sc); h01.y = __float2half(v.y * sc);
    h23.x = __float2half(v.z * sc); h23.y = __float2half(v.w * sc);
    *reinterpret_cast<__half2*>(dst)     = h01;
    *reinterpret_cast<__half2*>(dst + 2) = h23;
}

__device__ __forceinline__ void hmma1_chunk(const __half* Ah, const __half* Bh,
                                            int wm, int wn,
                                            wmma::fragment<wmma::accumulator,16,16,16,float> (&acc)[4][4]) {
    #pragma unroll
    for (int ks = 0; ks < BK; ks += 16) {
        wmma::fragment<wmma::matrix_a, 16, 16, 16, __half, wmma::row_major> ah[4];
        #pragma unroll
        for (int i = 0; i < 4; i++)
            wmma::load_matrix_sync(ah[i], Ah + (wm + i * 16) * BKP + ks, BKP);
        #pragma unroll
        for (int j = 0; j < 4; j++) {
            wmma::fragment<wmma::matrix_b, 16, 16, 16, __half, wmma::col_major> bf;
            wmma::load_matrix_sync(bf, Bh + (wn + j * 16) * BKP + ks, BKP);
            #pragma unroll
            for (int i = 0; i < 4; i++) wmma::mma_sync(acc[i][j], ah[i], bf, acc[i][j]);
        }
    }
}

// ---------------- fp16-1term plain GEMM (LM head), 128x256 tile ----------------
__global__ __launch_bounds__(256, 1) void gemm_head_fp16(const float* __restrict__ A,
                                                         const float* __restrict__ Bw,
                                                         float* __restrict__ C,
                                                         int N, int K) {
    extern __shared__ __half hsm_[];
    __half* Ah = hsm_;
    __half* Bh = Ah + 2 * ASME;

    const int tid = threadIdx.x;
    const int bm = blockIdx.y * 128, bn = blockIdx.x * 256;
    const int srow = tid >> 1;
    const int scol = (tid & 1) * 16;
    const int wid = tid >> 5;
    const int wm = (wid & 1) * 64;
    const int wn = (wid >> 1) * 64;

    const float* ap  = A  + (size_t)(bm + srow) * K + scol;
    const float* bp0 = Bw + (size_t)(bn + srow) * K + scol;
    const float* bp1 = Bw + (size_t)(bn + 128 + srow) * K + scol;

    wmma::fragment<wmma::accumulator, 16, 16, 16, float> acc[4][4];
    #pragma unroll
    for (int i = 0; i < 4; i++)
        #pragma unroll
        for (int j = 0; j < 4; j++) wmma::fill_fragment(acc[i][j], 0.f);

    float4 va[4], vb0[4], vb1[4];
    #pragma unroll
    for (int q = 0; q < 4; q++) {
        va[q]  = *reinterpret_cast<const float4*>(ap  + q * 4);
        vb0[q] = *reinterpret_cast<const float4*>(bp0 + q * 4);
        vb1[q] = *reinterpret_cast<const float4*>(bp1 + q * 4);
    }
    #pragma unroll
    for (int q = 0; q < 4; q++) {
        hconv_store4(va[q], 1.f, Ah + srow * BKP + scol + q * 4);
        hconv_store4(vb0[q], 1.f, Bh + srow * BKP + scol + q * 4);
        hconv_store4(vb1[q], 1.f, Bh + (128 + srow) * BKP + scol + q * 4);
    }
    __syncthreads();

    const int nk = K / BK;
    for (int kk = 0; kk < nk; kk++) {
        const int cur = kk & 1;
        if (kk + 1 < nk) {
            const int k0 = (kk + 1) * BK;
            #pragma unroll
            for (int q = 0; q < 4; q++) {
                va[q]  = *reinterpret_cast<const float4*>(ap  + k0 + q * 4);
                vb0[q] = *reinterpret_cast<const float4*>(bp0 + k0 + q * 4);
                vb1[q] = *reinterpret_cast<const float4*>(bp1 + k0 + q * 4);
            }
        }
        hmma1_chunk(Ah + cur * ASME, Bh + cur * BSME, wm, wn, acc);
        if (kk + 1 < nk) {
            const int nxt = cur ^ 1;
            #pragma unroll
            for (int q = 0; q < 4; q++) {
                hconv_store4(va[q], 1.f, Ah + nxt * ASME + srow * BKP + scol + q * 4);
                hconv_store4(vb0[q], 1.f, Bh + nxt * BSME + srow * BKP + scol + q * 4);
                hconv_store4(vb1[q], 1.f, Bh + nxt * BSME + (128 + srow) * BKP + scol + q * 4);
            }
            __syncthreads();
        }
    }
    #pragma unroll
    for (int i = 0; i < 4; i++)
        #pragma unroll
        for (int j = 0; j < 4; j++)
            wmma::store_matrix_sync(C + (size_t)(bm + wm + i * 16) * N + bn + wn + j * 16,
                                    acc[i][j], N, wmma::mem_row_major);
}

// ---------------- fp16-1term MoE grouped GEMM (layer-2 only: linear path) ----------------
template<bool GATHER, bool SCALE>
__global__ __launch_bounds__(256, 1) void gemm_fp16_moe(const float* __restrict__ X,
                                                        const float* __restrict__ Wbase,
                                                        long wstride,
                                                        float* __restrict__ C,
                                                        int N, int K,
                                                        const int* __restrict__ offs,
                                                        const int* __restrict__ slot_token,
                                                        const float* __restrict__ slot_w) {
    const int e = blockIdx.z;
    const int row0 = offs[e] + blockIdx.y * 128;
    if (row0 >= offs[e + 1]) return;
    const float* W = Wbase + (long)e * wstride;

    extern __shared__ __half hsm_[];
    __half* Ah = hsm_;
    __half* Bh = Ah + 2 * ASME;

    const int tid = threadIdx.x;
    const int bn = blockIdx.x * 256;
    const int srow = tid >> 1;
    const int scol = (tid & 1) * 16;
    const int wid = tid >> 5;
    const int wm = (wid & 1) * 64;
    const int wn = (wid >> 1) * 64;

    int grow = row0 + srow;
    int arow = GATHER ? slot_token[grow] : grow;
    float asc = (!GATHER && SCALE) ? slot_w[grow] : 1.f;
    const float* ap  = X + (size_t)arow * K + scol;
    const float* bp0 = W + (size_t)(bn + srow) * K + scol;
    const float* bp1 = W + (size_t)(bn + 128 + srow) * K + scol;

    wmma::fragment<wmma::accumulator, 16, 16, 16, float> acc[4][4];
    #pragma unroll
    for (int i = 0; i < 4; i++)
        #pragma unroll
        for (int j = 0; j < 4; j++) wmma::fill_fragment(acc[i][j], 0.f);

    float4 va[4], vb0[4], vb1[4];
    #pragma unroll
    for (int q = 0; q < 4; q++) {
        va[q]  = *reinterpret_cast<const float4*>(ap  + q * 4);
        vb0[q] = *reinterpret_cast<const float4*>(bp0 + q * 4);
        vb1[q] = *reinterpret_cast<const float4*>(bp1 + q * 4);
    }
    #pragma unroll
    for (int q = 0; q < 4; q++) {
        hconv_store4(va[q], asc, Ah + srow * BKP + scol + q * 4);
        hconv_store4(vb0[q], 1.f, Bh + srow * BKP + scol + q * 4);
        hconv_store4(vb1[q], 1.f, Bh + (128 + srow) * BKP + scol + q * 4);
    }
    __syncthreads();

    const int nk = K / BK;
    for (int kk = 0; kk < nk; kk++) {
        const int cur = kk & 1;
        if (kk + 1 < nk) {
            const int k0 = (kk + 1) * BK;
            #pragma unroll
            for (int q = 0; q < 4; q++) {
                va[q]  = *reinterpret_cast<const float4*>(ap  + k0 + q * 4);
                vb0[q] = *reinterpret_cast<const float4*>(bp0 + k0 + q * 4);
                vb1[q] = *reinterpret_cast<const float4*>(bp1 + k0 + q * 4);
            }
        }
        hmma1_chunk(Ah + cur * ASME, Bh + cur * BSME, wm, wn, acc);
        if (kk + 1 < nk) {
            const int nxt = cur ^ 1;
            #pragma unroll
            for (int q = 0; q < 4; q++) {
                hconv_store4(va[q], asc, Ah + nxt * ASME + srow * BKP + scol + q * 4);
                hconv_store4(vb0[q], 1.f, Bh + nxt * BSME + srow * BKP + scol + q * 4);
                hconv_store4(vb1[q], 1.f, Bh + nxt * BSME + (128 + srow) * BKP + scol + q * 4);
            }
            __syncthreads();
        }
    }
    #pragma unroll
    for (int i = 0; i < 4; i++)
        #pragma unroll
        for (int j = 0; j < 4; j++)
            wmma::store_matrix_sync(C + (size_t)(row0 + wm + i * 16) * N + bn + wn + j * 16,
                                    acc[i][j], N, wmma::mem_row_major);
}

// ---------------- tensor-core flash attention (bf16-split wmma, proven R7) ----------------
__device__ __forceinline__ void fsplit16(const float* __restrict__ src,
                                         __nv_bfloat16* hi, __nv_bfloat16* lo) {
    #pragma unroll
    for (int q = 0; q < 4; q++) {
        float4 v = *reinterpret_cast<const float4*>(src + q * 4);
        split_store4(v, 1.f, hi + q * 4, lo + q * 4);
    }
}

__global__ __launch_bounds__(256) void flash_kernel(const float* __restrict__ qkv,
                                                    float* __restrict__ y) {
    extern __shared__ char fsm[];
    __nv_bfloat16* Qh = (__nv_bfloat16*)(fsm + FO_QH);
    __nv_bfloat16* Ql = (__nv_bfloat16*)(fsm + FO_QL);
    __nv_bfloat16* Kh = (__nv_bfloat16*)(fsm + FO_KH);
    __nv_bfloat16* Kl = (__nv_bfloat16*)(fsm + FO_KL);
    __nv_bfloat16* Vh = (__nv_bfloat16*)(fsm + FO_VH);
    __nv_bfloat16* Vl = (__nv_bfloat16*)(fsm + FO_VL);
    float*         Ss = (float*)(fsm + FO_SS);
    float*         Os = (float*)(fsm + FO_OS);
    __nv_bfloat16* Ph = (__nv_bfloat16*)(fsm + FO_PH);
    __nv_bfloat16* Pl = (__nv_bfloat16*)(fsm + FO_PL);

    const int b = blockIdx.z, h = blockIdx.y;
    const int q0 = blockIdx.x * 64;
    const int kvh = h >> 2;
    const int tid = threadIdx.x;
    const int tx = tid & 15, ty = tid >> 4;
    const int wq = tid >> 5;
    const int wm2 = (wq >> 1) * 16;
    const int wn2 = (wq & 1) * 32;
    const int lr = tid >> 2;
    const int lc = (tid & 3) * 16;

    fsplit16(qkv + (size_t)(b * SEQ + q0 + lr) * QKVN + h * HDIM + lc,
             Qh + lr * FSB + lc, Ql + lr * FSB + lc);

    float m[4], l[4], O[4][4];
    #pragma unroll
    for (int i = 0; i < 4; i++) {
        m[i] = -FLT_MAX; l[i] = 0.f;
        #pragma unroll
        for (int j = 0; j < 4; j++) O[i][j] = 0.f;
    }

    const int ntile = q0 / 64 + 1;
    for (int kt = 0; kt < ntile; kt++) {
        const int k0 = kt * 64;
        fsplit16(qkv + (size_t)(b * SEQ + k0 + lr) * QKVN + DMODEL + kvh * HDIM + lc,
                 Kh + lr * FSB + lc, Kl + lr * FSB + lc);
        fsplit16(qkv + (size_t)(b * SEQ + k0 + lr) * QKVN + DMODEL + NKV * HDIM + kvh * HDIM + lc,
                 Vh + lr * FSB + lc, Vl + lr * FSB + lc);
        __syncthreads();

        {
            wmma::fragment<wmma::accumulator, 16, 16, 16, float> sfr[2];
            wmma::fill_fragment(sfr[0], 0.f);
            wmma::fill_fragment(sfr[1], 0.f);
            #pragma unroll
            for (int ks = 0; ks < 64; ks += 16) {
                wmma::fragment<wmma::matrix_a, 16, 16, 16, __nv_bfloat16, wmma::row_major> qh, ql;
                wmma::load_matrix_sync(qh, Qh + wm2 * FSB + ks, FSB);
                wmma::load_matrix_sync(ql, Ql + wm2 * FSB + ks, FSB);
                #pragma unroll
                for (int j = 0; j < 2; j++) {
                    wmma::fragment<wmma::matrix_b, 16, 16, 16, __nv_bfloat16, wmma::col_major> kf;
                    wmma::load_matrix_sync(kf, Kh + (wn2 + j * 16) * FSB + ks, FSB);
                    wmma::mma_sync(sfr[j], qh, kf, sfr[j]);
                    wmma::mma_sync(sfr[j], ql, kf, sfr[j]);
                    wmma::load_matrix_sync(kf, Kl + (wn2 + j * 16) * FSB + ks, FSB);
                    wmma::mma_sync(sfr[j], qh, kf, sfr[j]);
                }
            }
            wmma::store_matrix_sync(Ss + wm2 * FSF + wn2,      sfr[0], FSF, wmma::mem_row_major);
            wmma::store_matrix_sync(Ss + wm2 * FSF + wn2 + 16, sfr[1], FSF, wmma::mem_row_major);
        }
        __syncthreads();

        float corr[4];
        #pragma unroll
        for (int i = 0; i < 4; i++) {
            int row = ty * 4 + i;
            int qg = q0 + row;
            float s[4];
            float rm = -FLT_MAX;
            #pragma unroll
            for (int j = 0; j < 4; j++) {
                int kg = k0 + tx * 4 + j;
                float v = (kg <= qg) ? Ss[row * FSF + tx * 4 + j] * 0.125f : -FLT_MAX;
                s[j] = v;
                rm = fmaxf(rm, v);
            }
            for (int off = 8; off; off >>= 1)
                rm = fmaxf(rm, __shfl_xor_sync(0xffffffffu, rm, off, 16));
            float mn = fmaxf(m[i], rm);
            corr[i] = __expf(m[i] - mn);
            float rs = 0.f;
            #pragma unroll
            for (int j = 0; j < 4; j++) {
                float p = __expf(s[j] - mn);
                rs += p;
                __nv_bfloat16 ph = __float2bfloat16(p);
                Ph[row * FSB + tx * 4 + j] = ph;
                Pl[row * FSB + tx * 4 + j] = __float2bfloat16(p - __bfloat162float(ph));
            }
            for (int off = 8; off; off >>= 1)
                rs += __shfl_xor_sync(0xffffffffu, rs, off, 16);
            l[i] = l[i] * corr[i] + rs;
            m[i] = mn;
        }
        __syncthreads();

        {
            wmma::fragment<wmma::accumulator, 16, 16, 16, float> ofr[2];
            wmma::fill_fragment(ofr[0], 0.f);
            wmma::fill_fragment(ofr[1], 0.f);
            #pragma unroll
            for (int ks = 0; ks < 64; ks += 16) {
                wmma::fragment<wmma::matrix_a, 16, 16, 16, __nv_bfloat16, wmma::row_major> ph, pl;
                wmma::load_matrix_sync(ph, Ph + wm2 * FSB + ks, FSB);
                wmma::load_matrix_sync(pl, Pl + wm2 * FSB + ks, FSB);
                #pragma unroll
                for (int j = 0; j < 2; j++) {
                    wmma::fragment<wmma::matrix_b, 16, 16, 16, __nv_bfloat16, wmma::row_major> vf;
                    wmma::load_matrix_sync(vf, Vh + ks * FSB + wn2 + j * 16, FSB);
                    wmma::mma_sync(ofr[j], ph, vf, ofr[j]);
                    wmma::mma_sync(ofr[j], pl, vf, ofr[j]);
                    wmma::load_matrix_sync(vf, Vl + ks * FSB + wn2 + j * 16, FSB);
                    wmma::mma_sync(ofr[j], ph, vf, ofr[j]);
                }
            }
            wmma::store_matrix_sync(Os + wm2 * FSF + wn2,      ofr[0], FSF, wmma::mem_row_major);
            wmma::store_matrix_sync(Os + wm2 * FSF + wn2 + 16, ofr[1], FSF, wmma::mem_row_major);
        }
        __syncthreads();

        #pragma unroll
        for (int i = 0; i < 4; i++) {
            int row = ty * 4 + i;
            #pragma unroll
            for (int j = 0; j < 4; j++)
                O[i][j] = O[i][j] * corr[i] + Os[row * FSF + tx * 4 + j];
        }
        __syncthreads();
    }

    #pragma unroll
    for (int i = 0; i < 4; i++) {
        float inv = 1.f / l[i];
        #pragma unroll
        for (int j = 0; j < 4; j++)
            y[(size_t)(b * SEQ + q0 + ty * 4 + i) * DMODEL + h * HDIM + tx * 4 + j] = O[i][j] * inv;
    }
}

// ---------------- MoE routing ----------------
__global__ void zero_counts_kernel(int* counts) {
    if (threadIdx.x < NEXP) counts[threadIdx.x] = 0;
}

__global__ void init_slots_kernel(int* slot_token, float* slot_w) {
    int i = blockIdx.x * blockDim.x + threadIdx.x;
    if (i < NSLOTP) { slot_token[i] = 0; slot_w[i] = 0.f; }
}

__global__ __launch_bounds__(256) void gate_kernel(const float* __restrict__ xn,
                                                   const float* __restrict__ gw,
                                                   int* __restrict__ tok_e,
                                                   float* __restrict__ tok_w,
                                                   int* __restrict__ counts) {
    int t = blockIdx.x;
    int w = threadIdx.x >> 5, lane = threadIdx.x & 31;
    __shared__ float sc[NEXP];
    const float* x = xn + (size_t)t * DMODEL;
    const float* g = gw + (size_t)w * DMODEL;
    float s = 0.f;
    for (int d = lane; d < DMODEL; d += 32) s += x[d] * g[d];
    for (int off = 16; off; off >>= 1) s += __shfl_xor_sync(0xffffffffu, s, off);
    if (lane == 0) sc[w] = s;
    __syncthreads();
    if (threadIdx.x == 0) {
        float mx = sc[0];
        #pragma unroll
        for (int e = 1; e < NEXP; e++) mx = fmaxf(mx, sc[e]);
        float p[NEXP], sum = 0.f;
        #pragma unroll
        for (int e = 0; e < NEXP; e++) { p[e] = __expf(sc[e] - mx); sum += p[e]; }
        int i0 = 0;
        #pragma unroll
        for (int e = 1; e < NEXP; e++) if (p[e] > p[i0]) i0 = e;
        int i1 = (i0 == 0) ? 1 : 0;
        #pragma unroll
        for (int e = 0; e < NEXP; e++) if (e != i0 && p[e] > p[i1]) i1 = e;
        float v0 = p[i0] / sum, v1 = p[i1] / sum;
        float inv = 1.f / (v0 + v1);
        tok_e[2 * t] = i0;  tok_e[2 * t + 1] = i1;
        tok_w[2 * t] = v0 * inv; tok_w[2 * t + 1] = v1 * inv;
        atomicAdd(&counts[i0], 1); atomicAdd(&counts[i1], 1);
    }
}

__global__ void scan_kernel(const int* __restrict__ counts, int* __restrict__ offs,
                            int* __restrict__ cursor) {
    if (threadIdx.x == 0) {
        int acc = 0;
        for (int e = 0; e < NEXP; e++) {
            offs[e] = acc; cursor[e] = acc;
            acc += ((counts[e] + 127) >> 7) << 7;
        }
        offs[NEXP] = acc;
    }
}

__global__ void scatter_kernel(const int* __restrict__ tok_e, const float* __restrict__ tok_w,
                               int* __restrict__ cursor, int* __restrict__ slot_token,
                               float* __restrict__ slot_w, int* __restrict__ token_slot) {
    int t = blockIdx.x * blockDim.x + threadIdx.x;
    if (t >= TOK) return;
    #pragma unroll
    for (int j = 0; j < TOPK; j++) {
        int e = tok_e[2 * t + j];
        int slot = atomicAdd(&cursor[e], 1);
        slot_token[slot] = t;
        slot_w[slot] = tok_w[2 * t + j];
        token_slot[2 * t + j] = slot;
    }
}

__global__ void silu_mul_kernel(float* __restrict__ h1, const float* __restrict__ h3) {
    long i = (long)blockIdx.x * blockDim.x + threadIdx.x;
    if (i < (long)NSLOTP * FFI) {
        float a = h1[i];
        h1[i] = (a / (1.f + __expf(-a))) * h3[i];
    }
}

__global__ void combine_kernel(float* __restrict__ x, const float* __restrict__ so,
                               const int* __restrict__ token_slot) {
    int t = blockIdx.x;
    int s0 = token_slot[2 * t], s1 = token_slot[2 * t + 1];
    float* xp = x + (size_t)t * DMODEL;
    const float* a = so + (size_t)s0 * DMODEL;
    const float* b = so + (size_t)s1 * DMODEL;
    for (int d = threadIdx.x; d < DMODEL; d += blockDim.x) xp[d] += a[d] + b[d];
}

// ---------------- orchestration ----------------
extern "C" void kernel_launch(void* const* d_in, const int* in_sizes, int n_in,
                              void* d_out, int out_size) {
    const int*   idx      = (const int*)  d_in[0];
    const float* tok_emb  = (const float*)d_in[1];
    const float* attn_nw  = (const float*)d_in[2];
    const float* wqkv     = (const float*)d_in[3];
    const float* wo       = (const float*)d_in[4];
    const float* ffn_nw   = (const float*)d_in[5];
    const float* gate_w   = (const float*)d_in[6];
    const float* w1       = (const float*)d_in[7];
    const float* w2       = (const float*)d_in[8];
    const float* w3       = (const float*)d_in[9];
    const float* final_nw = (const float*)d_in[10];
    const float* out_w    = (const float*)d_in[11];
    float* logits = (float*)d_out;

    cudaFuncSetAttribute(gemm_bf16_nt<false>,
        cudaFuncAttributeMaxDynamicSharedMemorySize, GEMM_SMEM_BYTES);
    cudaFuncSetAttribute(gemm_bf16_nt<true>,
        cudaFuncAttributeMaxDynamicSharedMemorySize, GEMM_SMEM_BYTES);
    cudaFuncSetAttribute(gemm_bf16_moe<true, false>,
        cudaFuncAttributeMaxDynamicSharedMemorySize, GEMM_SMEM_BYTES);
    cudaFuncSetAttribute(gemm_bf16_moe<false, true>,
        cudaFuncAttributeMaxDynamicSharedMemorySize, GEMM_SMEM_BYTES);
    cudaFuncSetAttribute(gemm_fp16_moe<true, false>,
        cudaFuncAttributeMaxDynamicSharedMemorySize, FP16_SMEM_BYTES);
    cudaFuncSetAttribute(gemm_fp16_moe<false, true>,
        cudaFuncAttributeMaxDynamicSharedMemorySize, FP16_SMEM_BYTES);
    cudaFuncSetAttribute(gemm_head_fp16,
        cudaFuncAttributeMaxDynamicSharedMemorySize, FP16_SMEM_BYTES);
    cudaFuncSetAttribute(flash_kernel,
        cudaFuncAttributeMaxDynamicSharedMemorySize, FLASH_SMEM_BYTES);

    float *px, *pxn, *pqkv, *py, *ph1, *ph3, *pso, *pslot_w, *ptok_w;
    int *pcounts, *poffs, *pcursor, *pslot_token, *ptoken_slot, *ptok_e;
    cudaGetSymbolAddress((void**)&px, g_x);
    cudaGetSymbolAddress((void**)&pxn, g_xn);
    cudaGetSymbolAddress((void**)&pqkv, g_qkv);
    cudaGetSymbolAddress((void**)&py, g_y);
    cudaGetSymbolAddress((void**)&ph1, g_h1);
    cudaGetSymbolAddress((void**)&ph3, g_h3);
    cudaGetSymbolAddress((void**)&pso, g_so);
    cudaGetSymbolAddress((void**)&pcounts, g_counts);
    cudaGetSymbolAddress((void**)&poffs, g_offs);
    cudaGetSymbolAddress((void**)&pcursor, g_cursor);
    cudaGetSymbolAddress((void**)&pslot_token, g_slot_token);
    cudaGetSymbolAddress((void**)&pslot_w, g_slot_w);
    cudaGetSymbolAddress((void**)&ptoken_slot, g_token_slot);
    cudaGetSymbolAddress((void**)&ptok_e, g_tok_e);
    cudaGetSymbolAddress((void**)&ptok_w, g_tok_w);

    embed_kernel<<<TOK, 256>>>(idx, tok_emb, px);

    for (int l = 0; l < NLAYER; l++) {
        // ---- attention block (bf16-3term: upstream of routing) ----
        rmsnorm_kernel<<<TOK, 256>>>(px, attn_nw + (size_t)l * DMODEL, pxn);
        gemm_bf16_nt<false><<<dim3(QKVN / 256, TOK / 128), 256, GEMM_SMEM_BYTES>>>(
            pxn, wqkv + (size_t)l * QKVN * DMODEL, nullptr, pqkv, QKVN, DMODEL);
        {
            int total = TOK * (NH + NKV) * (HDIM / 2);
            rope_kernel<<<(total + 255) / 256, 256>>>(pqkv);
        }
        flash_kernel<<<dim3(SEQ / 64, NH, NB), 256, FLASH_SMEM_BYTES>>>(pqkv, py);
        gemm_bf16_nt<true><<<dim3(DMODEL / 256, TOK / 128), 256, GEMM_SMEM_BYTES>>>(
            py, wo + (size_t)l * DMODEL * DMODEL, px, px, DMODEL, DMODEL);

        // ---- MoE block ----
        rmsnorm_kernel<<<TOK, 256>>>(px, ffn_nw + (size_t)l * DMODEL, pxn);
        zero_counts_kernel<<<1, 32>>>(pcounts);
        init_slots_kernel<<<(NSLOTP + 255) / 256, 256>>>(pslot_token, pslot_w);
        gate_kernel<<<TOK, 256>>>(pxn, gate_w + (size_t)l * NEXP * DMODEL,
                                  ptok_e, ptok_w, pcounts);
        scan_kernel<<<1, 1>>>(pcounts, poffs, pcursor);
        scatter_kernel<<<(TOK + 255) / 256, 256>>>(ptok_e, ptok_w, pcursor,
                                                   pslot_token, pslot_w, ptoken_slot);
        if (l == 0) {
            // layer-1 MoE feeds layer-2 routing: keep bf16-3term
            gemm_bf16_moe<true, false><<<dim3(FFI / 256, NSLOTP / 128, NEXP), 256, GEMM_SMEM_BYTES>>>(
                pxn, w1 + (size_t)l * NEXP * FFI * DMODEL, (long)FFI * DMODEL,
                ph1, FFI, DMODEL, poffs, pslot_token, pslot_w);
            gemm_bf16_moe<true, false><<<dim3(FFI / 256, NSLOTP / 128, NEXP), 256, GEMM_SMEM_BYTES>>>(
                pxn, w3 + (size_t)l * NEXP * FFI * DMODEL, (long)FFI * DMODEL,
                ph3, FFI, DMODEL, poffs, pslot_token, pslot_w);
            {
                long n = (long)NSLOTP * FFI;
                silu_mul_kernel<<<(unsigned)((n + 255) / 256), 256>>>(ph1, ph3);
            }
            gemm_bf16_moe<false, true><<<dim3(DMODEL / 256, NSLOTP / 128, NEXP), 256, GEMM_SMEM_BYTES>>>(
                ph1, w2 + (size_t)l * NEXP * DMODEL * FFI, (long)DMODEL * FFI,
                pso, DMODEL, FFI, poffs, pslot_token, pslot_w);
        } else {
            // layer-2 MoE: linear path -> fp16 1-term
            gemm_fp16_moe<true, false><<<dim3(FFI / 256, NSLOTP / 128, NEXP), 256, FP16_SMEM_BYTES>>>(
                pxn, w1 + (size_t)l * NEXP * FFI * DMODEL, (long)FFI * DMODEL,
                ph1, FFI, DMODEL, poffs, pslot_token, pslot_w);
            gemm_fp16_moe<true, false><<<dim3(FFI / 256, NSLOTP / 128, NEXP), 256, FP16_SMEM_BYTES>>>(
                pxn, w3 + (size_t)l * NEXP * FFI * DMODEL, (long)FFI * DMODEL,
                ph3, FFI, DMODEL, poffs, pslot_token, pslot_w);
            {
                long n = (long)NSLOTP * FFI;
                silu_mul_kernel<<<(unsigned)((n + 255) / 256), 256>>>(ph1, ph3);
            }
            gemm_fp16_moe<false, true><<<dim3(DMODEL / 256, NSLOTP / 128, NEXP), 256, FP16_SMEM_BYTES>>>(
                ph1, w2 + (size_t)l * NEXP * DMODEL * FFI, (long)DMODEL * FFI,
                pso, DMODEL, FFI, poffs, pslot_token, pslot_w);
        }
        combine_kernel<<<TOK, 256>>>(px, pso, ptoken_slot);
    }

    // ---- final norm + LM head (fp16 1-term: linear path) ----
    rmsnorm_kernel<<<TOK, 256>>>(px, final_nw, pxn);
    gemm_head_fp16<<<dim3(VOCAB / 256, TOK / 128), 256, FP16_SMEM_BYTES>>>(
        pxn, out_w, logits, VOCAB, DMODEL);
}